// round 1
// baseline (speedup 1.0000x reference)
#include <cuda_runtime.h>

#define Hh 256
#define Ww 256
#define Bb 8
#define HW 65536
#define NPIX (Bb*HW)   // 524288

// Scratch (device globals — no allocation allowed)
__device__ float g_bufA[(size_t)Bb*128*HW];
__device__ float g_bufB[(size_t)Bb*128*HW];
__device__ float g_maskA[(size_t)Bb*HW];
__device__ float g_maskB[(size_t)Bb*HW];
__device__ float g_sums[256];
__device__ float g_ss[256];

// ---------------------------------------------------------------------------
// Fused sparse-conv block:
//   y = conv3x3_dilated(x * mask, W) / clamp(cin * box3x3(mask), 1e-5) + b
//   mask_out = maxpool3x3_dilated(mask)
//   also accumulates per-channel sum / sumsq of y for BatchNorm stats.
// Tiling: 16x16 output pixels per block; CI_CHUNK=8 input chans staged in smem;
// weights staged as [ci][k][co] so inner loop is broadcast LDS.128 + 4 FFMA.
// ---------------------------------------------------------------------------
template<int CIN, int COUT, int DIL, int COG>
__global__ void __launch_bounds__(256, 2) conv_block_kernel(
    const float* __restrict__ x, const float* __restrict__ mask,
    const float* __restrict__ W, const float* __restrict__ bias,
    float* __restrict__ y, float* __restrict__ mask_out,
    float* __restrict__ sums)
{
    constexpr int TILE = 16;
    constexpr int TP   = TILE + 2*DIL;
    constexpr int TPP  = TP*TP;
    constexpr int CIC  = 8;

    __shared__ float ms[TPP];
    __shared__ __align__(16) float xs[CIC*TPP];
    __shared__ __align__(16) float ws[CIC*9*COG];
    __shared__ float bias_s[COG];
    __shared__ float red_s[COG], red_q[COG];

    const int tid = threadIdx.x;
    const int px = tid & 15, py = tid >> 4;
    constexpr int NG = COUT / COG;
    const int b = blockIdx.z / NG;
    const int co_base = (blockIdx.z % NG) * COG;
    const int ox0 = blockIdx.x*TILE, oy0 = blockIdx.y*TILE;
    const int ox = ox0 + px, oy = oy0 + py;

    // mask tile (padded with zeros)
    for (int i = tid; i < TPP; i += 256) {
        int gy = oy0 - DIL + i / TP;
        int gx = ox0 - DIL + i % TP;
        float v = 0.f;
        if (gy >= 0 && gy < Hh && gx >= 0 && gx < Ww)
            v = mask[b*HW + gy*Ww + gx];
        ms[i] = v;
    }
    if (tid < COG) { bias_s[tid] = bias[co_base + tid]; red_s[tid] = 0.f; red_q[tid] = 0.f; }
    __syncthreads();

    // overlap count + mask maxpool (shared taps)
    float cnt = 0.f, mn = 0.f;
    #pragma unroll
    for (int ky = 0; ky < 3; ky++)
        #pragma unroll
        for (int kx = 0; kx < 3; kx++) {
            float v = ms[(py + ky*DIL)*TP + px + kx*DIL];
            cnt += v; mn = fmaxf(mn, v);
        }
    cnt *= (float)CIN;
    const float inv_cnt = 1.f / fmaxf(cnt, 1e-5f);
    if (co_base == 0) mask_out[b*HW + oy*Ww + ox] = mn;

    float acc[COG];
    #pragma unroll
    for (int c = 0; c < COG; c++) acc[c] = 0.f;

    for (int ci0 = 0; ci0 < CIN; ci0 += CIC) {
        __syncthreads();
        // stage masked input chunk
        for (int i = tid; i < CIC*TPP; i += 256) {
            int ci = i / TPP, r = i % TPP;
            int gy = oy0 - DIL + r / TP;
            int gx = ox0 - DIL + r % TP;
            float v = 0.f;
            if (gy >= 0 && gy < Hh && gx >= 0 && gx < Ww)
                v = x[(b*CIN + ci0 + ci)*HW + gy*Ww + gx] * ms[r];
            xs[i] = v;
        }
        // stage weights transposed to [ci][k][co]
        for (int i = tid; i < CIC*9*COG; i += 256) {
            int co = i % COG;
            int k  = (i / COG) % 9;
            int ci = i / (9*COG);
            ws[i] = W[((co_base + co)*CIN + ci0 + ci)*9 + k];
        }
        __syncthreads();

        #pragma unroll 2
        for (int ci = 0; ci < CIC; ci++) {
            float t[9];
            #pragma unroll
            for (int ky = 0; ky < 3; ky++)
                #pragma unroll
                for (int kx = 0; kx < 3; kx++)
                    t[ky*3+kx] = xs[ci*TPP + (py + ky*DIL)*TP + px + kx*DIL];
            #pragma unroll
            for (int k = 0; k < 9; k++) {
                const float4* wv = reinterpret_cast<const float4*>(&ws[(ci*9 + k)*COG]);
                #pragma unroll
                for (int c4 = 0; c4 < COG/4; c4++) {
                    float4 w = wv[c4];
                    acc[4*c4+0] = fmaf(t[k], w.x, acc[4*c4+0]);
                    acc[4*c4+1] = fmaf(t[k], w.y, acc[4*c4+1]);
                    acc[4*c4+2] = fmaf(t[k], w.z, acc[4*c4+2]);
                    acc[4*c4+3] = fmaf(t[k], w.w, acc[4*c4+3]);
                }
            }
        }
    }

    // write y and accumulate BN statistics
    const int lane = tid & 31;
    const int out_base = (b*COUT + co_base)*HW + oy*Ww + ox;
    #pragma unroll 4
    for (int c = 0; c < COG; c++) {
        float yv = fmaf(acc[c], inv_cnt, bias_s[c]);
        y[out_base + c*HW] = yv;
        float s = yv, q = yv*yv;
        #pragma unroll
        for (int o = 16; o > 0; o >>= 1) {
            s += __shfl_down_sync(0xffffffffu, s, o);
            q += __shfl_down_sync(0xffffffffu, q, o);
        }
        if (lane == 0) { atomicAdd(&red_s[c], s); atomicAdd(&red_q[c], q); }
    }
    __syncthreads();
    if (tid < COG) {
        atomicAdd(&sums[co_base + tid],        red_s[tid]);
        atomicAdd(&sums[COUT + co_base + tid], red_q[tid]);
    }
}

// per-channel scale/shift from sums
__global__ void stats_kernel(const float* __restrict__ sums,
                             const float* __restrict__ g,
                             const float* __restrict__ be,
                             float* __restrict__ ss, int C)
{
    int c = threadIdx.x;
    if (c < C) {
        const float invN = 1.f / (float)NPIX;
        float mean = sums[c] * invN;
        float var  = sums[C + c] * invN - mean*mean;
        float sc = g[c] * rsqrtf(var + 1e-5f);
        ss[c]     = sc;
        ss[C + c] = fmaf(-mean, sc, be[c]);
    }
}

// in-place BN + LeakyReLU (float4)
__global__ void bn_apply_kernel(float* __restrict__ y, const float* __restrict__ ss,
                                int C, int n4)
{
    int i = blockIdx.x*blockDim.x + threadIdx.x;
    if (i >= n4) return;
    int c = (i >> 14) % C;   // 16384 float4 per (b, channel) plane
    float sc = ss[c], sh = ss[C + c];
    float4 v = reinterpret_cast<float4*>(y)[i];
    v.x = fmaf(v.x, sc, sh); v.x = v.x >= 0.f ? v.x : 0.01f*v.x;
    v.y = fmaf(v.y, sc, sh); v.y = v.y >= 0.f ? v.y : 0.01f*v.y;
    v.z = fmaf(v.z, sc, sh); v.z = v.z >= 0.f ? v.z : 0.01f*v.z;
    v.w = fmaf(v.w, sc, sh); v.w = v.w >= 0.f ? v.w : 0.01f*v.w;
    reinterpret_cast<float4*>(y)[i] = v;
}

// final 1x1 conv: 128 -> 64
__global__ void __launch_bounds__(256, 2) conv1x1_kernel(
    const float* __restrict__ x, const float* __restrict__ Wf,
    const float* __restrict__ bf, float* __restrict__ out)
{
    __shared__ __align__(16) float wt[128*64];   // [ci][o]
    const int tid = threadIdx.x;
    for (int i = tid; i < 128*64; i += 256) {
        int o = i & 63, ci = i >> 6;
        wt[i] = Wf[o*128 + ci];
    }
    __syncthreads();

    int p  = blockIdx.x*256 + tid;       // 0 .. 524287
    int b  = p >> 16;
    int hw = p & 65535;

    float acc[64];
    #pragma unroll
    for (int o = 0; o < 64; o++) acc[o] = 0.f;

    for (int ci = 0; ci < 128; ci++) {
        float xv = x[(b*128 + ci)*HW + hw];
        const float4* wv = reinterpret_cast<const float4*>(&wt[ci*64]);
        #pragma unroll
        for (int c4 = 0; c4 < 16; c4++) {
            float4 w = wv[c4];
            acc[4*c4+0] = fmaf(xv, w.x, acc[4*c4+0]);
            acc[4*c4+1] = fmaf(xv, w.y, acc[4*c4+1]);
            acc[4*c4+2] = fmaf(xv, w.z, acc[4*c4+2]);
            acc[4*c4+3] = fmaf(xv, w.w, acc[4*c4+3]);
        }
    }
    #pragma unroll
    for (int o = 0; o < 64; o++)
        out[(b*64 + o)*HW + hw] = acc[o] + __ldg(&bf[o]);
}

extern "C" void kernel_launch(void* const* d_in, const int* in_sizes, int n_in,
                              void* d_out, int out_size)
{
    const float* feat = (const float*)d_in[0];
    const float* mask = (const float*)d_in[1];
    const float* Wl[5]; const float* bl[5]; const float* gl[5]; const float* bel[5];
    for (int l = 0; l < 5; l++) {
        Wl[l]  = (const float*)d_in[2 + 4*l];
        bl[l]  = (const float*)d_in[3 + 4*l];
        gl[l]  = (const float*)d_in[4 + 4*l];
        bel[l] = (const float*)d_in[5 + 4*l];
    }
    const float* Wf = (const float*)d_in[22];
    const float* bf = (const float*)d_in[23];

    float *bufA, *bufB, *mA, *mB, *sums, *ss;
    cudaGetSymbolAddress((void**)&bufA, g_bufA);
    cudaGetSymbolAddress((void**)&bufB, g_bufB);
    cudaGetSymbolAddress((void**)&mA,   g_maskA);
    cudaGetSymbolAddress((void**)&mB,   g_maskB);
    cudaGetSymbolAddress((void**)&sums, g_sums);
    cudaGetSymbolAddress((void**)&ss,   g_ss);

    // L0: 32 -> 16, d=1   feat/mask -> bufA/mA
    cudaMemsetAsync(sums, 0, 2*16*sizeof(float));
    conv_block_kernel<32,16,1,16><<<dim3(16,16,8), 256>>>(feat, mask, Wl[0], bl[0], bufA, mA, sums);
    stats_kernel<<<1,256>>>(sums, gl[0], bel[0], ss, 16);
    bn_apply_kernel<<<(16*131072 + 255)/256, 256>>>(bufA, ss, 16, 16*131072);

    // L1: 16 -> 32, d=2   bufA/mA -> bufB/mB
    cudaMemsetAsync(sums, 0, 2*32*sizeof(float));
    conv_block_kernel<16,32,2,32><<<dim3(16,16,8), 256>>>(bufA, mA, Wl[1], bl[1], bufB, mB, sums);
    stats_kernel<<<1,256>>>(sums, gl[1], bel[1], ss, 32);
    bn_apply_kernel<<<(32*131072 + 255)/256, 256>>>(bufB, ss, 32, 32*131072);

    // L2: 32 -> 64, d=1   bufB/mB -> bufA/mA
    cudaMemsetAsync(sums, 0, 2*64*sizeof(float));
    conv_block_kernel<32,64,1,64><<<dim3(16,16,8), 256>>>(bufB, mB, Wl[2], bl[2], bufA, mA, sums);
    stats_kernel<<<1,256>>>(sums, gl[2], bel[2], ss, 64);
    bn_apply_kernel<<<(64*131072 + 255)/256, 256>>>(bufA, ss, 64, 64*131072);

    // L3: 64 -> 64, d=2   bufA/mA -> bufB/mB
    cudaMemsetAsync(sums, 0, 2*64*sizeof(float));
    conv_block_kernel<64,64,2,64><<<dim3(16,16,8), 256>>>(bufA, mA, Wl[3], bl[3], bufB, mB, sums);
    stats_kernel<<<1,256>>>(sums, gl[3], bel[3], ss, 64);
    bn_apply_kernel<<<(64*131072 + 255)/256, 256>>>(bufB, ss, 64, 64*131072);

    // L4: 64 -> 128, d=1  bufB/mB -> bufA/mA  (two co-groups of 64)
    cudaMemsetAsync(sums, 0, 2*128*sizeof(float));
    conv_block_kernel<64,128,1,64><<<dim3(16,16,16), 256>>>(bufB, mB, Wl[4], bl[4], bufA, mA, sums);
    stats_kernel<<<1,256>>>(sums, gl[4], bel[4], ss, 128);
    bn_apply_kernel<<<(128*131072 + 255)/256, 256>>>(bufA, ss, 128, 128*131072);

    // final 1x1 conv -> d_out[0 : 8*64*65536)
    conv1x1_kernel<<<2048, 256>>>(bufA, Wf, bf, (float*)d_out);

    // final mask -> d_out[8*64*65536 : +8*65536)  (concat packing of the tuple)
    const int xelems = Bb*64*HW;
    const int melems = Bb*HW;
    if (out_size >= xelems + melems) {
        cudaMemcpyAsync((float*)d_out + xelems, mA, (size_t)melems*sizeof(float),
                        cudaMemcpyDeviceToDevice);
    }
}

// round 2
// speedup vs baseline: 1.1652x; 1.1652x over previous
#include <cuda_runtime.h>
#include <cstdint>

#define Hh 256
#define Ww 256
#define Bb 8
#define HW 65536
#define NPIX (Bb*HW)   // 524288

// Scratch (device globals — no allocation allowed)
__device__ float g_bufA[(size_t)Bb*128*HW];
__device__ float g_bufB[(size_t)Bb*128*HW];
__device__ float g_maskA[(size_t)Bb*HW];
__device__ float g_maskB[(size_t)Bb*HW];
__device__ float g_sums[256];
__device__ float g_ss[256];

// ---------------------------------------------------------------------------
// tf32 helpers
// ---------------------------------------------------------------------------
__device__ __forceinline__ uint32_t tf32_of(float v) {
    uint32_t r; asm("cvt.rna.tf32.f32 %0, %1;" : "=r"(r) : "f"(v)); return r;
}
// split v into (hi, lo) tf32 pair: hi + lo ~= v to ~21 mantissa bits
__device__ __forceinline__ float2 split_tf32(float v) {
    uint32_t h = tf32_of(v);
    float hf = __uint_as_float(h);
    uint32_t l = tf32_of(v - hf);
    return make_float2(hf, __uint_as_float(l));
}
// D += A(16x8) * B(8x8), tf32 operands, fp32 accum
__device__ __forceinline__ void mma8(float* c,
                                     float a0, float a1, float a2, float a3,
                                     float b0, float b1) {
    asm volatile(
        "mma.sync.aligned.m16n8k8.row.col.f32.tf32.tf32.f32 "
        "{%0,%1,%2,%3},{%4,%5,%6,%7},{%8,%9},{%0,%1,%2,%3};"
        : "+f"(c[0]), "+f"(c[1]), "+f"(c[2]), "+f"(c[3])
        : "r"(__float_as_uint(a0)), "r"(__float_as_uint(a1)),
          "r"(__float_as_uint(a2)), "r"(__float_as_uint(a3)),
          "r"(__float_as_uint(b0)), "r"(__float_as_uint(b1)));
}

// ---------------------------------------------------------------------------
// Fused sparse-conv block, tf32 MMA implicit GEMM.
//   Input staging applies previous layer's BN (scale/shift in ssv) + LeakyReLU,
//   then multiplies by the layer's input mask. 3-term tf32 split for precision.
//   Epilogue: /count, +bias, y write, BN-statistics accumulation, mask maxpool.
// Warp tile: 16 out-channels x 64 px (8 n-fragments). k-step = 8 ci x 1 tap.
// ---------------------------------------------------------------------------
template<int CIN, int CO_BLK, int NSPLIT, int DIL, int PXT, int WARPS, bool FUSE_BN>
__global__ void __launch_bounds__(WARPS*32, 2) conv_mma_kernel(
    const float* __restrict__ xin, const float* __restrict__ min_,
    const float* __restrict__ Wg,  const float* __restrict__ bg,
    const float* __restrict__ ssv,
    float* __restrict__ yout, float* __restrict__ mout,
    float* __restrict__ sums)
{
    constexpr int NT    = WARPS*32;
    constexpr int PXG   = WARPS*16/CO_BLK;      // px groups (warps per px strip)
    constexpr int XW    = PXT + 2*DIL;          // staged width (valid cols)
    constexpr int WPX   = PXT + 12;             // padded stride (float2 units)
    constexpr int COpad = CO_BLK + 4;           // padded co stride (float2 units)
    constexpr int COUTT = CO_BLK*NSPLIT;
    constexpr int TX    = 256/PXT;              // tiles per image row

    extern __shared__ char dsm[];
    float2* xt  = (float2*)dsm;                 // [8*3][WPX]   (hi,lo) inputs
    float2* wt  = xt + 24*WPX;                  // [72][COpad]  (hi,lo) weights
    float*  msk = (float*)(wt + 72*COpad);      // [3][WPX]
    float*  invc= msk + 3*WPX;                  // [PXT]
    float*  red = invc + PXT;                   // [2*CO_BLK]

    const int tid  = threadIdx.x;
    const int lane = tid & 31, warp = tid >> 5;
    const int g    = lane >> 2, tig = lane & 3;
    const int cog  = warp / PXG, pxg = warp % PXG;
    const int pxb  = pxg * 64;

    const int tile = blockIdx.x;
    const int x0 = (tile % TX) * PXT;
    const int y0 = tile / TX;
    const int z  = blockIdx.z;
    const int b  = z / NSPLIT;
    const int split = z % NSPLIT;
    const int co_base = split * CO_BLK;

    // --- stage mask rows (3 rows: y0-d, y0, y0+d) ---
    for (int i = tid; i < 3*XW; i += NT) {
        int col = i % XW, r = i / XW;
        int gy = y0 + (r-1)*DIL, gx = x0 - DIL + col;
        float v = 0.f;
        if (gy >= 0 && gy < Hh && gx >= 0 && gx < Ww) v = min_[b*HW + gy*Ww + gx];
        msk[r*WPX + col] = v;
    }
    for (int i = tid; i < 2*CO_BLK; i += NT) red[i] = 0.f;
    __syncthreads();

    // --- per-pixel 1/count + mask maxpool ---
    for (int px = tid; px < PXT; px += NT) {
        float cnt = 0.f, mn = 0.f;
        #pragma unroll
        for (int ky = 0; ky < 3; ky++)
            #pragma unroll
            for (int kx = 0; kx < 3; kx++) {
                float v = msk[ky*WPX + px + kx*DIL];
                cnt += v; mn = fmaxf(mn, v);
            }
        invc[px] = 1.f / fmaxf(cnt * (float)CIN, 1e-5f);
        if (split == 0) mout[b*HW + y0*Ww + x0 + px] = mn;
    }

    float c[8][4];
    #pragma unroll
    for (int f = 0; f < 8; f++) { c[f][0]=0.f; c[f][1]=0.f; c[f][2]=0.f; c[f][3]=0.f; }

    for (int ci0 = 0; ci0 < CIN; ci0 += 8) {
        __syncthreads();
        // stage weights chunk: [tap][ci][co] as (hi,lo)
        for (int i = tid; i < 72*CO_BLK; i += NT) {
            int co = i % CO_BLK, ci = (i/CO_BLK) & 7, t = i/(CO_BLK*8);
            float v = Wg[((co_base + co)*CIN + ci0 + ci)*9 + t];
            wt[(t*8 + ci)*COpad + co] = split_tf32(v);
        }
        // stage masked (+BN'd) input chunk: [ci][row][col] as (hi,lo)
        for (int i = tid; i < 24*XW; i += NT) {
            int col = i % XW, r = (i/XW) % 3, ci = i/(3*XW);
            int gy = y0 + (r-1)*DIL, gx = x0 - DIL + col;
            float v = 0.f;
            if (gy >= 0 && gy < Hh && gx >= 0 && gx < Ww) {
                float raw = xin[(size_t)(b*CIN + ci0 + ci)*HW + gy*Ww + gx];
                if (FUSE_BN) {
                    raw = fmaf(raw, ssv[ci0 + ci], ssv[CIN + ci0 + ci]);
                    raw = raw >= 0.f ? raw : 0.01f*raw;
                }
                v = raw * msk[r*WPX + col];
            }
            xt[(ci*3 + r)*WPX + col] = split_tf32(v);
        }
        __syncthreads();

        #pragma unroll 1
        for (int t = 0; t < 9; t++) {
            const int ky = t/3, kx = t - 3*ky;
            const int cb = cog*16;
            float2 a0 = wt[(t*8 + tig  )*COpad + cb + g    ];
            float2 a1 = wt[(t*8 + tig  )*COpad + cb + g + 8];
            float2 a2 = wt[(t*8 + tig+4)*COpad + cb + g    ];
            float2 a3 = wt[(t*8 + tig+4)*COpad + cb + g + 8];
            const float2* brow0 = &xt[(tig    *3 + ky)*WPX + pxb + kx*DIL + g];
            const float2* brow1 = &xt[((tig+4)*3 + ky)*WPX + pxb + kx*DIL + g];
            #pragma unroll
            for (int f = 0; f < 8; f++) {
                float2 b0 = brow0[f*8];
                float2 b1 = brow1[f*8];
                mma8(c[f], a0.x, a1.x, a2.x, a3.x, b0.x, b1.x);  // hi*hi
                mma8(c[f], a0.x, a1.x, a2.x, a3.x, b0.y, b1.y);  // hi*lo
                mma8(c[f], a0.y, a1.y, a2.y, a3.y, b0.x, b1.x);  // lo*hi
            }
        }
    }

    // --- epilogue: normalize, bias, write y, accumulate BN stats ---
    const int gco0 = co_base + cog*16 + g;
    const int gco1 = gco0 + 8;
    const float b0v = bg[gco0], b1v = bg[gco1];
    float* rowp0 = yout + (size_t)(b*COUTT + gco0)*HW + y0*Ww + x0;
    float* rowp1 = yout + (size_t)(b*COUTT + gco1)*HW + y0*Ww + x0;
    float s0 = 0.f, q0 = 0.f, s1 = 0.f, q1 = 0.f;
    #pragma unroll
    for (int f = 0; f < 8; f++) {
        int pxl = pxb + f*8 + 2*tig;
        float i0 = invc[pxl], i1 = invc[pxl + 1];
        float y00 = fmaf(c[f][0], i0, b0v);
        float y01 = fmaf(c[f][1], i1, b0v);
        float y10 = fmaf(c[f][2], i0, b1v);
        float y11 = fmaf(c[f][3], i1, b1v);
        *(float2*)(rowp0 + pxl) = make_float2(y00, y01);
        *(float2*)(rowp1 + pxl) = make_float2(y10, y11);
        s0 += y00 + y01; q0 += y00*y00 + y01*y01;
        s1 += y10 + y11; q1 += y10*y10 + y11*y11;
    }
    #pragma unroll
    for (int o = 1; o <= 2; o <<= 1) {
        s0 += __shfl_xor_sync(0xffffffffu, s0, o);
        q0 += __shfl_xor_sync(0xffffffffu, q0, o);
        s1 += __shfl_xor_sync(0xffffffffu, s1, o);
        q1 += __shfl_xor_sync(0xffffffffu, q1, o);
    }
    if (tig == 0) {
        atomicAdd(&red[cog*16 + g],              s0);
        atomicAdd(&red[CO_BLK + cog*16 + g],     q0);
        atomicAdd(&red[cog*16 + g + 8],          s1);
        atomicAdd(&red[CO_BLK + cog*16 + g + 8], q1);
    }
    __syncthreads();
    if (tid < CO_BLK) {
        atomicAdd(&sums[co_base + tid],          red[tid]);
        atomicAdd(&sums[COUTT + co_base + tid],  red[CO_BLK + tid]);
    }
}

// per-channel scale/shift from sums
__global__ void stats_kernel(const float* __restrict__ sums,
                             const float* __restrict__ g,
                             const float* __restrict__ be,
                             float* __restrict__ ss, int C)
{
    int c = threadIdx.x;
    if (c < C) {
        const float invN = 1.f / (float)NPIX;
        float mean = sums[c] * invN;
        float var  = sums[C + c] * invN - mean*mean;
        float sc = g[c] * rsqrtf(var + 1e-5f);
        ss[c]     = sc;
        ss[C + c] = fmaf(-mean, sc, be[c]);
    }
}

// ---------------------------------------------------------------------------
// final 1x1 conv 128 -> 64 via tf32 MMA; applies layer-4 BN+LeakyReLU on load
// ---------------------------------------------------------------------------
__global__ void __launch_bounds__(256, 2) conv1x1_mma_kernel(
    const float* __restrict__ xin, const float* __restrict__ ssv,
    const float* __restrict__ Wg,  const float* __restrict__ bg,
    float* __restrict__ out)
{
    constexpr int CIN = 128, CO = 64, PXT = 128, WPX1 = 132, COpad = 68;
    __shared__ float2 xt[8*WPX1];
    __shared__ float2 wt[8*COpad];

    const int tid = threadIdx.x, lane = tid & 31, warp = tid >> 5;
    const int g = lane >> 2, tig = lane & 3;
    const int cog = warp >> 1, pxg = warp & 1;   // 4 co-groups x 2 px-groups
    const int pxb = pxg * 64;
    const int tile = blockIdx.x;
    const int x0 = (tile & 1)*PXT, y0 = tile >> 1;
    const int b  = blockIdx.z;

    float c[8][4];
    #pragma unroll
    for (int f = 0; f < 8; f++) { c[f][0]=0.f; c[f][1]=0.f; c[f][2]=0.f; c[f][3]=0.f; }

    for (int ci0 = 0; ci0 < CIN; ci0 += 8) {
        __syncthreads();
        for (int i = tid; i < 8*CO; i += 256) {
            int co = i % CO, ci = i / CO;
            wt[ci*COpad + co] = split_tf32(Wg[co*CIN + ci0 + ci]);
        }
        for (int i = tid; i < 8*PXT; i += 256) {
            int col = i % PXT, ci = i / PXT;
            float raw = xin[(size_t)(b*CIN + ci0 + ci)*HW + y0*Ww + x0 + col];
            raw = fmaf(raw, ssv[ci0 + ci], ssv[CIN + ci0 + ci]);
            raw = raw >= 0.f ? raw : 0.01f*raw;
            xt[ci*WPX1 + col] = split_tf32(raw);
        }
        __syncthreads();
        float2 a0 = wt[tig    *COpad + cog*16 + g    ];
        float2 a1 = wt[tig    *COpad + cog*16 + g + 8];
        float2 a2 = wt[(tig+4)*COpad + cog*16 + g    ];
        float2 a3 = wt[(tig+4)*COpad + cog*16 + g + 8];
        #pragma unroll
        for (int f = 0; f < 8; f++) {
            float2 b0 = xt[tig    *WPX1 + pxb + f*8 + g];
            float2 b1 = xt[(tig+4)*WPX1 + pxb + f*8 + g];
            mma8(c[f], a0.x, a1.x, a2.x, a3.x, b0.x, b1.x);
            mma8(c[f], a0.x, a1.x, a2.x, a3.x, b0.y, b1.y);
            mma8(c[f], a0.y, a1.y, a2.y, a3.y, b0.x, b1.x);
        }
    }
    const int co0 = cog*16 + g, co1 = co0 + 8;
    const float b0v = bg[co0], b1v = bg[co1];
    float* r0 = out + (size_t)(b*CO + co0)*HW + y0*Ww + x0;
    float* r1 = out + (size_t)(b*CO + co1)*HW + y0*Ww + x0;
    #pragma unroll
    for (int f = 0; f < 8; f++) {
        int pxl = pxb + f*8 + 2*tig;
        *(float2*)(r0 + pxl) = make_float2(c[f][0] + b0v, c[f][1] + b0v);
        *(float2*)(r1 + pxl) = make_float2(c[f][2] + b1v, c[f][3] + b1v);
    }
}

// ---------------------------------------------------------------------------
extern "C" void kernel_launch(void* const* d_in, const int* in_sizes, int n_in,
                              void* d_out, int out_size)
{
    const float* feat = (const float*)d_in[0];
    const float* mask = (const float*)d_in[1];
    const float* Wl[5]; const float* bl[5]; const float* gl[5]; const float* bel[5];
    for (int l = 0; l < 5; l++) {
        Wl[l]  = (const float*)d_in[2 + 4*l];
        bl[l]  = (const float*)d_in[3 + 4*l];
        gl[l]  = (const float*)d_in[4 + 4*l];
        bel[l] = (const float*)d_in[5 + 4*l];
    }
    const float* Wf = (const float*)d_in[22];
    const float* bf = (const float*)d_in[23];

    float *bufA, *bufB, *mA, *mB, *sums, *ss;
    cudaGetSymbolAddress((void**)&bufA, g_bufA);
    cudaGetSymbolAddress((void**)&bufB, g_bufB);
    cudaGetSymbolAddress((void**)&mA,   g_maskA);
    cudaGetSymbolAddress((void**)&mB,   g_maskB);
    cudaGetSymbolAddress((void**)&sums, g_sums);
    cudaGetSymbolAddress((void**)&ss,   g_ss);

    // smem sizes (bytes): 24*WPX*8 + 72*COpad*8 + 3*WPX*4 + PXT*4 + 2*CO_BLK*4
    const int smem_L0 = 24*268*8 + 72*20*8 + 3*268*4 + 256*4 + 2*16*4;   // 67344
    const int smem_L1 = 24*268*8 + 72*36*8 + 3*268*4 + 256*4 + 2*32*4;   // 76688
    const int smem_Lx = 24*140*8 + 72*68*8 + 3*140*4 + 128*4 + 2*64*4;   // 68752

    auto k0 = conv_mma_kernel<32,16,1,1,256,4,false>;
    auto k1 = conv_mma_kernel<16,32,1,2,256,8,true>;
    auto k2 = conv_mma_kernel<32,64,1,1,128,8,true>;
    auto k3 = conv_mma_kernel<64,64,1,2,128,8,true>;
    auto k4 = conv_mma_kernel<64,64,2,1,128,8,true>;
    cudaFuncSetAttribute(k0, cudaFuncAttributeMaxDynamicSharedMemorySize, smem_L0);
    cudaFuncSetAttribute(k1, cudaFuncAttributeMaxDynamicSharedMemorySize, smem_L1);
    cudaFuncSetAttribute(k2, cudaFuncAttributeMaxDynamicSharedMemorySize, smem_Lx);
    cudaFuncSetAttribute(k3, cudaFuncAttributeMaxDynamicSharedMemorySize, smem_Lx);
    cudaFuncSetAttribute(k4, cudaFuncAttributeMaxDynamicSharedMemorySize, smem_Lx);

    // L0: 32 -> 16, d=1   feat/mask -> bufA/mA   (no BN on input)
    cudaMemsetAsync(sums, 0, 2*16*sizeof(float));
    k0<<<dim3(256,1,8), 128, smem_L0>>>(feat, mask, Wl[0], bl[0], nullptr, bufA, mA, sums);
    stats_kernel<<<1,256>>>(sums, gl[0], bel[0], ss, 16);

    // L1: 16 -> 32, d=2   bufA/mA -> bufB/mB   (BN0 fused on load)
    cudaMemsetAsync(sums, 0, 2*32*sizeof(float));
    k1<<<dim3(256,1,8), 256, smem_L1>>>(bufA, mA, Wl[1], bl[1], ss, bufB, mB, sums);
    stats_kernel<<<1,256>>>(sums, gl[1], bel[1], ss, 32);

    // L2: 32 -> 64, d=1   bufB/mB -> bufA/mA
    cudaMemsetAsync(sums, 0, 2*64*sizeof(float));
    k2<<<dim3(512,1,8), 256, smem_Lx>>>(bufB, mB, Wl[2], bl[2], ss, bufA, mA, sums);
    stats_kernel<<<1,256>>>(sums, gl[2], bel[2], ss, 64);

    // L3: 64 -> 64, d=2   bufA/mA -> bufB/mB
    cudaMemsetAsync(sums, 0, 2*64*sizeof(float));
    k3<<<dim3(512,1,8), 256, smem_Lx>>>(bufA, mA, Wl[3], bl[3], ss, bufB, mB, sums);
    stats_kernel<<<1,256>>>(sums, gl[3], bel[3], ss, 64);

    // L4: 64 -> 128, d=1  bufB/mB -> bufA/mA  (2 co-splits)
    cudaMemsetAsync(sums, 0, 2*128*sizeof(float));
    k4<<<dim3(512,1,16), 256, smem_Lx>>>(bufB, mB, Wl[4], bl[4], ss, bufA, mA, sums);
    stats_kernel<<<1,256>>>(sums, gl[4], bel[4], ss, 128);

    // final 1x1 conv (BN4 fused on load) -> d_out[0 : 8*64*65536)
    conv1x1_mma_kernel<<<dim3(512,1,8), 256>>>(bufA, ss, Wf, bf, (float*)d_out);

    // final mask -> d_out[8*64*65536 : +8*65536)
    const int xelems = Bb*64*HW;
    const int melems = Bb*HW;
    if (out_size >= xelems + melems) {
        cudaMemcpyAsync((float*)d_out + xelems, mA, (size_t)melems*sizeof(float),
                        cudaMemcpyDeviceToDevice);
    }
}

// round 3
// speedup vs baseline: 1.4713x; 1.2628x over previous
#include <cuda_runtime.h>
#include <cstdint>

#define Hh 256
#define Ww 256
#define Bb 8
#define HW 65536
#define NPIX (Bb*HW)   // 524288

// Scratch (device globals — no allocation allowed)
__device__ float g_bufA[(size_t)Bb*128*HW];
__device__ float g_bufB[(size_t)Bb*128*HW];
__device__ float g_maskA[(size_t)Bb*HW];
__device__ float g_maskB[(size_t)Bb*HW];
__device__ float g_sums[256];
__device__ float g_ss[256];
__device__ float2 g_wsplit[140000];   // pre-split tf32 weights, all conv layers

// ---------------------------------------------------------------------------
// tf32 helpers
// ---------------------------------------------------------------------------
__device__ __forceinline__ uint32_t tf32_of(float v) {
    uint32_t r; asm("cvt.rna.tf32.f32 %0, %1;" : "=r"(r) : "f"(v)); return r;
}
__device__ __forceinline__ float2 split_tf32(float v) {
    uint32_t h = tf32_of(v);
    float hf = __uint_as_float(h);
    uint32_t l = tf32_of(v - hf);
    return make_float2(hf, __uint_as_float(l));
}
__device__ __forceinline__ void mma8(float* c,
                                     float a0, float a1, float a2, float a3,
                                     float b0, float b1) {
    asm volatile(
        "mma.sync.aligned.m16n8k8.row.col.f32.tf32.tf32.f32 "
        "{%0,%1,%2,%3},{%4,%5,%6,%7},{%8,%9},{%0,%1,%2,%3};"
        : "+f"(c[0]), "+f"(c[1]), "+f"(c[2]), "+f"(c[3])
        : "r"(__float_as_uint(a0)), "r"(__float_as_uint(a1)),
          "r"(__float_as_uint(a2)), "r"(__float_as_uint(a3)),
          "r"(__float_as_uint(b0)), "r"(__float_as_uint(b1)));
}

// ---------------------------------------------------------------------------
// Weight pre-split: W[co_g][ci][3][3] -> float2(hi,lo) at
//   [(s*chunks + q)*72 + t*8 + ci_local]*CO_BLK + co
// ---------------------------------------------------------------------------
__global__ void presplit_kernel(const float* __restrict__ W, float2* __restrict__ dst,
                                int CIN, int CO_BLK, int total)
{
    int i = blockIdx.x*256 + threadIdx.x;
    if (i >= total) return;
    int co   = i % CO_BLK;
    int ci   = (i / CO_BLK) & 7;
    int t    = (i / (CO_BLK*8)) % 9;
    int rest = i / (CO_BLK*72);       // s*chunks + q
    int chunks = CIN >> 3;
    int q = rest % chunks;
    int s = rest / chunks;
    float v = W[(((s*CO_BLK + co)*CIN) + q*8 + ci)*9 + t];
    dst[i] = split_tf32(v);
}

// ---------------------------------------------------------------------------
// Fused sparse-conv block, tf32 MMA implicit GEMM, A from pre-split gmem.
// ---------------------------------------------------------------------------
template<int CIN, int CO_BLK, int NSPLIT, int DIL, int PXT, int WARPS, bool FUSE_BN>
__global__ void __launch_bounds__(WARPS*32, 2) conv_mma_kernel(
    const float* __restrict__ xin, const float* __restrict__ min_,
    const float2* __restrict__ wsplit, const float* __restrict__ bg,
    const float* __restrict__ ssv,
    float* __restrict__ yout, float* __restrict__ mout,
    float* __restrict__ sums)
{
    constexpr int NT    = WARPS*32;
    constexpr int PXG   = WARPS*16/CO_BLK;      // px groups
    constexpr int XW    = PXT + 2*DIL;
    constexpr int WPX   = PXT + 12;             // padded stride (float2 units)
    constexpr int COUTT = CO_BLK*NSPLIT;
    constexpr int TX    = 256/PXT;
    constexpr int CHUNKS = CIN/8;

    extern __shared__ char dsm[];
    float2* xt  = (float2*)dsm;                 // [24][WPX]
    float*  msk = (float*)(xt + 24*WPX);        // [3][WPX]
    float*  invc= msk + 3*WPX;                  // [PXT]
    float*  red = invc + PXT;                   // [2*CO_BLK]

    const int tid  = threadIdx.x;
    const int lane = tid & 31, warp = tid >> 5;
    const int g    = lane >> 2, tig = lane & 3;
    const int cog  = warp / PXG, pxg = warp % PXG;
    const int pxb  = pxg * 64;
    const int cb   = cog * 16;

    const int tile = blockIdx.x;
    const int x0 = (tile % TX) * PXT;
    const int y0 = tile / TX;
    const int z  = blockIdx.z;
    const int b  = z / NSPLIT;
    const int split = z % NSPLIT;
    const int co_base = split * CO_BLK;

    // --- stage mask rows ---
    for (int i = tid; i < 3*XW; i += NT) {
        int col = i % XW, r = i / XW;
        int gy = y0 + (r-1)*DIL, gx = x0 - DIL + col;
        float v = 0.f;
        if (gy >= 0 && gy < Hh && gx >= 0 && gx < Ww) v = min_[b*HW + gy*Ww + gx];
        msk[r*WPX + col] = v;
    }
    for (int i = tid; i < 2*CO_BLK; i += NT) red[i] = 0.f;
    __syncthreads();

    // --- per-pixel 1/count + mask maxpool ---
    for (int px = tid; px < PXT; px += NT) {
        float cnt = 0.f, mn = 0.f;
        #pragma unroll
        for (int ky = 0; ky < 3; ky++)
            #pragma unroll
            for (int kx = 0; kx < 3; kx++) {
                float v = msk[ky*WPX + px + kx*DIL];
                cnt += v; mn = fmaxf(mn, v);
            }
        invc[px] = 1.f / fmaxf(cnt * (float)CIN, 1e-5f);
        if (split == 0) mout[b*HW + y0*Ww + x0 + px] = mn;
    }

    float c[8][4];
    #pragma unroll
    for (int f = 0; f < 8; f++) { c[f][0]=0.f; c[f][1]=0.f; c[f][2]=0.f; c[f][3]=0.f; }

    for (int q = 0; q < CHUNKS; q++) {
        __syncthreads();
        // --- stage masked (+BN) input chunk: warp-per-ci, lane-per-col ---
        for (int ci = warp; ci < 8; ci += WARPS) {
            float sc = 1.f, sh = 0.f;
            if (FUSE_BN) { sc = ssv[q*8 + ci]; sh = ssv[CIN + q*8 + ci]; }
            const float* srcbase = xin + (size_t)(b*CIN + q*8 + ci)*HW + (x0 - DIL);
            #pragma unroll
            for (int r = 0; r < 3; r++) {
                int gy = y0 + (r-1)*DIL;
                float2* dstrow = &xt[(ci*3 + r)*WPX];
                if ((unsigned)gy < (unsigned)Hh) {
                    const float* src = srcbase + gy*Ww;
                    for (int col = lane; col < XW; col += 32) {
                        int gx = x0 - DIL + col;
                        float v = 0.f;
                        if ((unsigned)gx < (unsigned)Ww) {
                            v = src[col];
                            if (FUSE_BN) {
                                v = fmaf(v, sc, sh);
                                v = v >= 0.f ? v : 0.01f*v;
                            }
                            v *= msk[r*WPX + col];
                        }
                        dstrow[col] = split_tf32(v);
                    }
                } else {
                    for (int col = lane; col < XW; col += 32)
                        dstrow[col] = make_float2(0.f, 0.f);
                }
            }
        }
        __syncthreads();

        const float2* Ab = wsplit + (size_t)(split*CHUNKS + q)*72*CO_BLK + cb + g;
        #pragma unroll 3
        for (int t = 0; t < 9; t++) {
            const int ky = t/3, kx = t - 3*ky;
            const float2* Ap = Ab + t*8*CO_BLK;
            float2 a0 = __ldg(Ap + tig*CO_BLK);
            float2 a1 = __ldg(Ap + tig*CO_BLK + 8);
            float2 a2 = __ldg(Ap + (tig+4)*CO_BLK);
            float2 a3 = __ldg(Ap + (tig+4)*CO_BLK + 8);
            const float2* brow0 = &xt[(tig    *3 + ky)*WPX + pxb + kx*DIL + g];
            const float2* brow1 = &xt[((tig+4)*3 + ky)*WPX + pxb + kx*DIL + g];
            #pragma unroll
            for (int f = 0; f < 8; f++) {
                float2 b0 = brow0[f*8];
                float2 b1 = brow1[f*8];
                mma8(c[f], a0.x, a1.x, a2.x, a3.x, b0.x, b1.x);  // hi*hi
                mma8(c[f], a0.x, a1.x, a2.x, a3.x, b0.y, b1.y);  // hi*lo
                mma8(c[f], a0.y, a1.y, a2.y, a3.y, b0.x, b1.x);  // lo*hi
            }
        }
    }

    // --- epilogue ---
    const int gco0 = co_base + cb + g;
    const int gco1 = gco0 + 8;
    const float b0v = bg[gco0], b1v = bg[gco1];
    float* rowp0 = yout + (size_t)(b*COUTT + gco0)*HW + y0*Ww + x0;
    float* rowp1 = yout + (size_t)(b*COUTT + gco1)*HW + y0*Ww + x0;
    float s0 = 0.f, q0 = 0.f, s1 = 0.f, q1 = 0.f;
    #pragma unroll
    for (int f = 0; f < 8; f++) {
        int pxl = pxb + f*8 + 2*tig;
        float i0 = invc[pxl], i1 = invc[pxl + 1];
        float y00 = fmaf(c[f][0], i0, b0v);
        float y01 = fmaf(c[f][1], i1, b0v);
        float y10 = fmaf(c[f][2], i0, b1v);
        float y11 = fmaf(c[f][3], i1, b1v);
        *(float2*)(rowp0 + pxl) = make_float2(y00, y01);
        *(float2*)(rowp1 + pxl) = make_float2(y10, y11);
        s0 += y00 + y01; q0 += y00*y00 + y01*y01;
        s1 += y10 + y11; q1 += y10*y10 + y11*y11;
    }
    #pragma unroll
    for (int o = 1; o <= 2; o <<= 1) {
        s0 += __shfl_xor_sync(0xffffffffu, s0, o);
        q0 += __shfl_xor_sync(0xffffffffu, q0, o);
        s1 += __shfl_xor_sync(0xffffffffu, s1, o);
        q1 += __shfl_xor_sync(0xffffffffu, q1, o);
    }
    if (tig == 0) {
        atomicAdd(&red[cb + g],              s0);
        atomicAdd(&red[CO_BLK + cb + g],     q0);
        atomicAdd(&red[cb + g + 8],          s1);
        atomicAdd(&red[CO_BLK + cb + g + 8], q1);
    }
    __syncthreads();
    if (tid < CO_BLK) {
        atomicAdd(&sums[co_base + tid],          red[tid]);
        atomicAdd(&sums[COUTT + co_base + tid],  red[CO_BLK + tid]);
    }
}

// per-channel scale/shift from sums
__global__ void stats_kernel(const float* __restrict__ sums,
                             const float* __restrict__ g,
                             const float* __restrict__ be,
                             float* __restrict__ ss, int C)
{
    int c = threadIdx.x;
    if (c < C) {
        const float invN = 1.f / (float)NPIX;
        float mean = sums[c] * invN;
        float var  = sums[C + c] * invN - mean*mean;
        float sc = g[c] * rsqrtf(var + 1e-5f);
        ss[c]     = sc;
        ss[C + c] = fmaf(-mean, sc, be[c]);
    }
}

// ---------------------------------------------------------------------------
// final 1x1 conv 128 -> 64 via tf32 MMA; applies layer-4 BN+LeakyReLU on load
// ---------------------------------------------------------------------------
__global__ void __launch_bounds__(256, 2) conv1x1_mma_kernel(
    const float* __restrict__ xin, const float* __restrict__ ssv,
    const float* __restrict__ Wg,  const float* __restrict__ bg,
    float* __restrict__ out)
{
    constexpr int CIN = 128, CO = 64, PXT = 128, WPX1 = 132, COpad = 68;
    __shared__ float2 xt[8*WPX1];
    __shared__ float2 wt[8*COpad];

    const int tid = threadIdx.x, lane = tid & 31, warp = tid >> 5;
    const int g = lane >> 2, tig = lane & 3;
    const int cog = warp >> 1, pxg = warp & 1;
    const int pxb = pxg * 64;
    const int tile = blockIdx.x;
    const int x0 = (tile & 1)*PXT, y0 = tile >> 1;
    const int b  = blockIdx.z;

    float c[8][4];
    #pragma unroll
    for (int f = 0; f < 8; f++) { c[f][0]=0.f; c[f][1]=0.f; c[f][2]=0.f; c[f][3]=0.f; }

    for (int ci0 = 0; ci0 < CIN; ci0 += 8) {
        __syncthreads();
        for (int i = tid; i < 8*CO; i += 256) {
            int co = i % CO, ci = i / CO;
            wt[ci*COpad + co] = split_tf32(Wg[co*CIN + ci0 + ci]);
        }
        for (int i = tid; i < 8*PXT; i += 256) {
            int col = i & 127, ci = i >> 7;
            float raw = xin[(size_t)(b*CIN + ci0 + ci)*HW + y0*Ww + x0 + col];
            raw = fmaf(raw, ssv[ci0 + ci], ssv[CIN + ci0 + ci]);
            raw = raw >= 0.f ? raw : 0.01f*raw;
            xt[ci*WPX1 + col] = split_tf32(raw);
        }
        __syncthreads();
        float2 a0 = wt[tig    *COpad + cog*16 + g    ];
        float2 a1 = wt[tig    *COpad + cog*16 + g + 8];
        float2 a2 = wt[(tig+4)*COpad + cog*16 + g    ];
        float2 a3 = wt[(tig+4)*COpad + cog*16 + g + 8];
        #pragma unroll
        for (int f = 0; f < 8; f++) {
            float2 b0 = xt[tig    *WPX1 + pxb + f*8 + g];
            float2 b1 = xt[(tig+4)*WPX1 + pxb + f*8 + g];
            mma8(c[f], a0.x, a1.x, a2.x, a3.x, b0.x, b1.x);
            mma8(c[f], a0.x, a1.x, a2.x, a3.x, b0.y, b1.y);
            mma8(c[f], a0.y, a1.y, a2.y, a3.y, b0.x, b1.x);
        }
    }
    const int co0 = cog*16 + g, co1 = co0 + 8;
    const float b0v = bg[co0], b1v = bg[co1];
    float* r0 = out + (size_t)(b*CO + co0)*HW + y0*Ww + x0;
    float* r1 = out + (size_t)(b*CO + co1)*HW + y0*Ww + x0;
    #pragma unroll
    for (int f = 0; f < 8; f++) {
        int pxl = pxb + f*8 + 2*tig;
        *(float2*)(r0 + pxl) = make_float2(c[f][0] + b0v, c[f][1] + b0v);
        *(float2*)(r1 + pxl) = make_float2(c[f][2] + b1v, c[f][3] + b1v);
    }
}

// ---------------------------------------------------------------------------
extern "C" void kernel_launch(void* const* d_in, const int* in_sizes, int n_in,
                              void* d_out, int out_size)
{
    const float* feat = (const float*)d_in[0];
    const float* mask = (const float*)d_in[1];
    const float* Wl[5]; const float* bl[5]; const float* gl[5]; const float* bel[5];
    for (int l = 0; l < 5; l++) {
        Wl[l]  = (const float*)d_in[2 + 4*l];
        bl[l]  = (const float*)d_in[3 + 4*l];
        gl[l]  = (const float*)d_in[4 + 4*l];
        bel[l] = (const float*)d_in[5 + 4*l];
    }
    const float* Wf = (const float*)d_in[22];
    const float* bf = (const float*)d_in[23];

    float *bufA, *bufB, *mA, *mB, *sums, *ss;
    float2* wsp;
    cudaGetSymbolAddress((void**)&bufA, g_bufA);
    cudaGetSymbolAddress((void**)&bufB, g_bufB);
    cudaGetSymbolAddress((void**)&mA,   g_maskA);
    cudaGetSymbolAddress((void**)&mB,   g_maskB);
    cudaGetSymbolAddress((void**)&sums, g_sums);
    cudaGetSymbolAddress((void**)&ss,   g_ss);
    cudaGetSymbolAddress((void**)&wsp,  g_wsplit);

    // pre-split weight table offsets (float2 units)
    const int sz0 = 4608, sz1 = 4608, sz2 = 18432, sz3 = 36864, sz4 = 73728;
    const int off0 = 0, off1 = off0+sz0, off2 = off1+sz1, off3 = off2+sz2, off4 = off3+sz3;
    presplit_kernel<<<(sz0+255)/256, 256>>>(Wl[0], wsp+off0, 32, 16, sz0);
    presplit_kernel<<<(sz1+255)/256, 256>>>(Wl[1], wsp+off1, 16, 32, sz1);
    presplit_kernel<<<(sz2+255)/256, 256>>>(Wl[2], wsp+off2, 32, 64, sz2);
    presplit_kernel<<<(sz3+255)/256, 256>>>(Wl[3], wsp+off3, 64, 64, sz3);
    presplit_kernel<<<(sz4+255)/256, 256>>>(Wl[4], wsp+off4, 64, 64, sz4);

    // smem: 24*WPX*8 + 3*WPX*4 + PXT*4 + 2*CO_BLK*4
    const int smem_L0 = 24*268*8 + 3*268*4 + 256*4 + 2*16*4;   // 55856
    const int smem_L1 = 24*268*8 + 3*268*4 + 256*4 + 2*32*4;   // 55984
    const int smem_Lx = 24*140*8 + 3*140*4 + 128*4 + 2*64*4;   // 29584

    auto k0 = conv_mma_kernel<32,16,1,1,256,4,false>;
    auto k1 = conv_mma_kernel<16,32,1,2,256,8,true>;
    auto k2 = conv_mma_kernel<32,64,1,1,128,8,true>;
    auto k3 = conv_mma_kernel<64,64,1,2,128,8,true>;
    auto k4 = conv_mma_kernel<64,64,2,1,128,8,true>;
    cudaFuncSetAttribute(k0, cudaFuncAttributeMaxDynamicSharedMemorySize, smem_L0);
    cudaFuncSetAttribute(k1, cudaFuncAttributeMaxDynamicSharedMemorySize, smem_L1);
    cudaFuncSetAttribute(k2, cudaFuncAttributeMaxDynamicSharedMemorySize, smem_Lx);
    cudaFuncSetAttribute(k3, cudaFuncAttributeMaxDynamicSharedMemorySize, smem_Lx);
    cudaFuncSetAttribute(k4, cudaFuncAttributeMaxDynamicSharedMemorySize, smem_Lx);

    // L0: 32 -> 16, d=1
    cudaMemsetAsync(sums, 0, 2*16*sizeof(float));
    k0<<<dim3(256,1,8), 128, smem_L0>>>(feat, mask, wsp+off0, bl[0], nullptr, bufA, mA, sums);
    stats_kernel<<<1,256>>>(sums, gl[0], bel[0], ss, 16);

    // L1: 16 -> 32, d=2
    cudaMemsetAsync(sums, 0, 2*32*sizeof(float));
    k1<<<dim3(256,1,8), 256, smem_L1>>>(bufA, mA, wsp+off1, bl[1], ss, bufB, mB, sums);
    stats_kernel<<<1,256>>>(sums, gl[1], bel[1], ss, 32);

    // L2: 32 -> 64, d=1
    cudaMemsetAsync(sums, 0, 2*64*sizeof(float));
    k2<<<dim3(512,1,8), 256, smem_Lx>>>(bufB, mB, wsp+off2, bl[2], ss, bufA, mA, sums);
    stats_kernel<<<1,256>>>(sums, gl[2], bel[2], ss, 64);

    // L3: 64 -> 64, d=2
    cudaMemsetAsync(sums, 0, 2*64*sizeof(float));
    k3<<<dim3(512,1,8), 256, smem_Lx>>>(bufA, mA, wsp+off3, bl[3], ss, bufB, mB, sums);
    stats_kernel<<<1,256>>>(sums, gl[3], bel[3], ss, 64);

    // L4: 64 -> 128, d=1 (2 co-splits)
    cudaMemsetAsync(sums, 0, 2*128*sizeof(float));
    k4<<<dim3(512,1,16), 256, smem_Lx>>>(bufB, mB, wsp+off4, bl[4], ss, bufA, mA, sums);
    stats_kernel<<<1,256>>>(sums, gl[4], bel[4], ss, 128);

    // final 1x1 conv (BN4 fused on load)
    conv1x1_mma_kernel<<<dim3(512,1,8), 256>>>(bufA, ss, Wf, bf, (float*)d_out);

    // final mask
    const int xelems = Bb*64*HW;
    const int melems = Bb*HW;
    if (out_size >= xelems + melems) {
        cudaMemcpyAsync((float*)d_out + xelems, mA, (size_t)melems*sizeof(float),
                        cudaMemcpyDeviceToDevice);
    }
}

// round 4
// speedup vs baseline: 1.8788x; 1.2769x over previous
#include <cuda_runtime.h>
#include <cstdint>

#define Hh 256
#define Ww 256
#define Bb 8
#define HW 65536
#define NPIX (Bb*HW)   // 524288

// Scratch (device globals — no allocation allowed)
__device__ float g_bufA[(size_t)Bb*128*HW];
__device__ float g_bufB[(size_t)Bb*128*HW];
__device__ float g_maskA[(size_t)Bb*HW];
__device__ float g_maskB[(size_t)Bb*HW];
__device__ float g_sums[256];
__device__ float g_ss[256];
__device__ uint2 g_wsplit[140000];   // pre-split bf16 weight pairs, all conv layers

// ---------------------------------------------------------------------------
// bf16 pair helpers: value v ~ hi + lo, packed (hi in low 16, lo in high 16)
// ---------------------------------------------------------------------------
__device__ __forceinline__ uint32_t pack_split_bf16(float v) {
    uint16_t hb, lb;
    asm("cvt.rn.bf16.f32 %0, %1;" : "=h"(hb) : "f"(v));
    float hf = __uint_as_float((uint32_t)hb << 16);
    asm("cvt.rn.bf16.f32 %0, %1;" : "=h"(lb) : "f"(v - hf));
    return (uint32_t)hb | ((uint32_t)lb << 16);
}
// D += A(16x8,k16) * B, bf16 operands, fp32 accum
__device__ __forceinline__ void mma16(float* c,
                                      uint32_t a0, uint32_t a1, uint32_t a2, uint32_t a3,
                                      uint32_t b0, uint32_t b1) {
    asm volatile(
        "mma.sync.aligned.m16n8k16.row.col.f32.bf16.bf16.f32 "
        "{%0,%1,%2,%3},{%4,%5,%6,%7},{%8,%9},{%0,%1,%2,%3};"
        : "+f"(c[0]), "+f"(c[1]), "+f"(c[2]), "+f"(c[3])
        : "r"(a0), "r"(a1), "r"(a2), "r"(a3), "r"(b0), "r"(b1));
}

// ---------------------------------------------------------------------------
// Weight pre-split: W[co_g][ci][3][3] -> uint2{ (h,h), (l,l) } at
//   [(s*chunks + q)*72 + t*8 + ci_local]*CO_BLK + co
// ---------------------------------------------------------------------------
__global__ void presplit_kernel(const float* __restrict__ W, uint2* __restrict__ dst,
                                int CIN, int CO_BLK, int total)
{
    int i = blockIdx.x*256 + threadIdx.x;
    if (i >= total) return;
    int co   = i % CO_BLK;
    int ci   = (i / CO_BLK) & 7;
    int t    = (i / (CO_BLK*8)) % 9;
    int rest = i / (CO_BLK*72);       // s*chunks + q
    int chunks = CIN >> 3;
    int q = rest % chunks;
    int s = rest / chunks;
    float v = W[(((s*CO_BLK + co)*CIN) + q*8 + ci)*9 + t];
    uint16_t hb, lb;
    asm("cvt.rn.bf16.f32 %0, %1;" : "=h"(hb) : "f"(v));
    float hf = __uint_as_float((uint32_t)hb << 16);
    asm("cvt.rn.bf16.f32 %0, %1;" : "=h"(lb) : "f"(v - hf));
    dst[i] = make_uint2((uint32_t)hb * 0x00010001u, (uint32_t)lb * 0x00010001u);
}

// ---------------------------------------------------------------------------
// Fused sparse-conv block, bf16-pair MMA implicit GEMM, A from pre-split gmem.
// ---------------------------------------------------------------------------
template<int CIN, int CO_BLK, int NSPLIT, int DIL, int PXT, int WARPS, bool FUSE_BN>
__global__ void __launch_bounds__(WARPS*32, 3) conv_mma_kernel(
    const float* __restrict__ xin, const float* __restrict__ min_,
    const uint2* __restrict__ wsplit, const float* __restrict__ bg,
    const float* __restrict__ ssv,
    float* __restrict__ yout, float* __restrict__ mout,
    float* __restrict__ sums)
{
    constexpr int NT    = WARPS*32;
    constexpr int PXG   = WARPS*16/CO_BLK;      // px groups
    constexpr int XW    = PXT + 2*DIL;
    constexpr int WPX   = PXT + 12;             // padded stride (uint32 units)
    constexpr int COUTT = CO_BLK*NSPLIT;
    constexpr int TX    = 256/PXT;
    constexpr int CHUNKS = CIN/8;

    extern __shared__ char dsm[];
    uint32_t* xt  = (uint32_t*)dsm;             // [24][WPX] bf16 pairs
    float*  msk = (float*)(xt + 24*WPX);        // [3][WPX]
    float*  invc= msk + 3*WPX;                  // [PXT]
    float*  red = invc + PXT;                   // [2*CO_BLK]

    const int tid  = threadIdx.x;
    const int lane = tid & 31, warp = tid >> 5;
    const int g    = lane >> 2, tig = lane & 3;
    const int cog  = warp / PXG, pxg = warp % PXG;
    const int pxb  = pxg * 64;
    const int cb   = cog * 16;

    const int tile = blockIdx.x;
    const int x0 = (tile % TX) * PXT;
    const int y0 = tile / TX;
    const int z  = blockIdx.z;
    const int b  = z / NSPLIT;
    const int split = z % NSPLIT;
    const int co_base = split * CO_BLK;

    // --- stage mask rows ---
    for (int i = tid; i < 3*XW; i += NT) {
        int col = i % XW, r = i / XW;
        int gy = y0 + (r-1)*DIL, gx = x0 - DIL + col;
        float v = 0.f;
        if (gy >= 0 && gy < Hh && gx >= 0 && gx < Ww) v = min_[b*HW + gy*Ww + gx];
        msk[r*WPX + col] = v;
    }
    for (int i = tid; i < 2*CO_BLK; i += NT) red[i] = 0.f;
    __syncthreads();

    // --- per-pixel 1/count + mask maxpool ---
    for (int px = tid; px < PXT; px += NT) {
        float cnt = 0.f, mn = 0.f;
        #pragma unroll
        for (int ky = 0; ky < 3; ky++)
            #pragma unroll
            for (int kx = 0; kx < 3; kx++) {
                float v = msk[ky*WPX + px + kx*DIL];
                cnt += v; mn = fmaxf(mn, v);
            }
        invc[px] = 1.f / fmaxf(cnt * (float)CIN, 1e-5f);
        if (split == 0) mout[b*HW + y0*Ww + x0 + px] = mn;
    }

    float c[8][4];
    #pragma unroll
    for (int f = 0; f < 8; f++) { c[f][0]=0.f; c[f][1]=0.f; c[f][2]=0.f; c[f][3]=0.f; }

    for (int q = 0; q < CHUNKS; q++) {
        __syncthreads();
        // --- stage masked (+BN) input chunk: warp-per-ci, lane-per-col ---
        for (int ci = warp; ci < 8; ci += WARPS) {
            float sc = 1.f, sh = 0.f;
            if (FUSE_BN) { sc = ssv[q*8 + ci]; sh = ssv[CIN + q*8 + ci]; }
            const float* srcbase = xin + (size_t)(b*CIN + q*8 + ci)*HW + (x0 - DIL);
            #pragma unroll
            for (int r = 0; r < 3; r++) {
                int gy = y0 + (r-1)*DIL;
                uint32_t* dstrow = &xt[(ci*3 + r)*WPX];
                if ((unsigned)gy < (unsigned)Hh) {
                    const float* src = srcbase + gy*Ww;
                    for (int col = lane; col < XW; col += 32) {
                        int gx = x0 - DIL + col;
                        float v = 0.f;
                        if ((unsigned)gx < (unsigned)Ww) {
                            v = src[col];
                            if (FUSE_BN) {
                                v = fmaf(v, sc, sh);
                                v = v >= 0.f ? v : 0.01f*v;
                            }
                            v *= msk[r*WPX + col];
                        }
                        dstrow[col] = pack_split_bf16(v);
                    }
                } else {
                    for (int col = lane; col < XW; col += 32)
                        dstrow[col] = 0u;
                }
            }
        }
        __syncthreads();

        const uint2* Ab = wsplit + (size_t)(split*CHUNKS + q)*72*CO_BLK + cb + g;
        #pragma unroll 3
        for (int t = 0; t < 9; t++) {
            const int ky = t/3, kx = t - 3*ky;
            const uint2* Ap = Ab + t*8*CO_BLK;
            uint2 A0 = __ldg(Ap + tig*CO_BLK);          // (h,h),(l,l) k=tig, co=cb+g
            uint2 A1 = __ldg(Ap + tig*CO_BLK + 8);      // co=cb+g+8
            uint2 A2 = __ldg(Ap + (tig+4)*CO_BLK);      // k=tig+4
            uint2 A3 = __ldg(Ap + (tig+4)*CO_BLK + 8);
            const uint32_t* brow0 = &xt[(tig    *3 + ky)*WPX + pxb + kx*DIL + g];
            const uint32_t* brow1 = &xt[((tig+4)*3 + ky)*WPX + pxb + kx*DIL + g];
            #pragma unroll
            for (int f = 0; f < 8; f++) {
                uint32_t b0 = brow0[f*8];
                uint32_t b1 = brow1[f*8];
                mma16(c[f], A0.x, A1.x, A2.x, A3.x, b0, b1);  // w_hi * x
                mma16(c[f], A0.y, A1.y, A2.y, A3.y, b0, b1);  // w_lo * x
            }
        }
    }

    // --- epilogue ---
    const int gco0 = co_base + cb + g;
    const int gco1 = gco0 + 8;
    const float b0v = bg[gco0], b1v = bg[gco1];
    float* rowp0 = yout + (size_t)(b*COUTT + gco0)*HW + y0*Ww + x0;
    float* rowp1 = yout + (size_t)(b*COUTT + gco1)*HW + y0*Ww + x0;
    float s0 = 0.f, q0 = 0.f, s1 = 0.f, q1 = 0.f;
    #pragma unroll
    for (int f = 0; f < 8; f++) {
        int pxl = pxb + f*8 + 2*tig;
        float i0 = invc[pxl], i1 = invc[pxl + 1];
        float y00 = fmaf(c[f][0], i0, b0v);
        float y01 = fmaf(c[f][1], i1, b0v);
        float y10 = fmaf(c[f][2], i0, b1v);
        float y11 = fmaf(c[f][3], i1, b1v);
        *(float2*)(rowp0 + pxl) = make_float2(y00, y01);
        *(float2*)(rowp1 + pxl) = make_float2(y10, y11);
        s0 += y00 + y01; q0 += y00*y00 + y01*y01;
        s1 += y10 + y11; q1 += y10*y10 + y11*y11;
    }
    #pragma unroll
    for (int o = 1; o <= 2; o <<= 1) {
        s0 += __shfl_xor_sync(0xffffffffu, s0, o);
        q0 += __shfl_xor_sync(0xffffffffu, q0, o);
        s1 += __shfl_xor_sync(0xffffffffu, s1, o);
        q1 += __shfl_xor_sync(0xffffffffu, q1, o);
    }
    if (tig == 0) {
        atomicAdd(&red[cb + g],              s0);
        atomicAdd(&red[CO_BLK + cb + g],     q0);
        atomicAdd(&red[cb + g + 8],          s1);
        atomicAdd(&red[CO_BLK + cb + g + 8], q1);
    }
    __syncthreads();
    if (tid < CO_BLK) {
        atomicAdd(&sums[co_base + tid],          red[tid]);
        atomicAdd(&sums[COUTT + co_base + tid],  red[CO_BLK + tid]);
    }
}

// per-channel scale/shift from sums
__global__ void stats_kernel(const float* __restrict__ sums,
                             const float* __restrict__ g,
                             const float* __restrict__ be,
                             float* __restrict__ ss, int C)
{
    int c = threadIdx.x;
    if (c < C) {
        const float invN = 1.f / (float)NPIX;
        float mean = sums[c] * invN;
        float var  = sums[C + c] * invN - mean*mean;
        float sc = g[c] * rsqrtf(var + 1e-5f);
        ss[c]     = sc;
        ss[C + c] = fmaf(-mean, sc, be[c]);
    }
}

// ---------------------------------------------------------------------------
// final 1x1 conv 128 -> 64, bf16-pair MMA; applies layer-4 BN+LeakyReLU on load
// ---------------------------------------------------------------------------
__global__ void __launch_bounds__(256, 3) conv1x1_mma_kernel(
    const float* __restrict__ xin, const float* __restrict__ ssv,
    const float* __restrict__ Wg,  const float* __restrict__ bg,
    float* __restrict__ out)
{
    constexpr int CIN = 128, CO = 64, PXT = 128, WPX1 = 132, COpad = 68;
    __shared__ uint32_t xt[8*WPX1];
    __shared__ uint2 wt[8*COpad];

    const int tid = threadIdx.x, lane = tid & 31, warp = tid >> 5;
    const int g = lane >> 2, tig = lane & 3;
    const int cog = warp >> 1, pxg = warp & 1;
    const int pxb = pxg * 64;
    const int tile = blockIdx.x;
    const int x0 = (tile & 1)*PXT, y0 = tile >> 1;
    const int b  = blockIdx.z;

    float c[8][4];
    #pragma unroll
    for (int f = 0; f < 8; f++) { c[f][0]=0.f; c[f][1]=0.f; c[f][2]=0.f; c[f][3]=0.f; }

    for (int ci0 = 0; ci0 < CIN; ci0 += 8) {
        __syncthreads();
        for (int i = tid; i < 8*CO; i += 256) {
            int co = i % CO, ci = i / CO;
            float v = Wg[co*CIN + ci0 + ci];
            uint16_t hb, lb;
            asm("cvt.rn.bf16.f32 %0, %1;" : "=h"(hb) : "f"(v));
            float hf = __uint_as_float((uint32_t)hb << 16);
            asm("cvt.rn.bf16.f32 %0, %1;" : "=h"(lb) : "f"(v - hf));
            wt[ci*COpad + co] = make_uint2((uint32_t)hb * 0x00010001u,
                                           (uint32_t)lb * 0x00010001u);
        }
        for (int i = tid; i < 8*PXT; i += 256) {
            int col = i & 127, ci = i >> 7;
            float raw = xin[(size_t)(b*CIN + ci0 + ci)*HW + y0*Ww + x0 + col];
            raw = fmaf(raw, ssv[ci0 + ci], ssv[CIN + ci0 + ci]);
            raw = raw >= 0.f ? raw : 0.01f*raw;
            xt[ci*WPX1 + col] = pack_split_bf16(raw);
        }
        __syncthreads();
        uint2 a0 = wt[tig    *COpad + cog*16 + g    ];
        uint2 a1 = wt[tig    *COpad + cog*16 + g + 8];
        uint2 a2 = wt[(tig+4)*COpad + cog*16 + g    ];
        uint2 a3 = wt[(tig+4)*COpad + cog*16 + g + 8];
        #pragma unroll
        for (int f = 0; f < 8; f++) {
            uint32_t b0 = xt[tig    *WPX1 + pxb + f*8 + g];
            uint32_t b1 = xt[(tig+4)*WPX1 + pxb + f*8 + g];
            mma16(c[f], a0.x, a1.x, a2.x, a3.x, b0, b1);
            mma16(c[f], a0.y, a1.y, a2.y, a3.y, b0, b1);
        }
    }
    const int co0 = cog*16 + g, co1 = co0 + 8;
    const float b0v = bg[co0], b1v = bg[co1];
    float* r0 = out + (size_t)(b*CO + co0)*HW + y0*Ww + x0;
    float* r1 = out + (size_t)(b*CO + co1)*HW + y0*Ww + x0;
    #pragma unroll
    for (int f = 0; f < 8; f++) {
        int pxl = pxb + f*8 + 2*tig;
        *(float2*)(r0 + pxl) = make_float2(c[f][0] + b0v, c[f][1] + b0v);
        *(float2*)(r1 + pxl) = make_float2(c[f][2] + b1v, c[f][3] + b1v);
    }
}

// ---------------------------------------------------------------------------
extern "C" void kernel_launch(void* const* d_in, const int* in_sizes, int n_in,
                              void* d_out, int out_size)
{
    const float* feat = (const float*)d_in[0];
    const float* mask = (const float*)d_in[1];
    const float* Wl[5]; const float* bl[5]; const float* gl[5]; const float* bel[5];
    for (int l = 0; l < 5; l++) {
        Wl[l]  = (const float*)d_in[2 + 4*l];
        bl[l]  = (const float*)d_in[3 + 4*l];
        gl[l]  = (const float*)d_in[4 + 4*l];
        bel[l] = (const float*)d_in[5 + 4*l];
    }
    const float* Wf = (const float*)d_in[22];
    const float* bf = (const float*)d_in[23];

    float *bufA, *bufB, *mA, *mB, *sums, *ss;
    uint2* wsp;
    cudaGetSymbolAddress((void**)&bufA, g_bufA);
    cudaGetSymbolAddress((void**)&bufB, g_bufB);
    cudaGetSymbolAddress((void**)&mA,   g_maskA);
    cudaGetSymbolAddress((void**)&mB,   g_maskB);
    cudaGetSymbolAddress((void**)&sums, g_sums);
    cudaGetSymbolAddress((void**)&ss,   g_ss);
    cudaGetSymbolAddress((void**)&wsp,  g_wsplit);

    // pre-split weight table offsets (uint2 units)
    const int sz0 = 4608, sz1 = 4608, sz2 = 18432, sz3 = 36864, sz4 = 73728;
    const int off0 = 0, off1 = off0+sz0, off2 = off1+sz1, off3 = off2+sz2, off4 = off3+sz3;
    presplit_kernel<<<(sz0+255)/256, 256>>>(Wl[0], wsp+off0, 32, 16, sz0);
    presplit_kernel<<<(sz1+255)/256, 256>>>(Wl[1], wsp+off1, 16, 32, sz1);
    presplit_kernel<<<(sz2+255)/256, 256>>>(Wl[2], wsp+off2, 32, 64, sz2);
    presplit_kernel<<<(sz3+255)/256, 256>>>(Wl[3], wsp+off3, 64, 64, sz3);
    presplit_kernel<<<(sz4+255)/256, 256>>>(Wl[4], wsp+off4, 64, 64, sz4);

    // smem: 24*WPX*4 + 3*WPX*4 + PXT*4 + 2*CO_BLK*4
    const int smem_L0 = 24*268*4 + 3*268*4 + 256*4 + 2*16*4;   // 30160
    const int smem_L1 = 24*268*4 + 3*268*4 + 256*4 + 2*32*4;   // 30288
    const int smem_Lx = 24*140*4 + 3*140*4 + 128*4 + 2*64*4;   // 16144

    auto k0 = conv_mma_kernel<32,16,1,1,256,4,false>;
    auto k1 = conv_mma_kernel<16,32,1,2,256,8,true>;
    auto k2 = conv_mma_kernel<32,64,1,1,128,8,true>;
    auto k3 = conv_mma_kernel<64,64,1,2,128,8,true>;
    auto k4 = conv_mma_kernel<64,64,2,1,128,8,true>;
    cudaFuncSetAttribute(k0, cudaFuncAttributeMaxDynamicSharedMemorySize, smem_L0);
    cudaFuncSetAttribute(k1, cudaFuncAttributeMaxDynamicSharedMemorySize, smem_L1);
    cudaFuncSetAttribute(k2, cudaFuncAttributeMaxDynamicSharedMemorySize, smem_Lx);
    cudaFuncSetAttribute(k3, cudaFuncAttributeMaxDynamicSharedMemorySize, smem_Lx);
    cudaFuncSetAttribute(k4, cudaFuncAttributeMaxDynamicSharedMemorySize, smem_Lx);

    // L0: 32 -> 16, d=1
    cudaMemsetAsync(sums, 0, 2*16*sizeof(float));
    k0<<<dim3(256,1,8), 128, smem_L0>>>(feat, mask, wsp+off0, bl[0], nullptr, bufA, mA, sums);
    stats_kernel<<<1,256>>>(sums, gl[0], bel[0], ss, 16);

    // L1: 16 -> 32, d=2
    cudaMemsetAsync(sums, 0, 2*32*sizeof(float));
    k1<<<dim3(256,1,8), 256, smem_L1>>>(bufA, mA, wsp+off1, bl[1], ss, bufB, mB, sums);
    stats_kernel<<<1,256>>>(sums, gl[1], bel[1], ss, 32);

    // L2: 32 -> 64, d=1
    cudaMemsetAsync(sums, 0, 2*64*sizeof(float));
    k2<<<dim3(512,1,8), 256, smem_Lx>>>(bufB, mB, wsp+off2, bl[2], ss, bufA, mA, sums);
    stats_kernel<<<1,256>>>(sums, gl[2], bel[2], ss, 64);

    // L3: 64 -> 64, d=2
    cudaMemsetAsync(sums, 0, 2*64*sizeof(float));
    k3<<<dim3(512,1,8), 256, smem_Lx>>>(bufA, mA, wsp+off3, bl[3], ss, bufB, mB, sums);
    stats_kernel<<<1,256>>>(sums, gl[3], bel[3], ss, 64);

    // L4: 64 -> 128, d=1 (2 co-splits)
    cudaMemsetAsync(sums, 0, 2*128*sizeof(float));
    k4<<<dim3(512,1,16), 256, smem_Lx>>>(bufB, mB, wsp+off4, bl[4], ss, bufA, mA, sums);
    stats_kernel<<<1,256>>>(sums, gl[4], bel[4], ss, 128);

    // final 1x1 conv (BN4 fused on load)
    conv1x1_mma_kernel<<<dim3(512,1,8), 256>>>(bufA, ss, Wf, bf, (float*)d_out);

    // final mask
    const int xelems = Bb*64*HW;
    const int melems = Bb*HW;
    if (out_size >= xelems + melems) {
        cudaMemcpyAsync((float*)d_out + xelems, mA, (size_t)melems*sizeof(float),
                        cudaMemcpyDeviceToDevice);
    }
}

// round 5
// speedup vs baseline: 2.3014x; 1.2249x over previous
#include <cuda_runtime.h>
#include <cstdint>

#define Hh 256
#define Ww 256
#define Bb 8
#define HW 65536
#define NPIX (Bb*HW)   // 524288

// Scratch (device globals — no allocation allowed)
__device__ float    g_bufA[(size_t)Bb*128*HW];
__device__ float    g_bufB[(size_t)Bb*128*HW];
__device__ uint32_t g_bufP[(size_t)Bb*128*HW];   // packed bf16-pair activations
__device__ float    g_maskA[(size_t)Bb*HW];
__device__ float    g_maskB[(size_t)Bb*HW];
__device__ float    g_sums[256];
__device__ float    g_ss[256];
__device__ uint2    g_wsplit[150000];   // pre-split bf16 weight pairs

// ---------------------------------------------------------------------------
// bf16 pair helpers: value v ~ hi + lo, packed (hi low 16 bits, lo high 16)
// ---------------------------------------------------------------------------
__device__ __forceinline__ uint32_t pack_split_bf16(float v) {
    uint16_t hb, lb;
    asm("cvt.rn.bf16.f32 %0, %1;" : "=h"(hb) : "f"(v));
    float hf = __uint_as_float((uint32_t)hb << 16);
    asm("cvt.rn.bf16.f32 %0, %1;" : "=h"(lb) : "f"(v - hf));
    return (uint32_t)hb | ((uint32_t)lb << 16);
}
__device__ __forceinline__ void mma16(float* c,
                                      uint32_t a0, uint32_t a1, uint32_t a2, uint32_t a3,
                                      uint32_t b0, uint32_t b1) {
    asm volatile(
        "mma.sync.aligned.m16n8k16.row.col.f32.bf16.bf16.f32 "
        "{%0,%1,%2,%3},{%4,%5,%6,%7},{%8,%9},{%0,%1,%2,%3};"
        : "+f"(c[0]), "+f"(c[1]), "+f"(c[2]), "+f"(c[3])
        : "r"(a0), "r"(a1), "r"(a2), "r"(a3), "r"(b0), "r"(b1));
}
__device__ __forceinline__ void cp_async4(uint32_t dst_smem, const void* src, int src_size) {
    asm volatile("cp.async.ca.shared.global [%0],[%1],4,%2;\n"
                 :: "r"(dst_smem), "l"(src), "r"(src_size));
}

// ---------------------------------------------------------------------------
// Weight pre-split (3x3 layers): W[co_g][ci][3][3] -> uint2{(h,h),(l,l)} at
//   [(s*chunks + q)*72 + t*8 + ci_local]*CO_BLK + co
// ---------------------------------------------------------------------------
__global__ void presplit_kernel(const float* __restrict__ W, uint2* __restrict__ dst,
                                int CIN, int CO_BLK, int total)
{
    int i = blockIdx.x*256 + threadIdx.x;
    if (i >= total) return;
    int co   = i % CO_BLK;
    int ci   = (i / CO_BLK) & 7;
    int t    = (i / (CO_BLK*8)) % 9;
    int rest = i / (CO_BLK*72);
    int chunks = CIN >> 3;
    int q = rest % chunks;
    int s = rest / chunks;
    float v = W[(((s*CO_BLK + co)*CIN) + q*8 + ci)*9 + t];
    uint16_t hb, lb;
    asm("cvt.rn.bf16.f32 %0, %1;" : "=h"(hb) : "f"(v));
    float hf = __uint_as_float((uint32_t)hb << 16);
    asm("cvt.rn.bf16.f32 %0, %1;" : "=h"(lb) : "f"(v - hf));
    dst[i] = make_uint2((uint32_t)hb * 0x00010001u, (uint32_t)lb * 0x00010001u);
}
// 1x1 weights: [q][ci][co], CIN=128, CO=64
__global__ void presplit1x1_kernel(const float* __restrict__ W, uint2* __restrict__ dst)
{
    int i = blockIdx.x*256 + threadIdx.x;
    if (i >= 8192) return;
    int co = i & 63, ci = (i >> 6) & 7, q = i >> 9;
    float v = W[co*128 + q*8 + ci];
    uint16_t hb, lb;
    asm("cvt.rn.bf16.f32 %0, %1;" : "=h"(hb) : "f"(v));
    float hf = __uint_as_float((uint32_t)hb << 16);
    asm("cvt.rn.bf16.f32 %0, %1;" : "=h"(lb) : "f"(v - hf));
    dst[i] = make_uint2((uint32_t)hb * 0x00010001u, (uint32_t)lb * 0x00010001u);
}

// ---------------------------------------------------------------------------
// Activation transform: y(fp32) [+BN+LeakyReLU] [*mask] -> packed bf16 pair.
// Memory bound; hoists all per-element scalar work out of the conv hot loop.
// ---------------------------------------------------------------------------
template<bool BN, bool MASKED>
__global__ void transform_kernel(const float* __restrict__ y,
                                 const float* __restrict__ m,
                                 const float* __restrict__ ss,
                                 uint32_t* __restrict__ out, int C, int n4)
{
    int i = blockIdx.x*256 + threadIdx.x;
    if (i >= n4) return;
    int plane = i >> 14;            // 16384 float4 per (b,c) plane
    int c = plane % C;
    int b = plane / C;
    float sc = 1.f, sh = 0.f;
    if (BN) { sc = ss[c]; sh = ss[C + c]; }
    float4 v = ((const float4*)y)[i];
    float4 mk = make_float4(1.f,1.f,1.f,1.f);
    if (MASKED) mk = ((const float4*)m)[b*16384 + (i & 16383)];
    float* vp = &v.x; const float* mp = &mk.x;
    uint32_t r[4];
    #pragma unroll
    for (int k = 0; k < 4; k++) {
        float x = vp[k];
        if (BN) { x = fmaf(x, sc, sh); x = x >= 0.f ? x : 0.01f*x; }
        if (MASKED) x *= mp[k];
        r[k] = pack_split_bf16(x);
    }
    ((uint4*)out)[i] = make_uint4(r[0], r[1], r[2], r[3]);
}

// ---------------------------------------------------------------------------
// Fused sparse-conv block, bf16-pair MMA, pre-packed input, cp.async staging.
// ---------------------------------------------------------------------------
template<int CIN, int CO_BLK, int NSPLIT, int DIL, int PXT, int WARPS>
__global__ void __launch_bounds__(WARPS*32, 3) conv_mma_kernel(
    const uint32_t* __restrict__ xpk, const float* __restrict__ min_,
    const uint2* __restrict__ wsplit, const float* __restrict__ bg,
    float* __restrict__ yout, float* __restrict__ mout,
    float* __restrict__ sums)
{
    constexpr int NT    = WARPS*32;
    constexpr int PXG   = WARPS*16/CO_BLK;
    constexpr int XW    = PXT + 2*DIL;
    constexpr int WPX   = PXT + 12;
    constexpr int COUTT = CO_BLK*NSPLIT;
    constexpr int TX    = 256/PXT;
    constexpr int CHUNKS = CIN/8;

    extern __shared__ char dsm[];
    uint32_t* xt  = (uint32_t*)dsm;             // [24][WPX] packed pairs
    float*  msk = (float*)(xt + 24*WPX);        // [3][WPX]
    float*  invc= msk + 3*WPX;                  // [PXT]
    float*  red = invc + PXT;                   // [2*CO_BLK]

    const int tid  = threadIdx.x;
    const int lane = tid & 31, warp = tid >> 5;
    const int g    = lane >> 2, tig = lane & 3;
    const int cog  = warp / PXG, pxg = warp % PXG;
    const int pxb  = pxg * 64;
    const int cb   = cog * 16;
    const uint32_t sx = (uint32_t)__cvta_generic_to_shared(xt);

    const int tile = blockIdx.x;
    const int x0 = (tile % TX) * PXT;
    const int y0 = tile / TX;
    const int z  = blockIdx.z;
    const int b  = z / NSPLIT;
    const int split = z % NSPLIT;
    const int co_base = split * CO_BLK;

    // --- stage mask rows ---
    for (int i = tid; i < 3*XW; i += NT) {
        int col = i % XW, r = i / XW;
        int gy = y0 + (r-1)*DIL, gx = x0 - DIL + col;
        float v = 0.f;
        if (gy >= 0 && gy < Hh && gx >= 0 && gx < Ww) v = min_[b*HW + gy*Ww + gx];
        msk[r*WPX + col] = v;
    }
    for (int i = tid; i < 2*CO_BLK; i += NT) red[i] = 0.f;
    __syncthreads();

    // --- per-pixel 1/count + mask maxpool ---
    for (int px = tid; px < PXT; px += NT) {
        float cnt = 0.f, mn = 0.f;
        #pragma unroll
        for (int ky = 0; ky < 3; ky++)
            #pragma unroll
            for (int kx = 0; kx < 3; kx++) {
                float v = msk[ky*WPX + px + kx*DIL];
                cnt += v; mn = fmaxf(mn, v);
            }
        invc[px] = 1.f / fmaxf(cnt * (float)CIN, 1e-5f);
        if (split == 0) mout[b*HW + y0*Ww + x0 + px] = mn;
    }

    float c[8][4];
    #pragma unroll
    for (int f = 0; f < 8; f++) { c[f][0]=0.f; c[f][1]=0.f; c[f][2]=0.f; c[f][3]=0.f; }

    for (int q = 0; q < CHUNKS; q++) {
        __syncthreads();
        // --- stage packed input chunk via cp.async (zero-fill OOB) ---
        for (int ci = warp; ci < 8; ci += WARPS) {
            const uint32_t* srcp = xpk + (size_t)(b*CIN + q*8 + ci)*HW;
            #pragma unroll
            for (int r = 0; r < 3; r++) {
                int gy = y0 + (r-1)*DIL;
                bool rowok = ((unsigned)gy < (unsigned)Hh);
                const uint32_t* srow = srcp + (rowok ? gy*Ww : 0);
                uint32_t dstb = sx + (((ci*3 + r)*WPX) << 2);
                for (int col = lane; col < XW; col += 32) {
                    int gx = x0 - DIL + col;
                    bool ok = rowok && ((unsigned)gx < (unsigned)Ww);
                    cp_async4(dstb + (col << 2), srow + (ok ? gx : 0), ok ? 4 : 0);
                }
            }
        }
        asm volatile("cp.async.commit_group;\n");
        asm volatile("cp.async.wait_group 0;\n");
        __syncthreads();

        const uint2* Ab = wsplit + (size_t)(split*CHUNKS + q)*72*CO_BLK + cb + g;
        #pragma unroll 3
        for (int t = 0; t < 9; t++) {
            const int ky = t/3, kx = t - 3*ky;
            const uint2* Ap = Ab + t*8*CO_BLK;
            uint2 A0 = __ldg(Ap + tig*CO_BLK);
            uint2 A1 = __ldg(Ap + tig*CO_BLK + 8);
            uint2 A2 = __ldg(Ap + (tig+4)*CO_BLK);
            uint2 A3 = __ldg(Ap + (tig+4)*CO_BLK + 8);
            const uint32_t* brow0 = &xt[(tig    *3 + ky)*WPX + pxb + kx*DIL + g];
            const uint32_t* brow1 = &xt[((tig+4)*3 + ky)*WPX + pxb + kx*DIL + g];
            #pragma unroll
            for (int f = 0; f < 8; f++) {
                uint32_t b0 = brow0[f*8];
                uint32_t b1 = brow1[f*8];
                mma16(c[f], A0.x, A1.x, A2.x, A3.x, b0, b1);  // w_hi * x
                mma16(c[f], A0.y, A1.y, A2.y, A3.y, b0, b1);  // w_lo * x
            }
        }
    }

    // --- epilogue ---
    const int gco0 = co_base + cb + g;
    const int gco1 = gco0 + 8;
    const float b0v = bg[gco0], b1v = bg[gco1];
    float* rowp0 = yout + (size_t)(b*COUTT + gco0)*HW + y0*Ww + x0;
    float* rowp1 = yout + (size_t)(b*COUTT + gco1)*HW + y0*Ww + x0;
    float s0 = 0.f, q0 = 0.f, s1 = 0.f, q1 = 0.f;
    #pragma unroll
    for (int f = 0; f < 8; f++) {
        int pxl = pxb + f*8 + 2*tig;
        float i0 = invc[pxl], i1 = invc[pxl + 1];
        float y00 = fmaf(c[f][0], i0, b0v);
        float y01 = fmaf(c[f][1], i1, b0v);
        float y10 = fmaf(c[f][2], i0, b1v);
        float y11 = fmaf(c[f][3], i1, b1v);
        *(float2*)(rowp0 + pxl) = make_float2(y00, y01);
        *(float2*)(rowp1 + pxl) = make_float2(y10, y11);
        s0 += y00 + y01; q0 += y00*y00 + y01*y01;
        s1 += y10 + y11; q1 += y10*y10 + y11*y11;
    }
    #pragma unroll
    for (int o = 1; o <= 2; o <<= 1) {
        s0 += __shfl_xor_sync(0xffffffffu, s0, o);
        q0 += __shfl_xor_sync(0xffffffffu, q0, o);
        s1 += __shfl_xor_sync(0xffffffffu, s1, o);
        q1 += __shfl_xor_sync(0xffffffffu, q1, o);
    }
    if (tig == 0) {
        atomicAdd(&red[cb + g],              s0);
        atomicAdd(&red[CO_BLK + cb + g],     q0);
        atomicAdd(&red[cb + g + 8],          s1);
        atomicAdd(&red[CO_BLK + cb + g + 8], q1);
    }
    __syncthreads();
    if (tid < CO_BLK) {
        atomicAdd(&sums[co_base + tid],          red[tid]);
        atomicAdd(&sums[COUTT + co_base + tid],  red[CO_BLK + tid]);
    }
}

// per-channel scale/shift from sums
__global__ void stats_kernel(const float* __restrict__ sums,
                             const float* __restrict__ g,
                             const float* __restrict__ be,
                             float* __restrict__ ss, int C)
{
    int c = threadIdx.x;
    if (c < C) {
        const float invN = 1.f / (float)NPIX;
        float mean = sums[c] * invN;
        float var  = sums[C + c] * invN - mean*mean;
        float sc = g[c] * rsqrtf(var + 1e-5f);
        ss[c]     = sc;
        ss[C + c] = fmaf(-mean, sc, be[c]);
    }
}

// ---------------------------------------------------------------------------
// final 1x1 conv 128 -> 64, bf16-pair MMA on pre-packed input
// ---------------------------------------------------------------------------
__global__ void __launch_bounds__(256, 3) conv1x1_mma_kernel(
    const uint32_t* __restrict__ xpk, const uint2* __restrict__ wsp1,
    const float* __restrict__ bg, float* __restrict__ out)
{
    constexpr int CIN = 128, CO = 64, PXT = 128, WPX1 = 140;
    __shared__ uint32_t xt[8*WPX1];

    const int tid = threadIdx.x, lane = tid & 31, warp = tid >> 5;
    const int g = lane >> 2, tig = lane & 3;
    const int cog = warp >> 1, pxg = warp & 1;
    const int pxb = pxg * 64;
    const int tile = blockIdx.x;
    const int x0 = (tile & 1)*PXT, y0 = tile >> 1;
    const int b  = blockIdx.z;
    const uint32_t sx = (uint32_t)__cvta_generic_to_shared(xt);

    float c[8][4];
    #pragma unroll
    for (int f = 0; f < 8; f++) { c[f][0]=0.f; c[f][1]=0.f; c[f][2]=0.f; c[f][3]=0.f; }

    for (int q = 0; q < 16; q++) {
        __syncthreads();
        {
            const int ci = warp;
            const uint32_t* s = xpk + (size_t)(b*CIN + q*8 + ci)*HW + y0*Ww + x0;
            uint32_t dstb = sx + ((ci*WPX1) << 2);
            #pragma unroll
            for (int k = 0; k < 4; k++) {
                int col = lane + k*32;
                cp_async4(dstb + (col << 2), s + col, 4);
            }
        }
        asm volatile("cp.async.commit_group;\n");
        asm volatile("cp.async.wait_group 0;\n");
        __syncthreads();

        const uint2* Ap = wsp1 + q*512;
        uint2 a0 = __ldg(Ap + tig*64 + cog*16 + g);
        uint2 a1 = __ldg(Ap + tig*64 + cog*16 + g + 8);
        uint2 a2 = __ldg(Ap + (tig+4)*64 + cog*16 + g);
        uint2 a3 = __ldg(Ap + (tig+4)*64 + cog*16 + g + 8);
        #pragma unroll
        for (int f = 0; f < 8; f++) {
            uint32_t b0 = xt[tig    *WPX1 + pxb + f*8 + g];
            uint32_t b1 = xt[(tig+4)*WPX1 + pxb + f*8 + g];
            mma16(c[f], a0.x, a1.x, a2.x, a3.x, b0, b1);
            mma16(c[f], a0.y, a1.y, a2.y, a3.y, b0, b1);
        }
    }
    const int co0 = cog*16 + g, co1 = co0 + 8;
    const float b0v = bg[co0], b1v = bg[co1];
    float* r0 = out + (size_t)(b*CO + co0)*HW + y0*Ww + x0;
    float* r1 = out + (size_t)(b*CO + co1)*HW + y0*Ww + x0;
    #pragma unroll
    for (int f = 0; f < 8; f++) {
        int pxl = pxb + f*8 + 2*tig;
        *(float2*)(r0 + pxl) = make_float2(c[f][0] + b0v, c[f][1] + b0v);
        *(float2*)(r1 + pxl) = make_float2(c[f][2] + b1v, c[f][3] + b1v);
    }
}

// ---------------------------------------------------------------------------
extern "C" void kernel_launch(void* const* d_in, const int* in_sizes, int n_in,
                              void* d_out, int out_size)
{
    const float* feat = (const float*)d_in[0];
    const float* mask = (const float*)d_in[1];
    const float* Wl[5]; const float* bl[5]; const float* gl[5]; const float* bel[5];
    for (int l = 0; l < 5; l++) {
        Wl[l]  = (const float*)d_in[2 + 4*l];
        bl[l]  = (const float*)d_in[3 + 4*l];
        gl[l]  = (const float*)d_in[4 + 4*l];
        bel[l] = (const float*)d_in[5 + 4*l];
    }
    const float* Wf = (const float*)d_in[22];
    const float* bf = (const float*)d_in[23];

    float *bufA, *bufB, *mA, *mB, *sums, *ss;
    uint32_t* P;
    uint2* wsp;
    cudaGetSymbolAddress((void**)&bufA, g_bufA);
    cudaGetSymbolAddress((void**)&bufB, g_bufB);
    cudaGetSymbolAddress((void**)&P,    g_bufP);
    cudaGetSymbolAddress((void**)&mA,   g_maskA);
    cudaGetSymbolAddress((void**)&mB,   g_maskB);
    cudaGetSymbolAddress((void**)&sums, g_sums);
    cudaGetSymbolAddress((void**)&ss,   g_ss);
    cudaGetSymbolAddress((void**)&wsp,  g_wsplit);

    // pre-split weight tables (uint2 units)
    const int sz0 = 4608, sz1 = 4608, sz2 = 18432, sz3 = 36864, sz4 = 73728;
    const int off0 = 0, off1 = off0+sz0, off2 = off1+sz1, off3 = off2+sz2, off4 = off3+sz3;
    const int off1x1 = off4 + sz4;   // 138240, +8192 = 146432 <= 150000
    presplit_kernel<<<(sz0+255)/256, 256>>>(Wl[0], wsp+off0, 32, 16, sz0);
    presplit_kernel<<<(sz1+255)/256, 256>>>(Wl[1], wsp+off1, 16, 32, sz1);
    presplit_kernel<<<(sz2+255)/256, 256>>>(Wl[2], wsp+off2, 32, 64, sz2);
    presplit_kernel<<<(sz3+255)/256, 256>>>(Wl[3], wsp+off3, 64, 64, sz3);
    presplit_kernel<<<(sz4+255)/256, 256>>>(Wl[4], wsp+off4, 64, 64, sz4);
    presplit1x1_kernel<<<32, 256>>>(Wf, wsp+off1x1);

    // smem: 24*WPX*4 + 3*WPX*4 + PXT*4 + 2*CO_BLK*4 (+pad)
    const int smem_L0 = 24*268*4 + 3*268*4 + 256*4 + 2*16*4 + 16;
    const int smem_L1 = 24*268*4 + 3*268*4 + 256*4 + 2*32*4 + 16;
    const int smem_Lx = 24*140*4 + 3*140*4 + 128*4 + 2*64*4 + 16;

    auto k0 = conv_mma_kernel<32,16,1,1,256,4>;
    auto k1 = conv_mma_kernel<16,32,1,2,256,8>;
    auto k2 = conv_mma_kernel<32,64,1,1,128,8>;
    auto k3 = conv_mma_kernel<64,64,1,2,128,8>;
    auto k4 = conv_mma_kernel<64,64,2,1,128,8>;
    cudaFuncSetAttribute(k0, cudaFuncAttributeMaxDynamicSharedMemorySize, smem_L0);
    cudaFuncSetAttribute(k1, cudaFuncAttributeMaxDynamicSharedMemorySize, smem_L1);
    cudaFuncSetAttribute(k2, cudaFuncAttributeMaxDynamicSharedMemorySize, smem_Lx);
    cudaFuncSetAttribute(k3, cudaFuncAttributeMaxDynamicSharedMemorySize, smem_Lx);
    cudaFuncSetAttribute(k4, cudaFuncAttributeMaxDynamicSharedMemorySize, smem_Lx);

    auto TFM  = transform_kernel<true,  true >;
    auto TF0  = transform_kernel<false, true >;
    auto TFNM = transform_kernel<true,  false>;
    #define TGRID(C) (((C)*131072 + 255)/256)

    // input transform: feat * mask -> packed
    TF0<<<TGRID(32), 256>>>(feat, mask, nullptr, P, 32, 32*131072);

    // L0: 32 -> 16, d=1
    cudaMemsetAsync(sums, 0, 2*16*sizeof(float));
    k0<<<dim3(256,1,8), 128, smem_L0>>>(P, mask, wsp+off0, bl[0], bufA, mA, sums);
    stats_kernel<<<1,256>>>(sums, gl[0], bel[0], ss, 16);
    TFM<<<TGRID(16), 256>>>(bufA, mA, ss, P, 16, 16*131072);

    // L1: 16 -> 32, d=2
    cudaMemsetAsync(sums, 0, 2*32*sizeof(float));
    k1<<<dim3(256,1,8), 256, smem_L1>>>(P, mA, wsp+off1, bl[1], bufB, mB, sums);
    stats_kernel<<<1,256>>>(sums, gl[1], bel[1], ss, 32);
    TFM<<<TGRID(32), 256>>>(bufB, mB, ss, P, 32, 32*131072);

    // L2: 32 -> 64, d=1
    cudaMemsetAsync(sums, 0, 2*64*sizeof(float));
    k2<<<dim3(512,1,8), 256, smem_Lx>>>(P, mB, wsp+off2, bl[2], bufA, mA, sums);
    stats_kernel<<<1,256>>>(sums, gl[2], bel[2], ss, 64);
    TFM<<<TGRID(64), 256>>>(bufA, mA, ss, P, 64, 64*131072);

    // L3: 64 -> 64, d=2
    cudaMemsetAsync(sums, 0, 2*64*sizeof(float));
    k3<<<dim3(512,1,8), 256, smem_Lx>>>(P, mA, wsp+off3, bl[3], bufB, mB, sums);
    stats_kernel<<<1,256>>>(sums, gl[3], bel[3], ss, 64);
    TFM<<<TGRID(64), 256>>>(bufB, mB, ss, P, 64, 64*131072);

    // L4: 64 -> 128, d=1 (2 co-splits)
    cudaMemsetAsync(sums, 0, 2*128*sizeof(float));
    k4<<<dim3(512,1,16), 256, smem_Lx>>>(P, mB, wsp+off4, bl[4], bufA, mA, sums);
    stats_kernel<<<1,256>>>(sums, gl[4], bel[4], ss, 128);
    TFNM<<<TGRID(128), 256>>>(bufA, nullptr, ss, P, 128, 128*131072);

    // final 1x1 conv
    conv1x1_mma_kernel<<<dim3(512,1,8), 256>>>(P, wsp+off1x1, bf, (float*)d_out);

    // final mask
    const int xelems = Bb*64*HW;
    const int melems = Bb*HW;
    if (out_size >= xelems + melems) {
        cudaMemcpyAsync((float*)d_out + xelems, mA, (size_t)melems*sizeof(float),
                        cudaMemcpyDeviceToDevice);
    }
}

// round 6
// speedup vs baseline: 2.3019x; 1.0002x over previous
#include <cuda_runtime.h>
#include <cstdint>

#define Hh 256
#define Ww 256
#define Bb 8
#define HW 65536
#define NPIX (Bb*HW)   // 524288

// Scratch (device globals — no allocation allowed)
__device__ float    g_bufA[(size_t)Bb*128*HW];
__device__ float    g_bufB[(size_t)Bb*128*HW];
__device__ uint32_t g_bufP[(size_t)Bb*128*HW];   // packed bf16-pair activations
__device__ float    g_maskA[(size_t)Bb*HW];
__device__ float    g_maskB[(size_t)Bb*HW];
__device__ float    g_sums[256];
__device__ float    g_ss[256];
__device__ uint2    g_wsplit[150000];   // pre-split bf16 weight pairs

// ---------------------------------------------------------------------------
// bf16 pair helpers: value v ~ hi + lo, packed (hi low 16 bits, lo high 16)
// ---------------------------------------------------------------------------
__device__ __forceinline__ uint32_t pack_split_bf16(float v) {
    uint16_t hb, lb;
    asm("cvt.rn.bf16.f32 %0, %1;" : "=h"(hb) : "f"(v));
    float hf = __uint_as_float((uint32_t)hb << 16);
    asm("cvt.rn.bf16.f32 %0, %1;" : "=h"(lb) : "f"(v - hf));
    return (uint32_t)hb | ((uint32_t)lb << 16);
}
__device__ __forceinline__ void mma16(float* c,
                                      uint32_t a0, uint32_t a1, uint32_t a2, uint32_t a3,
                                      uint32_t b0, uint32_t b1) {
    asm volatile(
        "mma.sync.aligned.m16n8k16.row.col.f32.bf16.bf16.f32 "
        "{%0,%1,%2,%3},{%4,%5,%6,%7},{%8,%9},{%0,%1,%2,%3};"
        : "+f"(c[0]), "+f"(c[1]), "+f"(c[2]), "+f"(c[3])
        : "r"(a0), "r"(a1), "r"(a2), "r"(a3), "r"(b0), "r"(b1));
}
__device__ __forceinline__ void cp_async4(uint32_t dst_smem, const void* src, int src_size) {
    asm volatile("cp.async.ca.shared.global [%0],[%1],4,%2;\n"
                 :: "r"(dst_smem), "l"(src), "r"(src_size));
}

// ---------------------------------------------------------------------------
// Weight pre-split (3x3 layers): W[co_g][ci][3][3] -> uint2{(h,h),(l,l)} at
//   [(s*chunks + q)*72 + t*8 + ci_local]*CO_BLK + co
// ---------------------------------------------------------------------------
__global__ void presplit_kernel(const float* __restrict__ W, uint2* __restrict__ dst,
                                int CIN, int CO_BLK, int total)
{
    int i = blockIdx.x*256 + threadIdx.x;
    if (i >= total) return;
    int co   = i % CO_BLK;
    int ci   = (i / CO_BLK) & 7;
    int t    = (i / (CO_BLK*8)) % 9;
    int rest = i / (CO_BLK*72);
    int chunks = CIN >> 3;
    int q = rest % chunks;
    int s = rest / chunks;
    float v = W[(((s*CO_BLK + co)*CIN) + q*8 + ci)*9 + t];
    uint16_t hb, lb;
    asm("cvt.rn.bf16.f32 %0, %1;" : "=h"(hb) : "f"(v));
    float hf = __uint_as_float((uint32_t)hb << 16);
    asm("cvt.rn.bf16.f32 %0, %1;" : "=h"(lb) : "f"(v - hf));
    dst[i] = make_uint2((uint32_t)hb * 0x00010001u, (uint32_t)lb * 0x00010001u);
}
// 1x1 weights: [q][ci][co], CIN=128, CO=64
__global__ void presplit1x1_kernel(const float* __restrict__ W, uint2* __restrict__ dst)
{
    int i = blockIdx.x*256 + threadIdx.x;
    if (i >= 8192) return;
    int co = i & 63, ci = (i >> 6) & 7, q = i >> 9;
    float v = W[co*128 + q*8 + ci];
    uint16_t hb, lb;
    asm("cvt.rn.bf16.f32 %0, %1;" : "=h"(hb) : "f"(v));
    float hf = __uint_as_float((uint32_t)hb << 16);
    asm("cvt.rn.bf16.f32 %0, %1;" : "=h"(lb) : "f"(v - hf));
    dst[i] = make_uint2((uint32_t)hb * 0x00010001u, (uint32_t)lb * 0x00010001u);
}

// ---------------------------------------------------------------------------
// Activation transform: y(fp32) [+BN+LeakyReLU] [*mask] -> packed bf16 pair.
// Memory bound; hoists all per-element scalar work out of the conv hot loop.
// ---------------------------------------------------------------------------
template<bool BN, bool MASKED>
__global__ void transform_kernel(const float* __restrict__ y,
                                 const float* __restrict__ m,
                                 const float* __restrict__ ss,
                                 uint32_t* __restrict__ out, int C, int n4)
{
    int i = blockIdx.x*256 + threadIdx.x;
    if (i >= n4) return;
    int plane = i >> 14;            // 16384 float4 per (b,c) plane
    int c = plane % C;
    int b = plane / C;
    float sc = 1.f, sh = 0.f;
    if (BN) { sc = ss[c]; sh = ss[C + c]; }
    float4 v = ((const float4*)y)[i];
    float4 mk = make_float4(1.f,1.f,1.f,1.f);
    if (MASKED) mk = ((const float4*)m)[b*16384 + (i & 16383)];
    float* vp = &v.x; const float* mp = &mk.x;
    uint32_t r[4];
    #pragma unroll
    for (int k = 0; k < 4; k++) {
        float x = vp[k];
        if (BN) { x = fmaf(x, sc, sh); x = x >= 0.f ? x : 0.01f*x; }
        if (MASKED) x *= mp[k];
        r[k] = pack_split_bf16(x);
    }
    ((uint4*)out)[i] = make_uint4(r[0], r[1], r[2], r[3]);
}

// ---------------------------------------------------------------------------
// Fused sparse-conv block, bf16-pair MMA, pre-packed input, cp.async staging.
// ---------------------------------------------------------------------------
template<int CIN, int CO_BLK, int NSPLIT, int DIL, int PXT, int WARPS>
__global__ void __launch_bounds__(WARPS*32, 3) conv_mma_kernel(
    const uint32_t* __restrict__ xpk, const float* __restrict__ min_,
    const uint2* __restrict__ wsplit, const float* __restrict__ bg,
    float* __restrict__ yout, float* __restrict__ mout,
    float* __restrict__ sums)
{
    constexpr int NT    = WARPS*32;
    constexpr int PXG   = WARPS*16/CO_BLK;
    constexpr int XW    = PXT + 2*DIL;
    constexpr int WPX   = PXT + 12;
    constexpr int COUTT = CO_BLK*NSPLIT;
    constexpr int TX    = 256/PXT;
    constexpr int CHUNKS = CIN/8;

    extern __shared__ char dsm[];
    uint32_t* xt  = (uint32_t*)dsm;             // [24][WPX] packed pairs
    float*  msk = (float*)(xt + 24*WPX);        // [3][WPX]
    float*  invc= msk + 3*WPX;                  // [PXT]
    float*  red = invc + PXT;                   // [2*CO_BLK]

    const int tid  = threadIdx.x;
    const int lane = tid & 31, warp = tid >> 5;
    const int g    = lane >> 2, tig = lane & 3;
    const int cog  = warp / PXG, pxg = warp % PXG;
    const int pxb  = pxg * 64;
    const int cb   = cog * 16;
    const uint32_t sx = (uint32_t)__cvta_generic_to_shared(xt);

    const int tile = blockIdx.x;
    const int x0 = (tile % TX) * PXT;
    const int y0 = tile / TX;
    const int z  = blockIdx.z;
    const int b  = z / NSPLIT;
    const int split = z % NSPLIT;
    const int co_base = split * CO_BLK;

    // --- stage mask rows ---
    for (int i = tid; i < 3*XW; i += NT) {
        int col = i % XW, r = i / XW;
        int gy = y0 + (r-1)*DIL, gx = x0 - DIL + col;
        float v = 0.f;
        if (gy >= 0 && gy < Hh && gx >= 0 && gx < Ww) v = min_[b*HW + gy*Ww + gx];
        msk[r*WPX + col] = v;
    }
    for (int i = tid; i < 2*CO_BLK; i += NT) red[i] = 0.f;
    __syncthreads();

    // --- per-pixel 1/count + mask maxpool ---
    for (int px = tid; px < PXT; px += NT) {
        float cnt = 0.f, mn = 0.f;
        #pragma unroll
        for (int ky = 0; ky < 3; ky++)
            #pragma unroll
            for (int kx = 0; kx < 3; kx++) {
                float v = msk[ky*WPX + px + kx*DIL];
                cnt += v; mn = fmaxf(mn, v);
            }
        invc[px] = 1.f / fmaxf(cnt * (float)CIN, 1e-5f);
        if (split == 0) mout[b*HW + y0*Ww + x0 + px] = mn;
    }

    float c[8][4];
    #pragma unroll
    for (int f = 0; f < 8; f++) { c[f][0]=0.f; c[f][1]=0.f; c[f][2]=0.f; c[f][3]=0.f; }

    for (int q = 0; q < CHUNKS; q++) {
        __syncthreads();
        // --- stage packed input chunk via cp.async (zero-fill OOB) ---
        for (int ci = warp; ci < 8; ci += WARPS) {
            const uint32_t* srcp = xpk + (size_t)(b*CIN + q*8 + ci)*HW;
            #pragma unroll
            for (int r = 0; r < 3; r++) {
                int gy = y0 + (r-1)*DIL;
                bool rowok = ((unsigned)gy < (unsigned)Hh);
                const uint32_t* srow = srcp + (rowok ? gy*Ww : 0);
                uint32_t dstb = sx + (((ci*3 + r)*WPX) << 2);
                for (int col = lane; col < XW; col += 32) {
                    int gx = x0 - DIL + col;
                    bool ok = rowok && ((unsigned)gx < (unsigned)Ww);
                    cp_async4(dstb + (col << 2), srow + (ok ? gx : 0), ok ? 4 : 0);
                }
            }
        }
        asm volatile("cp.async.commit_group;\n");
        asm volatile("cp.async.wait_group 0;\n");
        __syncthreads();

        const uint2* Ab = wsplit + (size_t)(split*CHUNKS + q)*72*CO_BLK + cb + g;
        #pragma unroll 3
        for (int t = 0; t < 9; t++) {
            const int ky = t/3, kx = t - 3*ky;
            const uint2* Ap = Ab + t*8*CO_BLK;
            uint2 A0 = __ldg(Ap + tig*CO_BLK);
            uint2 A1 = __ldg(Ap + tig*CO_BLK + 8);
            uint2 A2 = __ldg(Ap + (tig+4)*CO_BLK);
            uint2 A3 = __ldg(Ap + (tig+4)*CO_BLK + 8);
            const uint32_t* brow0 = &xt[(tig    *3 + ky)*WPX + pxb + kx*DIL + g];
            const uint32_t* brow1 = &xt[((tig+4)*3 + ky)*WPX + pxb + kx*DIL + g];
            #pragma unroll
            for (int f = 0; f < 8; f++) {
                uint32_t b0 = brow0[f*8];
                uint32_t b1 = brow1[f*8];
                mma16(c[f], A0.x, A1.x, A2.x, A3.x, b0, b1);  // w_hi * x
                mma16(c[f], A0.y, A1.y, A2.y, A3.y, b0, b1);  // w_lo * x
            }
        }
    }

    // --- epilogue ---
    const int gco0 = co_base + cb + g;
    const int gco1 = gco0 + 8;
    const float b0v = bg[gco0], b1v = bg[gco1];
    float* rowp0 = yout + (size_t)(b*COUTT + gco0)*HW + y0*Ww + x0;
    float* rowp1 = yout + (size_t)(b*COUTT + gco1)*HW + y0*Ww + x0;
    float s0 = 0.f, q0 = 0.f, s1 = 0.f, q1 = 0.f;
    #pragma unroll
    for (int f = 0; f < 8; f++) {
        int pxl = pxb + f*8 + 2*tig;
        float i0 = invc[pxl], i1 = invc[pxl + 1];
        float y00 = fmaf(c[f][0], i0, b0v);
        float y01 = fmaf(c[f][1], i1, b0v);
        float y10 = fmaf(c[f][2], i0, b1v);
        float y11 = fmaf(c[f][3], i1, b1v);
        *(float2*)(rowp0 + pxl) = make_float2(y00, y01);
        *(float2*)(rowp1 + pxl) = make_float2(y10, y11);
        s0 += y00 + y01; q0 += y00*y00 + y01*y01;
        s1 += y10 + y11; q1 += y10*y10 + y11*y11;
    }
    #pragma unroll
    for (int o = 1; o <= 2; o <<= 1) {
        s0 += __shfl_xor_sync(0xffffffffu, s0, o);
        q0 += __shfl_xor_sync(0xffffffffu, q0, o);
        s1 += __shfl_xor_sync(0xffffffffu, s1, o);
        q1 += __shfl_xor_sync(0xffffffffu, q1, o);
    }
    if (tig == 0) {
        atomicAdd(&red[cb + g],              s0);
        atomicAdd(&red[CO_BLK + cb + g],     q0);
        atomicAdd(&red[cb + g + 8],          s1);
        atomicAdd(&red[CO_BLK + cb + g + 8], q1);
    }
    __syncthreads();
    if (tid < CO_BLK) {
        atomicAdd(&sums[co_base + tid],          red[tid]);
        atomicAdd(&sums[COUTT + co_base + tid],  red[CO_BLK + tid]);
    }
}

// per-channel scale/shift from sums
__global__ void stats_kernel(const float* __restrict__ sums,
                             const float* __restrict__ g,
                             const float* __restrict__ be,
                             float* __restrict__ ss, int C)
{
    int c = threadIdx.x;
    if (c < C) {
        const float invN = 1.f / (float)NPIX;
        float mean = sums[c] * invN;
        float var  = sums[C + c] * invN - mean*mean;
        float sc = g[c] * rsqrtf(var + 1e-5f);
        ss[c]     = sc;
        ss[C + c] = fmaf(-mean, sc, be[c]);
    }
}

// ---------------------------------------------------------------------------
// final 1x1 conv 128 -> 64, bf16-pair MMA on pre-packed input
// ---------------------------------------------------------------------------
__global__ void __launch_bounds__(256, 3) conv1x1_mma_kernel(
    const uint32_t* __restrict__ xpk, const uint2* __restrict__ wsp1,
    const float* __restrict__ bg, float* __restrict__ out)
{
    constexpr int CIN = 128, CO = 64, PXT = 128, WPX1 = 140;
    __shared__ uint32_t xt[8*WPX1];

    const int tid = threadIdx.x, lane = tid & 31, warp = tid >> 5;
    const int g = lane >> 2, tig = lane & 3;
    const int cog = warp >> 1, pxg = warp & 1;
    const int pxb = pxg * 64;
    const int tile = blockIdx.x;
    const int x0 = (tile & 1)*PXT, y0 = tile >> 1;
    const int b  = blockIdx.z;
    const uint32_t sx = (uint32_t)__cvta_generic_to_shared(xt);

    float c[8][4];
    #pragma unroll
    for (int f = 0; f < 8; f++) { c[f][0]=0.f; c[f][1]=0.f; c[f][2]=0.f; c[f][3]=0.f; }

    for (int q = 0; q < 16; q++) {
        __syncthreads();
        {
            const int ci = warp;
            const uint32_t* s = xpk + (size_t)(b*CIN + q*8 + ci)*HW + y0*Ww + x0;
            uint32_t dstb = sx + ((ci*WPX1) << 2);
            #pragma unroll
            for (int k = 0; k < 4; k++) {
                int col = lane + k*32;
                cp_async4(dstb + (col << 2), s + col, 4);
            }
        }
        asm volatile("cp.async.commit_group;\n");
        asm volatile("cp.async.wait_group 0;\n");
        __syncthreads();

        const uint2* Ap = wsp1 + q*512;
        uint2 a0 = __ldg(Ap + tig*64 + cog*16 + g);
        uint2 a1 = __ldg(Ap + tig*64 + cog*16 + g + 8);
        uint2 a2 = __ldg(Ap + (tig+4)*64 + cog*16 + g);
        uint2 a3 = __ldg(Ap + (tig+4)*64 + cog*16 + g + 8);
        #pragma unroll
        for (int f = 0; f < 8; f++) {
            uint32_t b0 = xt[tig    *WPX1 + pxb + f*8 + g];
            uint32_t b1 = xt[(tig+4)*WPX1 + pxb + f*8 + g];
            mma16(c[f], a0.x, a1.x, a2.x, a3.x, b0, b1);
            mma16(c[f], a0.y, a1.y, a2.y, a3.y, b0, b1);
        }
    }
    const int co0 = cog*16 + g, co1 = co0 + 8;
    const float b0v = bg[co0], b1v = bg[co1];
    float* r0 = out + (size_t)(b*CO + co0)*HW + y0*Ww + x0;
    float* r1 = out + (size_t)(b*CO + co1)*HW + y0*Ww + x0;
    #pragma unroll
    for (int f = 0; f < 8; f++) {
        int pxl = pxb + f*8 + 2*tig;
        *(float2*)(r0 + pxl) = make_float2(c[f][0] + b0v, c[f][1] + b0v);
        *(float2*)(r1 + pxl) = make_float2(c[f][2] + b1v, c[f][3] + b1v);
    }
}

// ---------------------------------------------------------------------------
extern "C" void kernel_launch(void* const* d_in, const int* in_sizes, int n_in,
                              void* d_out, int out_size)
{
    const float* feat = (const float*)d_in[0];
    const float* mask = (const float*)d_in[1];
    const float* Wl[5]; const float* bl[5]; const float* gl[5]; const float* bel[5];
    for (int l = 0; l < 5; l++) {
        Wl[l]  = (const float*)d_in[2 + 4*l];
        bl[l]  = (const float*)d_in[3 + 4*l];
        gl[l]  = (const float*)d_in[4 + 4*l];
        bel[l] = (const float*)d_in[5 + 4*l];
    }
    const float* Wf = (const float*)d_in[22];
    const float* bf = (const float*)d_in[23];

    float *bufA, *bufB, *mA, *mB, *sums, *ss;
    uint32_t* P;
    uint2* wsp;
    cudaGetSymbolAddress((void**)&bufA, g_bufA);
    cudaGetSymbolAddress((void**)&bufB, g_bufB);
    cudaGetSymbolAddress((void**)&P,    g_bufP);
    cudaGetSymbolAddress((void**)&mA,   g_maskA);
    cudaGetSymbolAddress((void**)&mB,   g_maskB);
    cudaGetSymbolAddress((void**)&sums, g_sums);
    cudaGetSymbolAddress((void**)&ss,   g_ss);
    cudaGetSymbolAddress((void**)&wsp,  g_wsplit);

    // pre-split weight tables (uint2 units)
    const int sz0 = 4608, sz1 = 4608, sz2 = 18432, sz3 = 36864, sz4 = 73728;
    const int off0 = 0, off1 = off0+sz0, off2 = off1+sz1, off3 = off2+sz2, off4 = off3+sz3;
    const int off1x1 = off4 + sz4;   // 138240, +8192 = 146432 <= 150000
    presplit_kernel<<<(sz0+255)/256, 256>>>(Wl[0], wsp+off0, 32, 16, sz0);
    presplit_kernel<<<(sz1+255)/256, 256>>>(Wl[1], wsp+off1, 16, 32, sz1);
    presplit_kernel<<<(sz2+255)/256, 256>>>(Wl[2], wsp+off2, 32, 64, sz2);
    presplit_kernel<<<(sz3+255)/256, 256>>>(Wl[3], wsp+off3, 64, 64, sz3);
    presplit_kernel<<<(sz4+255)/256, 256>>>(Wl[4], wsp+off4, 64, 64, sz4);
    presplit1x1_kernel<<<32, 256>>>(Wf, wsp+off1x1);

    // smem: 24*WPX*4 + 3*WPX*4 + PXT*4 + 2*CO_BLK*4 (+pad)
    const int smem_L0 = 24*268*4 + 3*268*4 + 256*4 + 2*16*4 + 16;
    const int smem_L1 = 24*268*4 + 3*268*4 + 256*4 + 2*32*4 + 16;
    const int smem_Lx = 24*140*4 + 3*140*4 + 128*4 + 2*64*4 + 16;

    auto k0 = conv_mma_kernel<32,16,1,1,256,4>;
    auto k1 = conv_mma_kernel<16,32,1,2,256,8>;
    auto k2 = conv_mma_kernel<32,64,1,1,128,8>;
    auto k3 = conv_mma_kernel<64,64,1,2,128,8>;
    auto k4 = conv_mma_kernel<64,64,2,1,128,8>;
    cudaFuncSetAttribute(k0, cudaFuncAttributeMaxDynamicSharedMemorySize, smem_L0);
    cudaFuncSetAttribute(k1, cudaFuncAttributeMaxDynamicSharedMemorySize, smem_L1);
    cudaFuncSetAttribute(k2, cudaFuncAttributeMaxDynamicSharedMemorySize, smem_Lx);
    cudaFuncSetAttribute(k3, cudaFuncAttributeMaxDynamicSharedMemorySize, smem_Lx);
    cudaFuncSetAttribute(k4, cudaFuncAttributeMaxDynamicSharedMemorySize, smem_Lx);

    auto TFM  = transform_kernel<true,  true >;
    auto TF0  = transform_kernel<false, true >;
    auto TFNM = transform_kernel<true,  false>;
    #define TGRID(C) (((C)*131072 + 255)/256)

    // input transform: feat * mask -> packed
    TF0<<<TGRID(32), 256>>>(feat, mask, nullptr, P, 32, 32*131072);

    // L0: 32 -> 16, d=1
    cudaMemsetAsync(sums, 0, 2*16*sizeof(float));
    k0<<<dim3(256,1,8), 128, smem_L0>>>(P, mask, wsp+off0, bl[0], bufA, mA, sums);
    stats_kernel<<<1,256>>>(sums, gl[0], bel[0], ss, 16);
    TFM<<<TGRID(16), 256>>>(bufA, mA, ss, P, 16, 16*131072);

    // L1: 16 -> 32, d=2
    cudaMemsetAsync(sums, 0, 2*32*sizeof(float));
    k1<<<dim3(256,1,8), 256, smem_L1>>>(P, mA, wsp+off1, bl[1], bufB, mB, sums);
    stats_kernel<<<1,256>>>(sums, gl[1], bel[1], ss, 32);
    TFM<<<TGRID(32), 256>>>(bufB, mB, ss, P, 32, 32*131072);

    // L2: 32 -> 64, d=1
    cudaMemsetAsync(sums, 0, 2*64*sizeof(float));
    k2<<<dim3(512,1,8), 256, smem_Lx>>>(P, mB, wsp+off2, bl[2], bufA, mA, sums);
    stats_kernel<<<1,256>>>(sums, gl[2], bel[2], ss, 64);
    TFM<<<TGRID(64), 256>>>(bufA, mA, ss, P, 64, 64*131072);

    // L3: 64 -> 64, d=2
    cudaMemsetAsync(sums, 0, 2*64*sizeof(float));
    k3<<<dim3(512,1,8), 256, smem_Lx>>>(P, mA, wsp+off3, bl[3], bufB, mB, sums);
    stats_kernel<<<1,256>>>(sums, gl[3], bel[3], ss, 64);
    TFM<<<TGRID(64), 256>>>(bufB, mB, ss, P, 64, 64*131072);

    // L4: 64 -> 128, d=1 (2 co-splits)
    cudaMemsetAsync(sums, 0, 2*128*sizeof(float));
    k4<<<dim3(512,1,16), 256, smem_Lx>>>(P, mB, wsp+off4, bl[4], bufA, mA, sums);
    stats_kernel<<<1,256>>>(sums, gl[4], bel[4], ss, 128);
    TFNM<<<TGRID(128), 256>>>(bufA, nullptr, ss, P, 128, 128*131072);

    // final 1x1 conv
    conv1x1_mma_kernel<<<dim3(512,1,8), 256>>>(P, wsp+off1x1, bf, (float*)d_out);

    // final mask
    const int xelems = Bb*64*HW;
    const int melems = Bb*HW;
    if (out_size >= xelems + melems) {
        cudaMemcpyAsync((float*)d_out + xelems, mA, (size_t)melems*sizeof(float),
                        cudaMemcpyDeviceToDevice);
    }
}

// round 8
// speedup vs baseline: 2.4482x; 1.0635x over previous
#include <cuda_runtime.h>
#include <cstdint>

#define Hh 256
#define Ww 256
#define Bb 8
#define HW 65536
#define NPIX (Bb*HW)   // 524288

// Scratch (device globals — no allocation allowed)
__device__ float    g_bufA[(size_t)Bb*128*HW];
__device__ float    g_bufB[(size_t)Bb*128*HW];
__device__ uint32_t g_bufP[(size_t)Bb*128*HW];   // packed bf16-pair activations
__device__ float    g_maskA[(size_t)Bb*HW];
__device__ float    g_maskB[(size_t)Bb*HW];
__device__ float    g_sums[256];
__device__ float    g_ss[256];
__device__ uint2    g_wsplit[150000];   // pre-split bf16 weight pairs

// ---------------------------------------------------------------------------
// bf16 pair helpers: value v ~ hi + lo, packed (hi low 16 bits, lo high 16)
// ---------------------------------------------------------------------------
__device__ __forceinline__ uint32_t pack_split_bf16(float v) {
    uint16_t hb, lb;
    asm("cvt.rn.bf16.f32 %0, %1;" : "=h"(hb) : "f"(v));
    float hf = __uint_as_float((uint32_t)hb << 16);
    asm("cvt.rn.bf16.f32 %0, %1;" : "=h"(lb) : "f"(v - hf));
    return (uint32_t)hb | ((uint32_t)lb << 16);
}
__device__ __forceinline__ void mma16(float* c,
                                      uint32_t a0, uint32_t a1, uint32_t a2, uint32_t a3,
                                      uint32_t b0, uint32_t b1) {
    asm volatile(
        "mma.sync.aligned.m16n8k16.row.col.f32.bf16.bf16.f32 "
        "{%0,%1,%2,%3},{%4,%5,%6,%7},{%8,%9},{%0,%1,%2,%3};"
        : "+f"(c[0]), "+f"(c[1]), "+f"(c[2]), "+f"(c[3])
        : "r"(a0), "r"(a1), "r"(a2), "r"(a3), "r"(b0), "r"(b1));
}
__device__ __forceinline__ void cp_async4(uint32_t dst_smem, const void* src, int src_size) {
    asm volatile("cp.async.ca.shared.global [%0],[%1],4,%2;\n"
                 :: "r"(dst_smem), "l"(src), "r"(src_size));
}

// ---------------------------------------------------------------------------
// Weight pre-split (3x3 layers)
// ---------------------------------------------------------------------------
__global__ void presplit_kernel(const float* __restrict__ W, uint2* __restrict__ dst,
                                int CIN, int CO_BLK, int total)
{
    int i = blockIdx.x*256 + threadIdx.x;
    if (i >= total) return;
    int co   = i % CO_BLK;
    int ci   = (i / CO_BLK) & 7;
    int t    = (i / (CO_BLK*8)) % 9;
    int rest = i / (CO_BLK*72);
    int chunks = CIN >> 3;
    int q = rest % chunks;
    int s = rest / chunks;
    float v = W[(((s*CO_BLK + co)*CIN) + q*8 + ci)*9 + t];
    uint16_t hb, lb;
    asm("cvt.rn.bf16.f32 %0, %1;" : "=h"(hb) : "f"(v));
    float hf = __uint_as_float((uint32_t)hb << 16);
    asm("cvt.rn.bf16.f32 %0, %1;" : "=h"(lb) : "f"(v - hf));
    dst[i] = make_uint2((uint32_t)hb * 0x00010001u, (uint32_t)lb * 0x00010001u);
}
// 1x1 weights: [q][ci][co], CIN=128, CO=64
__global__ void presplit1x1_kernel(const float* __restrict__ W, uint2* __restrict__ dst)
{
    int i = blockIdx.x*256 + threadIdx.x;
    if (i >= 8192) return;
    int co = i & 63, ci = (i >> 6) & 7, q = i >> 9;
    float v = W[co*128 + q*8 + ci];
    uint16_t hb, lb;
    asm("cvt.rn.bf16.f32 %0, %1;" : "=h"(hb) : "f"(v));
    float hf = __uint_as_float((uint32_t)hb << 16);
    asm("cvt.rn.bf16.f32 %0, %1;" : "=h"(lb) : "f"(v - hf));
    dst[i] = make_uint2((uint32_t)hb * 0x00010001u, (uint32_t)lb * 0x00010001u);
}

// ---------------------------------------------------------------------------
// Activation transform: y(fp32) [+BN+LeakyReLU] [*mask] -> packed bf16 pair.
// ---------------------------------------------------------------------------
template<bool BN, bool MASKED>
__global__ void transform_kernel(const float* __restrict__ y,
                                 const float* __restrict__ m,
                                 const float* __restrict__ ss,
                                 uint32_t* __restrict__ out, int C, int n4)
{
    int i = blockIdx.x*256 + threadIdx.x;
    if (i >= n4) return;
    int plane = i >> 14;
    int c = plane % C;
    int b = plane / C;
    float sc = 1.f, sh = 0.f;
    if (BN) { sc = ss[c]; sh = ss[C + c]; }
    float4 v = ((const float4*)y)[i];
    float4 mk = make_float4(1.f,1.f,1.f,1.f);
    if (MASKED) mk = ((const float4*)m)[b*16384 + (i & 16383)];
    float* vp = &v.x; const float* mp = &mk.x;
    uint32_t r[4];
    #pragma unroll
    for (int k = 0; k < 4; k++) {
        float x = vp[k];
        if (BN) { x = fmaf(x, sc, sh); x = x >= 0.f ? x : 0.01f*x; }
        if (MASKED) x *= mp[k];
        r[k] = pack_split_bf16(x);
    }
    ((uint4*)out)[i] = make_uint4(r[0], r[1], r[2], r[3]);
}

// ---------------------------------------------------------------------------
// Fused sparse-conv block, bf16-pair MMA, DOUBLE-BUFFERED cp.async staging.
// ---------------------------------------------------------------------------
template<int CIN, int CO_BLK, int NSPLIT, int DIL, int PXT, int WARPS>
__global__ void __launch_bounds__(WARPS*32, 3) conv_mma_kernel(
    const uint32_t* __restrict__ xpk, const float* __restrict__ min_,
    const uint2* __restrict__ wsplit, const float* __restrict__ bg,
    float* __restrict__ yout, float* __restrict__ mout,
    float* __restrict__ sums)
{
    constexpr int NT    = WARPS*32;
    constexpr int PXG   = WARPS*16/CO_BLK;
    constexpr int XW    = PXT + 2*DIL;
    constexpr int WPX   = PXT + 12;
    constexpr int XTSZ  = 24*WPX;               // one buffer, uint32 units
    constexpr int COUTT = CO_BLK*NSPLIT;
    constexpr int TX    = 256/PXT;
    constexpr int CHUNKS = CIN/8;

    extern __shared__ char dsm[];
    uint32_t* xt  = (uint32_t*)dsm;             // [2][24][WPX]
    float*  msk = (float*)(xt + 2*XTSZ);        // [3][WPX]
    float*  invc= msk + 3*WPX;                  // [PXT]
    float*  red = invc + PXT;                   // [2*CO_BLK]

    const int tid  = threadIdx.x;
    const int lane = tid & 31, warp = tid >> 5;
    const int g    = lane >> 2, tig = lane & 3;
    const int cog  = warp / PXG, pxg = warp % PXG;
    const int pxb  = pxg * 64;
    const int cb   = cog * 16;
    const uint32_t sx = (uint32_t)__cvta_generic_to_shared(xt);

    const int tile = blockIdx.x;
    const int x0 = (tile % TX) * PXT;
    const int y0 = tile / TX;
    const int z  = blockIdx.z;
    const int b  = z / NSPLIT;
    const int split = z % NSPLIT;
    const int co_base = split * CO_BLK;

    // --- stage mask rows ---
    for (int i = tid; i < 3*XW; i += NT) {
        int col = i % XW, r = i / XW;
        int gy = y0 + (r-1)*DIL, gx = x0 - DIL + col;
        float v = 0.f;
        if (gy >= 0 && gy < Hh && gx >= 0 && gx < Ww) v = min_[b*HW + gy*Ww + gx];
        msk[r*WPX + col] = v;
    }
    for (int i = tid; i < 2*CO_BLK; i += NT) red[i] = 0.f;

    // stage chunk into buffer (no barrier inside)
    auto stage = [&](int q, int buf) {
        for (int ci = warp; ci < 8; ci += WARPS) {
            const uint32_t* srcp = xpk + (size_t)(b*CIN + q*8 + ci)*HW;
            #pragma unroll
            for (int r = 0; r < 3; r++) {
                int gy = y0 + (r-1)*DIL;
                bool rowok = ((unsigned)gy < (unsigned)Hh);
                const uint32_t* srow = srcp + (rowok ? gy*Ww : 0);
                uint32_t dstb = sx + ((buf*XTSZ + (ci*3 + r)*WPX) << 2);
                for (int col = lane; col < XW; col += 32) {
                    int gx = x0 - DIL + col;
                    bool ok = rowok && ((unsigned)gx < (unsigned)Ww);
                    cp_async4(dstb + (col << 2), srow + (ok ? gx : 0), ok ? 4 : 0);
                }
            }
        }
        asm volatile("cp.async.commit_group;\n");
    };

    // prologue: prefetch chunk 0
    stage(0, 0);
    __syncthreads();

    // --- per-pixel 1/count + mask maxpool (overlaps chunk-0 arrival) ---
    for (int px = tid; px < PXT; px += NT) {
        float cnt = 0.f, mn = 0.f;
        #pragma unroll
        for (int ky = 0; ky < 3; ky++)
            #pragma unroll
            for (int kx = 0; kx < 3; kx++) {
                float v = msk[ky*WPX + px + kx*DIL];
                cnt += v; mn = fmaxf(mn, v);
            }
        invc[px] = 1.f / fmaxf(cnt * (float)CIN, 1e-5f);
        if (split == 0) mout[b*HW + y0*Ww + x0 + px] = mn;
    }

    float c[8][4];
    #pragma unroll
    for (int f = 0; f < 8; f++) { c[f][0]=0.f; c[f][1]=0.f; c[f][2]=0.f; c[f][3]=0.f; }

    for (int q = 0; q < CHUNKS; q++) {
        const int buf = q & 1;
        if (q + 1 < CHUNKS) {
            stage(q + 1, buf ^ 1);
            asm volatile("cp.async.wait_group 1;\n");
        } else {
            asm volatile("cp.async.wait_group 0;\n");
        }
        __syncthreads();

        const uint32_t* xb = xt + buf*XTSZ;
        const uint2* Ab = wsplit + (size_t)(split*CHUNKS + q)*72*CO_BLK + cb + g;
        #pragma unroll 3
        for (int t = 0; t < 9; t++) {
            const int ky = t/3, kx = t - 3*ky;
            const uint2* Ap = Ab + t*8*CO_BLK;
            uint2 A0 = __ldg(Ap + tig*CO_BLK);
            uint2 A1 = __ldg(Ap + tig*CO_BLK + 8);
            uint2 A2 = __ldg(Ap + (tig+4)*CO_BLK);
            uint2 A3 = __ldg(Ap + (tig+4)*CO_BLK + 8);
            const uint32_t* brow0 = &xb[(tig    *3 + ky)*WPX + pxb + kx*DIL + g];
            const uint32_t* brow1 = &xb[((tig+4)*3 + ky)*WPX + pxb + kx*DIL + g];
            #pragma unroll
            for (int f = 0; f < 8; f++) {
                uint32_t b0 = brow0[f*8];
                uint32_t b1 = brow1[f*8];
                mma16(c[f], A0.x, A1.x, A2.x, A3.x, b0, b1);  // w_hi * x
                mma16(c[f], A0.y, A1.y, A2.y, A3.y, b0, b1);  // w_lo * x
            }
        }
        __syncthreads();   // buffer q&1 free for restage at iteration q+1
    }

    // --- epilogue ---
    const int gco0 = co_base + cb + g;
    const int gco1 = gco0 + 8;
    const float b0v = bg[gco0], b1v = bg[gco1];
    float* rowp0 = yout + (size_t)(b*COUTT + gco0)*HW + y0*Ww + x0;
    float* rowp1 = yout + (size_t)(b*COUTT + gco1)*HW + y0*Ww + x0;
    float s0 = 0.f, q0 = 0.f, s1 = 0.f, q1 = 0.f;
    #pragma unroll
    for (int f = 0; f < 8; f++) {
        int pxl = pxb + f*8 + 2*tig;
        float i0 = invc[pxl], i1 = invc[pxl + 1];
        float y00 = fmaf(c[f][0], i0, b0v);
        float y01 = fmaf(c[f][1], i1, b0v);
        float y10 = fmaf(c[f][2], i0, b1v);
        float y11 = fmaf(c[f][3], i1, b1v);
        *(float2*)(rowp0 + pxl) = make_float2(y00, y01);
        *(float2*)(rowp1 + pxl) = make_float2(y10, y11);
        s0 += y00 + y01; q0 += y00*y00 + y01*y01;
        s1 += y10 + y11; q1 += y10*y10 + y11*y11;
    }
    #pragma unroll
    for (int o = 1; o <= 2; o <<= 1) {
        s0 += __shfl_xor_sync(0xffffffffu, s0, o);
        q0 += __shfl_xor_sync(0xffffffffu, q0, o);
        s1 += __shfl_xor_sync(0xffffffffu, s1, o);
        q1 += __shfl_xor_sync(0xffffffffu, q1, o);
    }
    if (tig == 0) {
        atomicAdd(&red[cb + g],              s0);
        atomicAdd(&red[CO_BLK + cb + g],     q0);
        atomicAdd(&red[cb + g + 8],          s1);
        atomicAdd(&red[CO_BLK + cb + g + 8], q1);
    }
    __syncthreads();
    if (tid < CO_BLK) {
        atomicAdd(&sums[co_base + tid],          red[tid]);
        atomicAdd(&sums[COUTT + co_base + tid],  red[CO_BLK + tid]);
    }
}

// per-channel scale/shift from sums
__global__ void stats_kernel(const float* __restrict__ sums,
                             const float* __restrict__ g,
                             const float* __restrict__ be,
                             float* __restrict__ ss, int C)
{
    int c = threadIdx.x;
    if (c < C) {
        const float invN = 1.f / (float)NPIX;
        float mean = sums[c] * invN;
        float var  = sums[C + c] * invN - mean*mean;
        float sc = g[c] * rsqrtf(var + 1e-5f);
        ss[c]     = sc;
        ss[C + c] = fmaf(-mean, sc, be[c]);
    }
}

// ---------------------------------------------------------------------------
// final 1x1 conv 128 -> 64, bf16-pair MMA, double-buffered staging
// ---------------------------------------------------------------------------
__global__ void __launch_bounds__(256, 3) conv1x1_mma_kernel(
    const uint32_t* __restrict__ xpk, const uint2* __restrict__ wsp1,
    const float* __restrict__ bg, float* __restrict__ out)
{
    constexpr int CIN = 128, CO = 64, PXT = 128, WPX1 = 140;
    __shared__ uint32_t xt[2*8*WPX1];

    const int tid = threadIdx.x, lane = tid & 31, warp = tid >> 5;
    const int g = lane >> 2, tig = lane & 3;
    const int cog = warp >> 1, pxg = warp & 1;
    const int pxb = pxg * 64;
    const int tile = blockIdx.x;
    const int x0 = (tile & 1)*PXT, y0 = tile >> 1;
    const int b  = blockIdx.z;
    const uint32_t sx = (uint32_t)__cvta_generic_to_shared(xt);

    auto stage = [&](int q, int buf) {
        const int ci = warp;
        const uint32_t* s = xpk + (size_t)(b*CIN + q*8 + ci)*HW + y0*Ww + x0;
        uint32_t dstb = sx + ((buf*8*WPX1 + ci*WPX1) << 2);
        #pragma unroll
        for (int k = 0; k < 4; k++) {
            int col = lane + k*32;
            cp_async4(dstb + (col << 2), s + col, 4);
        }
        asm volatile("cp.async.commit_group;\n");
    };

    float c[8][4];
    #pragma unroll
    for (int f = 0; f < 8; f++) { c[f][0]=0.f; c[f][1]=0.f; c[f][2]=0.f; c[f][3]=0.f; }

    stage(0, 0);
    for (int q = 0; q < 16; q++) {
        const int buf = q & 1;
        if (q + 1 < 16) {
            stage(q + 1, buf ^ 1);
            asm volatile("cp.async.wait_group 1;\n");
        } else {
            asm volatile("cp.async.wait_group 0;\n");
        }
        __syncthreads();

        const uint32_t* xb = xt + buf*8*WPX1;
        const uint2* Ap = wsp1 + q*512;
        uint2 a0 = __ldg(Ap + tig*64 + cog*16 + g);
        uint2 a1 = __ldg(Ap + tig*64 + cog*16 + g + 8);
        uint2 a2 = __ldg(Ap + (tig+4)*64 + cog*16 + g);
        uint2 a3 = __ldg(Ap + (tig+4)*64 + cog*16 + g + 8);
        #pragma unroll
        for (int f = 0; f < 8; f++) {
            uint32_t b0 = xb[tig    *WPX1 + pxb + f*8 + g];
            uint32_t b1 = xb[(tig+4)*WPX1 + pxb + f*8 + g];
            mma16(c[f], a0.x, a1.x, a2.x, a3.x, b0, b1);
            mma16(c[f], a0.y, a1.y, a2.y, a3.y, b0, b1);
        }
        __syncthreads();
    }
    const int co0 = cog*16 + g, co1 = co0 + 8;
    const float b0v = bg[co0], b1v = bg[co1];
    float* r0 = out + (size_t)(b*CO + co0)*HW + y0*Ww + x0;
    float* r1 = out + (size_t)(b*CO + co1)*HW + y0*Ww + x0;
    #pragma unroll
    for (int f = 0; f < 8; f++) {
        int pxl = pxb + f*8 + 2*tig;
        *(float2*)(r0 + pxl) = make_float2(c[f][0] + b0v, c[f][1] + b0v);
        *(float2*)(r1 + pxl) = make_float2(c[f][2] + b1v, c[f][3] + b1v);
    }
}

// ---------------------------------------------------------------------------
extern "C" void kernel_launch(void* const* d_in, const int* in_sizes, int n_in,
                              void* d_out, int out_size)
{
    const float* feat = (const float*)d_in[0];
    const float* mask = (const float*)d_in[1];
    const float* Wl[5]; const float* bl[5]; const float* gl[5]; const float* bel[5];
    for (int l = 0; l < 5; l++) {
        Wl[l]  = (const float*)d_in[2 + 4*l];
        bl[l]  = (const float*)d_in[3 + 4*l];
        gl[l]  = (const float*)d_in[4 + 4*l];
        bel[l] = (const float*)d_in[5 + 4*l];
    }
    const float* Wf = (const float*)d_in[22];
    const float* bf = (const float*)d_in[23];

    float *bufA, *bufB, *mA, *mB, *sums, *ss;
    uint32_t* P;
    uint2* wsp;
    cudaGetSymbolAddress((void**)&bufA, g_bufA);
    cudaGetSymbolAddress((void**)&bufB, g_bufB);
    cudaGetSymbolAddress((void**)&P,    g_bufP);
    cudaGetSymbolAddress((void**)&mA,   g_maskA);
    cudaGetSymbolAddress((void**)&mB,   g_maskB);
    cudaGetSymbolAddress((void**)&sums, g_sums);
    cudaGetSymbolAddress((void**)&ss,   g_ss);
    cudaGetSymbolAddress((void**)&wsp,  g_wsplit);

    const int sz0 = 4608, sz1 = 4608, sz2 = 18432, sz3 = 36864, sz4 = 73728;
    const int off0 = 0, off1 = off0+sz0, off2 = off1+sz1, off3 = off2+sz2, off4 = off3+sz3;
    const int off1x1 = off4 + sz4;
    presplit_kernel<<<(sz0+255)/256, 256>>>(Wl[0], wsp+off0, 32, 16, sz0);
    presplit_kernel<<<(sz1+255)/256, 256>>>(Wl[1], wsp+off1, 16, 32, sz1);
    presplit_kernel<<<(sz2+255)/256, 256>>>(Wl[2], wsp+off2, 32, 64, sz2);
    presplit_kernel<<<(sz3+255)/256, 256>>>(Wl[3], wsp+off3, 64, 64, sz3);
    presplit_kernel<<<(sz4+255)/256, 256>>>(Wl[4], wsp+off4, 64, 64, sz4);
    presplit1x1_kernel<<<32, 256>>>(Wf, wsp+off1x1);

    // smem: 2*24*WPX*4 + 3*WPX*4 + PXT*4 + 2*CO_BLK*4 (+pad)
    const int smem_L0 = 2*24*268*4 + 3*268*4 + 256*4 + 2*16*4 + 16;   // 55840
    const int smem_L1 = 2*24*268*4 + 3*268*4 + 256*4 + 2*32*4 + 16;   // 55968
    const int smem_Lx = 2*24*140*4 + 3*140*4 + 128*4 + 2*64*4 + 16;   // 29600

    auto k0 = conv_mma_kernel<32,16,1,1,256,4>;
    auto k1 = conv_mma_kernel<16,32,1,2,256,8>;
    auto k2 = conv_mma_kernel<32,64,1,1,128,8>;
    auto k3 = conv_mma_kernel<64,64,1,2,128,8>;
    auto k4 = conv_mma_kernel<64,64,2,1,128,8>;
    cudaFuncSetAttribute(k0, cudaFuncAttributeMaxDynamicSharedMemorySize, smem_L0);
    cudaFuncSetAttribute(k1, cudaFuncAttributeMaxDynamicSharedMemorySize, smem_L1);
    cudaFuncSetAttribute(k2, cudaFuncAttributeMaxDynamicSharedMemorySize, smem_Lx);
    cudaFuncSetAttribute(k3, cudaFuncAttributeMaxDynamicSharedMemorySize, smem_Lx);
    cudaFuncSetAttribute(k4, cudaFuncAttributeMaxDynamicSharedMemorySize, smem_Lx);

    auto TFM  = transform_kernel<true,  true >;
    auto TF0  = transform_kernel<false, true >;
    auto TFNM = transform_kernel<true,  false>;
    #define TGRID(C) (((C)*131072 + 255)/256)

    // input transform: feat * mask -> packed
    TF0<<<TGRID(32), 256>>>(feat, mask, nullptr, P, 32, 32*131072);

    // L0: 32 -> 16, d=1
    cudaMemsetAsync(sums, 0, 2*16*sizeof(float));
    k0<<<dim3(256,1,8), 128, smem_L0>>>(P, mask, wsp+off0, bl[0], bufA, mA, sums);
    stats_kernel<<<1,256>>>(sums, gl[0], bel[0], ss, 16);
    TFM<<<TGRID(16), 256>>>(bufA, mA, ss, P, 16, 16*131072);

    // L1: 16 -> 32, d=2
    cudaMemsetAsync(sums, 0, 2*32*sizeof(float));
    k1<<<dim3(256,1,8), 256, smem_L1>>>(P, mA, wsp+off1, bl[1], bufB, mB, sums);
    stats_kernel<<<1,256>>>(sums, gl[1], bel[1], ss, 32);
    TFM<<<TGRID(32), 256>>>(bufB, mB, ss, P, 32, 32*131072);

    // L2: 32 -> 64, d=1
    cudaMemsetAsync(sums, 0, 2*64*sizeof(float));
    k2<<<dim3(512,1,8), 256, smem_Lx>>>(P, mB, wsp+off2, bl[2], bufA, mA, sums);
    stats_kernel<<<1,256>>>(sums, gl[2], bel[2], ss, 64);
    TFM<<<TGRID(64), 256>>>(bufA, mA, ss, P, 64, 64*131072);

    // L3: 64 -> 64, d=2
    cudaMemsetAsync(sums, 0, 2*64*sizeof(float));
    k3<<<dim3(512,1,8), 256, smem_Lx>>>(P, mA, wsp+off3, bl[3], bufB, mB, sums);
    stats_kernel<<<1,256>>>(sums, gl[3], bel[3], ss, 64);
    TFM<<<TGRID(64), 256>>>(bufB, mB, ss, P, 64, 64*131072);

    // L4: 64 -> 128, d=1 (2 co-splits)
    cudaMemsetAsync(sums, 0, 2*128*sizeof(float));
    k4<<<dim3(512,1,16), 256, smem_Lx>>>(P, mB, wsp+off4, bl[4], bufA, mA, sums);
    stats_kernel<<<1,256>>>(sums, gl[4], bel[4], ss, 128);
    TFNM<<<TGRID(128), 256>>>(bufA, nullptr, ss, P, 128, 128*131072);

    // final 1x1 conv
    conv1x1_mma_kernel<<<dim3(512,1,8), 256>>>(P, wsp+off1x1, bf, (float*)d_out);

    // final mask
    const int xelems = Bb*64*HW;
    const int melems = Bb*HW;
    if (out_size >= xelems + melems) {
        cudaMemcpyAsync((float*)d_out + xelems, mA, (size_t)melems*sizeof(float),
                        cudaMemcpyDeviceToDevice);
    }
}

// round 9
// speedup vs baseline: 4.4968x; 1.8368x over previous
#include <cuda_runtime.h>
#include <cuda_fp16.h>
#include <cstdint>

#define Hh 256
#define Ww 256
#define Bb 8
#define HW 65536
#define NPIX (Bb*HW)   // 524288

// Scratch (device globals — no allocation allowed)
__device__ float    g_bufA[(size_t)Bb*128*HW];
__device__ float    g_bufB[(size_t)Bb*128*HW];
__device__ uint32_t g_bufP[(size_t)Bb*64*HW];    // packed fp16 x (2 ci per word)
__device__ float    g_maskA[(size_t)Bb*HW];
__device__ float    g_maskB[(size_t)Bb*HW];
__device__ float    g_sums[256];
__device__ float    g_ss[256];
__device__ uint2    g_wsplit[100000];   // fp16 (hi,lo) weight pair words

// ---------------------------------------------------------------------------
// helpers
// ---------------------------------------------------------------------------
__device__ __forceinline__ uint32_t pack2_f16(float a, float b) {
    __half2 h = __floats2half2_rn(a, b);
    return *reinterpret_cast<uint32_t*>(&h);
}
// D += A(16x8,k16) * B, fp16 operands, fp32 accum
__device__ __forceinline__ void mma16f(float* c,
                                       uint32_t a0, uint32_t a1, uint32_t a2, uint32_t a3,
                                       uint32_t b0, uint32_t b1) {
    asm volatile(
        "mma.sync.aligned.m16n8k16.row.col.f32.f16.f16.f32 "
        "{%0,%1,%2,%3},{%4,%5,%6,%7},{%8,%9},{%0,%1,%2,%3};"
        : "+f"(c[0]), "+f"(c[1]), "+f"(c[2]), "+f"(c[3])
        : "r"(a0), "r"(a1), "r"(a2), "r"(a3), "r"(b0), "r"(b1));
}
__device__ __forceinline__ void cp_async4(uint32_t dst_smem, const void* src, int src_size) {
    asm volatile("cp.async.ca.shared.global [%0],[%1],4,%2;\n"
                 :: "r"(dst_smem), "l"(src), "r"(src_size));
}
__device__ __forceinline__ uint2 wpair(float v0, float v1) {
    __half h0 = __float2half_rn(v0), h1 = __float2half_rn(v1);
    __half l0 = __float2half_rn(v0 - __half2float(h0));
    __half l1 = __float2half_rn(v1 - __half2float(h1));
    __half2 HH = __halves2half2(h0, h1), LL = __halves2half2(l0, l1);
    return make_uint2(*reinterpret_cast<uint32_t*>(&HH), *reinterpret_cast<uint32_t*>(&LL));
}

// ---------------------------------------------------------------------------
// Weight pre-split (3x3): table [(s*chunks+q)*72 + t*8 + pair]*CO_BLK + co
//   chunk = 16 ci; pair word = fp16{w[2p], w[2p+1]}, hi and lo terms.
// ---------------------------------------------------------------------------
__global__ void presplit_kernel(const float* __restrict__ W, uint2* __restrict__ dst,
                                int CIN, int CO_BLK, int total)
{
    int i = blockIdx.x*256 + threadIdx.x;
    if (i >= total) return;
    int co   = i % CO_BLK;
    int pr   = (i / CO_BLK) & 7;
    int t    = (i / (CO_BLK*8)) % 9;
    int rest = i / (CO_BLK*72);
    int chunks = CIN >> 4;
    int q = rest % chunks;
    int s = rest / chunks;
    int ci = q*16 + 2*pr;
    const float* wb = W + ((size_t)(s*CO_BLK + co)*CIN + ci)*9 + t;
    dst[i] = wpair(wb[0], wb[9]);
}
// 1x1 weights: [q][pair][co], CIN=128, CO=64, chunks=8
__global__ void presplit1x1_kernel(const float* __restrict__ W, uint2* __restrict__ dst)
{
    int i = blockIdx.x*256 + threadIdx.x;
    if (i >= 4096) return;
    int co = i & 63, pr = (i >> 6) & 7, q = i >> 9;
    int ci = q*16 + 2*pr;
    dst[i] = wpair(W[co*128 + ci], W[co*128 + ci + 1]);
}

// ---------------------------------------------------------------------------
// Activation transform: pairs of NCHW fp32 planes [+BN+leaky] [*mask]
//   -> one packed fp16x2 plane per pair.
// ---------------------------------------------------------------------------
template<bool BN, bool MASKED>
__global__ void transform_kernel(const float* __restrict__ y,
                                 const float* __restrict__ m,
                                 const float* __restrict__ ss,
                                 uint32_t* __restrict__ out, int C, int n4)
{
    int i = blockIdx.x*256 + threadIdx.x;
    if (i >= n4) return;
    int plane = i >> 14;            // output pair-plane index
    int half = C >> 1;
    int pp = plane % half;
    int b  = plane / half;
    int c0 = pp*2;
    float sc0 = 1.f, sh0 = 0.f, sc1 = 1.f, sh1 = 0.f;
    if (BN) { sc0 = ss[c0]; sh0 = ss[C + c0]; sc1 = ss[c0+1]; sh1 = ss[C + c0 + 1]; }
    int px4 = i & 16383;
    float4 v0 = ((const float4*)y)[(((size_t)b*C + c0    ) << 14) + px4];
    float4 v1 = ((const float4*)y)[(((size_t)b*C + c0 + 1) << 14) + px4];
    float4 mk = make_float4(1.f,1.f,1.f,1.f);
    if (MASKED) mk = ((const float4*)m)[(((size_t)b) << 14) + px4];
    const float* p0 = &v0.x; const float* p1 = &v1.x; const float* pm = &mk.x;
    uint32_t r[4];
    #pragma unroll
    for (int k = 0; k < 4; k++) {
        float a = p0[k], c = p1[k];
        if (BN) {
            a = fmaf(a, sc0, sh0); a = a >= 0.f ? a : 0.01f*a;
            c = fmaf(c, sc1, sh1); c = c >= 0.f ? c : 0.01f*c;
        }
        if (MASKED) { a *= pm[k]; c *= pm[k]; }
        r[k] = pack2_f16(a, c);
    }
    ((uint4*)out)[i] = make_uint4(r[0], r[1], r[2], r[3]);
}

// ---------------------------------------------------------------------------
// Fused sparse-conv block, fp16 asymmetric-split MMA (k16 = 16 ci),
// double-buffered cp.async staging of pair-planes.
// ---------------------------------------------------------------------------
template<int CIN, int CO_BLK, int NSPLIT, int DIL, int PXT, int WARPS>
__global__ void __launch_bounds__(WARPS*32, 3) conv_mma_kernel(
    const uint32_t* __restrict__ xpk, const float* __restrict__ min_,
    const uint2* __restrict__ wsplit, const float* __restrict__ bg,
    float* __restrict__ yout, float* __restrict__ mout,
    float* __restrict__ sums)
{
    constexpr int NT    = WARPS*32;
    constexpr int PXG   = WARPS*16/CO_BLK;
    constexpr int XW    = PXT + 2*DIL;
    constexpr int WPX   = PXT + 12;
    constexpr int XTSZ  = 24*WPX;               // one buffer (8 pairs x 3 rows)
    constexpr int COUTT = CO_BLK*NSPLIT;
    constexpr int TX    = 256/PXT;
    constexpr int CHUNKS = CIN/16;
    constexpr int PLANES = CIN/2;

    extern __shared__ char dsm[];
    uint32_t* xt  = (uint32_t*)dsm;             // [2][24][WPX]
    float*  msk = (float*)(xt + 2*XTSZ);        // [3][WPX]
    float*  invc= msk + 3*WPX;                  // [PXT]
    float*  red = invc + PXT;                   // [2*CO_BLK]

    const int tid  = threadIdx.x;
    const int lane = tid & 31, warp = tid >> 5;
    const int g    = lane >> 2, tig = lane & 3;
    const int cog  = warp / PXG, pxg = warp % PXG;
    const int pxb  = pxg * 64;
    const int cb   = cog * 16;
    const uint32_t sx = (uint32_t)__cvta_generic_to_shared(xt);

    const int tile = blockIdx.x;
    const int x0 = (tile % TX) * PXT;
    const int y0 = tile / TX;
    const int z  = blockIdx.z;
    const int b  = z / NSPLIT;
    const int split = z % NSPLIT;
    const int co_base = split * CO_BLK;

    // --- stage mask rows ---
    for (int i = tid; i < 3*XW; i += NT) {
        int col = i % XW, r = i / XW;
        int gy = y0 + (r-1)*DIL, gx = x0 - DIL + col;
        float v = 0.f;
        if (gy >= 0 && gy < Hh && gx >= 0 && gx < Ww) v = min_[b*HW + gy*Ww + gx];
        msk[r*WPX + col] = v;
    }
    for (int i = tid; i < 2*CO_BLK; i += NT) red[i] = 0.f;

    // stage chunk q (8 pair-planes x 3 rows) into buffer
    auto stage = [&](int q, int buf) {
        for (int pr = warp; pr < 8; pr += WARPS) {
            const uint32_t* srcp = xpk + (size_t)(b*PLANES + q*8 + pr)*HW;
            #pragma unroll
            for (int r = 0; r < 3; r++) {
                int gy = y0 + (r-1)*DIL;
                bool rowok = ((unsigned)gy < (unsigned)Hh);
                const uint32_t* srow = srcp + (rowok ? gy*Ww : 0);
                uint32_t dstb = sx + ((buf*XTSZ + (pr*3 + r)*WPX) << 2);
                for (int col = lane; col < XW; col += 32) {
                    int gx = x0 - DIL + col;
                    bool ok = rowok && ((unsigned)gx < (unsigned)Ww);
                    cp_async4(dstb + (col << 2), srow + (ok ? gx : 0), ok ? 4 : 0);
                }
            }
        }
        asm volatile("cp.async.commit_group;\n");
    };

    stage(0, 0);
    __syncthreads();

    // --- per-pixel 1/count + mask maxpool (overlaps chunk-0 arrival) ---
    for (int px = tid; px < PXT; px += NT) {
        float cnt = 0.f, mn = 0.f;
        #pragma unroll
        for (int ky = 0; ky < 3; ky++)
            #pragma unroll
            for (int kx = 0; kx < 3; kx++) {
                float v = msk[ky*WPX + px + kx*DIL];
                cnt += v; mn = fmaxf(mn, v);
            }
        invc[px] = 1.f / fmaxf(cnt * (float)CIN, 1e-5f);
        if (split == 0) mout[b*HW + y0*Ww + x0 + px] = mn;
    }

    float c[8][4];
    #pragma unroll
    for (int f = 0; f < 8; f++) { c[f][0]=0.f; c[f][1]=0.f; c[f][2]=0.f; c[f][3]=0.f; }

    for (int q = 0; q < CHUNKS; q++) {
        const int buf = q & 1;
        if (q + 1 < CHUNKS) {
            stage(q + 1, buf ^ 1);
            asm volatile("cp.async.wait_group 1;\n");
        } else {
            asm volatile("cp.async.wait_group 0;\n");
        }
        __syncthreads();

        const uint32_t* xb = xt + buf*XTSZ;
        const uint2* Ab = wsplit + (size_t)(split*CHUNKS + q)*72*CO_BLK + cb + g;
        #pragma unroll 3
        for (int t = 0; t < 9; t++) {
            const int ky = t/3, kx = t - 3*ky;
            const uint2* Ap = Ab + t*8*CO_BLK;
            uint2 A0 = __ldg(Ap + tig*CO_BLK);          // k pair tig, co g
            uint2 A1 = __ldg(Ap + tig*CO_BLK + 8);      // co g+8
            uint2 A2 = __ldg(Ap + (tig+4)*CO_BLK);      // k pair tig+4
            uint2 A3 = __ldg(Ap + (tig+4)*CO_BLK + 8);
            const uint32_t* brow0 = &xb[(tig    *3 + ky)*WPX + pxb + kx*DIL + g];
            const uint32_t* brow1 = &xb[((tig+4)*3 + ky)*WPX + pxb + kx*DIL + g];
            #pragma unroll
            for (int f = 0; f < 8; f++) {
                uint32_t b0 = brow0[f*8];
                uint32_t b1 = brow1[f*8];
                mma16f(c[f], A0.x, A1.x, A2.x, A3.x, b0, b1);  // w_hi * x
                mma16f(c[f], A0.y, A1.y, A2.y, A3.y, b0, b1);  // w_lo * x
            }
        }
        __syncthreads();
    }

    // --- epilogue ---
    const int gco0 = co_base + cb + g;
    const int gco1 = gco0 + 8;
    const float b0v = bg[gco0], b1v = bg[gco1];
    float* rowp0 = yout + (size_t)(b*COUTT + gco0)*HW + y0*Ww + x0;
    float* rowp1 = yout + (size_t)(b*COUTT + gco1)*HW + y0*Ww + x0;
    float s0 = 0.f, q0 = 0.f, s1 = 0.f, q1 = 0.f;
    #pragma unroll
    for (int f = 0; f < 8; f++) {
        int pxl = pxb + f*8 + 2*tig;
        float i0 = invc[pxl], i1 = invc[pxl + 1];
        float y00 = fmaf(c[f][0], i0, b0v);
        float y01 = fmaf(c[f][1], i1, b0v);
        float y10 = fmaf(c[f][2], i0, b1v);
        float y11 = fmaf(c[f][3], i1, b1v);
        *(float2*)(rowp0 + pxl) = make_float2(y00, y01);
        *(float2*)(rowp1 + pxl) = make_float2(y10, y11);
        s0 += y00 + y01; q0 += y00*y00 + y01*y01;
        s1 += y10 + y11; q1 += y10*y10 + y11*y11;
    }
    #pragma unroll
    for (int o = 1; o <= 2; o <<= 1) {
        s0 += __shfl_xor_sync(0xffffffffu, s0, o);
        q0 += __shfl_xor_sync(0xffffffffu, q0, o);
        s1 += __shfl_xor_sync(0xffffffffu, s1, o);
        q1 += __shfl_xor_sync(0xffffffffu, q1, o);
    }
    if (tig == 0) {
        atomicAdd(&red[cb + g],              s0);
        atomicAdd(&red[CO_BLK + cb + g],     q0);
        atomicAdd(&red[cb + g + 8],          s1);
        atomicAdd(&red[CO_BLK + cb + g + 8], q1);
    }
    __syncthreads();
    if (tid < CO_BLK) {
        atomicAdd(&sums[co_base + tid],          red[tid]);
        atomicAdd(&sums[COUTT + co_base + tid],  red[CO_BLK + tid]);
    }
}

// per-channel scale/shift from sums
__global__ void stats_kernel(const float* __restrict__ sums,
                             const float* __restrict__ g,
                             const float* __restrict__ be,
                             float* __restrict__ ss, int C)
{
    int c = threadIdx.x;
    if (c < C) {
        const float invN = 1.f / (float)NPIX;
        float mean = sums[c] * invN;
        float var  = sums[C + c] * invN - mean*mean;
        float sc = g[c] * rsqrtf(var + 1e-5f);
        ss[c]     = sc;
        ss[C + c] = fmaf(-mean, sc, be[c]);
    }
}

// ---------------------------------------------------------------------------
// final 1x1 conv 128 -> 64, fp16 asymmetric split, double-buffered
// ---------------------------------------------------------------------------
__global__ void __launch_bounds__(256, 3) conv1x1_mma_kernel(
    const uint32_t* __restrict__ xpk, const uint2* __restrict__ wsp1,
    const float* __restrict__ bg, float* __restrict__ out)
{
    constexpr int CO = 64, PXT = 128, WPX1 = 140, PLANES = 64;
    __shared__ uint32_t xt[2*8*WPX1];

    const int tid = threadIdx.x, lane = tid & 31, warp = tid >> 5;
    const int g = lane >> 2, tig = lane & 3;
    const int cog = warp >> 1, pxg = warp & 1;
    const int pxb = pxg * 64;
    const int tile = blockIdx.x;
    const int x0 = (tile & 1)*PXT, y0 = tile >> 1;
    const int b  = blockIdx.z;
    const uint32_t sx = (uint32_t)__cvta_generic_to_shared(xt);

    auto stage = [&](int q, int buf) {
        const int pr = warp;
        const uint32_t* s = xpk + (size_t)(b*PLANES + q*8 + pr)*HW + y0*Ww + x0;
        uint32_t dstb = sx + ((buf*8*WPX1 + pr*WPX1) << 2);
        #pragma unroll
        for (int k = 0; k < 4; k++) {
            int col = lane + k*32;
            cp_async4(dstb + (col << 2), s + col, 4);
        }
        asm volatile("cp.async.commit_group;\n");
    };

    float c[8][4];
    #pragma unroll
    for (int f = 0; f < 8; f++) { c[f][0]=0.f; c[f][1]=0.f; c[f][2]=0.f; c[f][3]=0.f; }

    stage(0, 0);
    for (int q = 0; q < 8; q++) {
        const int buf = q & 1;
        if (q + 1 < 8) {
            stage(q + 1, buf ^ 1);
            asm volatile("cp.async.wait_group 1;\n");
        } else {
            asm volatile("cp.async.wait_group 0;\n");
        }
        __syncthreads();

        const uint32_t* xb = xt + buf*8*WPX1;
        const uint2* Ap = wsp1 + q*512;
        uint2 a0 = __ldg(Ap + tig*64 + cog*16 + g);
        uint2 a1 = __ldg(Ap + tig*64 + cog*16 + g + 8);
        uint2 a2 = __ldg(Ap + (tig+4)*64 + cog*16 + g);
        uint2 a3 = __ldg(Ap + (tig+4)*64 + cog*16 + g + 8);
        #pragma unroll
        for (int f = 0; f < 8; f++) {
            uint32_t b0 = xb[tig    *WPX1 + pxb + f*8 + g];
            uint32_t b1 = xb[(tig+4)*WPX1 + pxb + f*8 + g];
            mma16f(c[f], a0.x, a1.x, a2.x, a3.x, b0, b1);
            mma16f(c[f], a0.y, a1.y, a2.y, a3.y, b0, b1);
        }
        __syncthreads();
    }
    const int co0 = cog*16 + g, co1 = co0 + 8;
    const float b0v = bg[co0], b1v = bg[co1];
    float* r0 = out + (size_t)(b*CO + co0)*HW + y0*Ww + x0;
    float* r1 = out + (size_t)(b*CO + co1)*HW + y0*Ww + x0;
    #pragma unroll
    for (int f = 0; f < 8; f++) {
        int pxl = pxb + f*8 + 2*tig;
        *(float2*)(r0 + pxl) = make_float2(c[f][0] + b0v, c[f][1] + b0v);
        *(float2*)(r1 + pxl) = make_float2(c[f][2] + b1v, c[f][3] + b1v);
    }
}

// ---------------------------------------------------------------------------
extern "C" void kernel_launch(void* const* d_in, const int* in_sizes, int n_in,
                              void* d_out, int out_size)
{
    const float* feat = (const float*)d_in[0];
    const float* mask = (const float*)d_in[1];
    const float* Wl[5]; const float* bl[5]; const float* gl[5]; const float* bel[5];
    for (int l = 0; l < 5; l++) {
        Wl[l]  = (const float*)d_in[2 + 4*l];
        bl[l]  = (const float*)d_in[3 + 4*l];
        gl[l]  = (const float*)d_in[4 + 4*l];
        bel[l] = (const float*)d_in[5 + 4*l];
    }
    const float* Wf = (const float*)d_in[22];
    const float* bf = (const float*)d_in[23];

    float *bufA, *bufB, *mA, *mB, *sums, *ss;
    uint32_t* P;
    uint2* wsp;
    cudaGetSymbolAddress((void**)&bufA, g_bufA);
    cudaGetSymbolAddress((void**)&bufB, g_bufB);
    cudaGetSymbolAddress((void**)&P,    g_bufP);
    cudaGetSymbolAddress((void**)&mA,   g_maskA);
    cudaGetSymbolAddress((void**)&mB,   g_maskB);
    cudaGetSymbolAddress((void**)&sums, g_sums);
    cudaGetSymbolAddress((void**)&ss,   g_ss);
    cudaGetSymbolAddress((void**)&wsp,  g_wsplit);

    // table sizes (uint2): chunks*NSPLIT*72*CO_BLK
    const int sz0 = 2*72*16, sz1 = 1*72*32, sz2 = 2*72*64, sz3 = 4*72*64, sz4 = 8*72*64;
    const int off0 = 0, off1 = off0+sz0, off2 = off1+sz1, off3 = off2+sz2, off4 = off3+sz3;
    const int off1x1 = off4 + sz4;
    presplit_kernel<<<(sz0+255)/256, 256>>>(Wl[0], wsp+off0, 32, 16, sz0);
    presplit_kernel<<<(sz1+255)/256, 256>>>(Wl[1], wsp+off1, 16, 32, sz1);
    presplit_kernel<<<(sz2+255)/256, 256>>>(Wl[2], wsp+off2, 32, 64, sz2);
    presplit_kernel<<<(sz3+255)/256, 256>>>(Wl[3], wsp+off3, 64, 64, sz3);
    presplit_kernel<<<(sz4+255)/256, 256>>>(Wl[4], wsp+off4, 64, 64, sz4);
    presplit1x1_kernel<<<16, 256>>>(Wf, wsp+off1x1);

    // smem: 2*24*WPX*4 + 3*WPX*4 + PXT*4 + 2*CO_BLK*4 (+pad)
    const int smem_L0 = 2*24*268*4 + 3*268*4 + 256*4 + 2*16*4 + 16;
    const int smem_L1 = 2*24*268*4 + 3*268*4 + 256*4 + 2*32*4 + 16;
    const int smem_Lx = 2*24*140*4 + 3*140*4 + 128*4 + 2*64*4 + 16;

    auto k0 = conv_mma_kernel<32,16,1,1,256,4>;
    auto k1 = conv_mma_kernel<16,32,1,2,256,8>;
    auto k2 = conv_mma_kernel<32,64,1,1,128,8>;
    auto k3 = conv_mma_kernel<64,64,1,2,128,8>;
    auto k4 = conv_mma_kernel<64,64,2,1,128,8>;
    cudaFuncSetAttribute(k0, cudaFuncAttributeMaxDynamicSharedMemorySize, smem_L0);
    cudaFuncSetAttribute(k1, cudaFuncAttributeMaxDynamicSharedMemorySize, smem_L1);
    cudaFuncSetAttribute(k2, cudaFuncAttributeMaxDynamicSharedMemorySize, smem_Lx);
    cudaFuncSetAttribute(k3, cudaFuncAttributeMaxDynamicSharedMemorySize, smem_Lx);
    cudaFuncSetAttribute(k4, cudaFuncAttributeMaxDynamicSharedMemorySize, smem_Lx);

    auto TFM  = transform_kernel<true,  true >;
    auto TF0  = transform_kernel<false, true >;
    auto TFNM = transform_kernel<true,  false>;
    // n4 = (C/2) pair-planes * 8 imgs * 16384 float4 = C*65536
    #define TGRID(C) (((C)*65536 + 255)/256)

    // input transform: feat * mask -> packed fp16 pairs
    TF0<<<TGRID(32), 256>>>(feat, mask, nullptr, P, 32, 32*65536);

    // L0: 32 -> 16, d=1
    cudaMemsetAsync(sums, 0, 2*16*sizeof(float));
    k0<<<dim3(256,1,8), 128, smem_L0>>>(P, mask, wsp+off0, bl[0], bufA, mA, sums);
    stats_kernel<<<1,256>>>(sums, gl[0], bel[0], ss, 16);
    TFM<<<TGRID(16), 256>>>(bufA, mA, ss, P, 16, 16*65536);

    // L1: 16 -> 32, d=2
    cudaMemsetAsync(sums, 0, 2*32*sizeof(float));
    k1<<<dim3(256,1,8), 256, smem_L1>>>(P, mA, wsp+off1, bl[1], bufB, mB, sums);
    stats_kernel<<<1,256>>>(sums, gl[1], bel[1], ss, 32);
    TFM<<<TGRID(32), 256>>>(bufB, mB, ss, P, 32, 32*65536);

    // L2: 32 -> 64, d=1
    cudaMemsetAsync(sums, 0, 2*64*sizeof(float));
    k2<<<dim3(512,1,8), 256, smem_Lx>>>(P, mB, wsp+off2, bl[2], bufA, mA, sums);
    stats_kernel<<<1,256>>>(sums, gl[2], bel[2], ss, 64);
    TFM<<<TGRID(64), 256>>>(bufA, mA, ss, P, 64, 64*65536);

    // L3: 64 -> 64, d=2
    cudaMemsetAsync(sums, 0, 2*64*sizeof(float));
    k3<<<dim3(512,1,8), 256, smem_Lx>>>(P, mA, wsp+off3, bl[3], bufB, mB, sums);
    stats_kernel<<<1,256>>>(sums, gl[3], bel[3], ss, 64);
    TFM<<<TGRID(64), 256>>>(bufB, mB, ss, P, 64, 64*65536);

    // L4: 64 -> 128, d=1 (2 co-splits)
    cudaMemsetAsync(sums, 0, 2*128*sizeof(float));
    k4<<<dim3(512,1,16), 256, smem_Lx>>>(P, mB, wsp+off4, bl[4], bufA, mA, sums);
    stats_kernel<<<1,256>>>(sums, gl[4], bel[4], ss, 128);
    TFNM<<<TGRID(128), 256>>>(bufA, nullptr, ss, P, 128, 128*65536);

    // final 1x1 conv
    conv1x1_mma_kernel<<<dim3(512,1,8), 256>>>(P, wsp+off1x1, bf, (float*)d_out);

    // final mask
    const int xelems = Bb*64*HW;
    const int melems = Bb*HW;
    if (out_size >= xelems + melems) {
        cudaMemcpyAsync((float*)d_out + xelems, mA, (size_t)melems*sizeof(float),
                        cudaMemcpyDeviceToDevice);
    }
}

// round 10
// speedup vs baseline: 4.6664x; 1.0377x over previous
#include <cuda_runtime.h>
#include <cuda_fp16.h>
#include <cstdint>

#define Hh 256
#define Ww 256
#define Bb 8
#define HW 65536
#define NPIX (Bb*HW)   // 524288

// Scratch (device globals — no allocation allowed)
__device__ float    g_bufA[(size_t)Bb*128*HW];
__device__ float    g_bufB[(size_t)Bb*128*HW];
__device__ uint32_t g_bufP[(size_t)Bb*64*HW];    // packed fp16 x (2 ci per word)
__device__ float    g_maskA[(size_t)Bb*HW];
__device__ float    g_maskB[(size_t)Bb*HW];
__device__ float    g_sums[512];                 // two ping-pong buffers of 256
__device__ uint2    g_wsplit[100000];            // fp16 (hi,lo) weight pair words

// ---------------------------------------------------------------------------
// helpers
// ---------------------------------------------------------------------------
__device__ __forceinline__ uint32_t pack2_f16(float a, float b) {
    __half2 h = __floats2half2_rn(a, b);
    return *reinterpret_cast<uint32_t*>(&h);
}
__device__ __forceinline__ void mma16f(float* c,
                                       uint32_t a0, uint32_t a1, uint32_t a2, uint32_t a3,
                                       uint32_t b0, uint32_t b1) {
    asm volatile(
        "mma.sync.aligned.m16n8k16.row.col.f32.f16.f16.f32 "
        "{%0,%1,%2,%3},{%4,%5,%6,%7},{%8,%9},{%0,%1,%2,%3};"
        : "+f"(c[0]), "+f"(c[1]), "+f"(c[2]), "+f"(c[3])
        : "r"(a0), "r"(a1), "r"(a2), "r"(a3), "r"(b0), "r"(b1));
}
__device__ __forceinline__ void cp_async4(uint32_t dst_smem, const void* src, int src_size) {
    asm volatile("cp.async.ca.shared.global [%0],[%1],4,%2;\n"
                 :: "r"(dst_smem), "l"(src), "r"(src_size));
}
__device__ __forceinline__ uint2 wpair(float v0, float v1) {
    __half h0 = __float2half_rn(v0), h1 = __float2half_rn(v1);
    __half l0 = __float2half_rn(v0 - __half2float(h0));
    __half l1 = __float2half_rn(v1 - __half2float(h1));
    __half2 HH = __halves2half2(h0, h1), LL = __halves2half2(l0, l1);
    return make_uint2(*reinterpret_cast<uint32_t*>(&HH), *reinterpret_cast<uint32_t*>(&LL));
}

// ---------------------------------------------------------------------------
// Weight pre-split, ALL 3x3 layers in one launch.
//   table: [(s*chunks+q)*72 + t*8 + pair]*CO_BLK + co ; chunk = 16 ci.
// Segments (uint2 offsets): L0@0(2304) L1@2304(2304) L2@4608(9216)
//   L3@13824(18432) L4@32256(36864, CO_BLK=128)  total 69120
// ---------------------------------------------------------------------------
__device__ __forceinline__ void presplit_one(const float* W, uint2* dst,
                                             int CIN, int CO_BLK, int i)
{
    int co   = i % CO_BLK;
    int pr   = (i / CO_BLK) & 7;
    int t    = (i / (CO_BLK*8)) % 9;
    int rest = i / (CO_BLK*72);
    int chunks = CIN >> 4;
    int q = rest % chunks;
    int s = rest / chunks;
    int ci = q*16 + 2*pr;
    const float* wb = W + ((size_t)(s*CO_BLK + co)*CIN + ci)*9 + t;
    dst[i] = wpair(wb[0], wb[9]);
}
__global__ void presplit3x3_all(const float* __restrict__ W0, const float* __restrict__ W1,
                                const float* __restrict__ W2, const float* __restrict__ W3,
                                const float* __restrict__ W4, uint2* __restrict__ dst)
{
    int j = blockIdx.x*256 + threadIdx.x;
    if (j >= 69120) return;
    if      (j < 2304)  presplit_one(W0, dst,          32, 16,  j);
    else if (j < 4608)  presplit_one(W1, dst + 2304,   16, 32,  j - 2304);
    else if (j < 13824) presplit_one(W2, dst + 4608,   32, 64,  j - 4608);
    else if (j < 32256) presplit_one(W3, dst + 13824,  64, 64,  j - 13824);
    else                presplit_one(W4, dst + 32256,  64, 128, j - 32256);
}
// 1x1 weights: [q][pair][co], CIN=128, CO=64, chunks=8
__global__ void presplit1x1_kernel(const float* __restrict__ W, uint2* __restrict__ dst)
{
    int i = blockIdx.x*256 + threadIdx.x;
    if (i >= 4096) return;
    int co = i & 63, pr = (i >> 6) & 7, q = i >> 9;
    int ci = q*16 + 2*pr;
    dst[i] = wpair(W[co*128 + ci], W[co*128 + ci + 1]);
}

// ---------------------------------------------------------------------------
// Activation transform + fused BN-stats finalization + next-sums zeroing.
//   pairs of NCHW fp32 planes [+BN+leaky] [*mask] -> one packed fp16x2 plane.
// ---------------------------------------------------------------------------
template<bool BN, bool MASKED>
__global__ void transform_kernel(const float* __restrict__ y,
                                 const float* __restrict__ m,
                                 const float* __restrict__ sums,
                                 const float* __restrict__ gam,
                                 const float* __restrict__ bet,
                                 float* __restrict__ sums_next,
                                 uint32_t* __restrict__ out, int C, int n4)
{
    __shared__ float ssm[256];
    const int tid = threadIdx.x;
    if (BN) {
        if (tid < C) {
            const float invN = 1.f / (float)NPIX;
            float mean = sums[tid] * invN;
            float var  = sums[C + tid] * invN - mean*mean;
            float sc = gam[tid] * rsqrtf(var + 1e-5f);
            ssm[tid]     = sc;
            ssm[C + tid] = fmaf(-mean, sc, bet[tid]);
        }
        __syncthreads();
    }
    if (blockIdx.x == 0 && sums_next != nullptr && tid < 256) sums_next[tid] = 0.f;

    int i = blockIdx.x*256 + tid;
    if (i >= n4) return;
    int plane = i >> 14;
    int half = C >> 1;
    int pp = plane % half;
    int b  = plane / half;
    int c0 = pp*2;
    float sc0 = 1.f, sh0 = 0.f, sc1 = 1.f, sh1 = 0.f;
    if (BN) { sc0 = ssm[c0]; sh0 = ssm[C + c0]; sc1 = ssm[c0+1]; sh1 = ssm[C + c0 + 1]; }
    int px4 = i & 16383;
    float4 v0 = ((const float4*)y)[(((size_t)b*C + c0    ) << 14) + px4];
    float4 v1 = ((const float4*)y)[(((size_t)b*C + c0 + 1) << 14) + px4];
    float4 mk = make_float4(1.f,1.f,1.f,1.f);
    if (MASKED) mk = ((const float4*)m)[(((size_t)b) << 14) + px4];
    const float* p0 = &v0.x; const float* p1 = &v1.x; const float* pm = &mk.x;
    uint32_t r[4];
    #pragma unroll
    for (int k = 0; k < 4; k++) {
        float a = p0[k], c = p1[k];
        if (BN) {
            a = fmaf(a, sc0, sh0); a = a >= 0.f ? a : 0.01f*a;
            c = fmaf(c, sc1, sh1); c = c >= 0.f ? c : 0.01f*c;
        }
        if (MASKED) { a *= pm[k]; c *= pm[k]; }
        r[k] = pack2_f16(a, c);
    }
    ((uint4*)out)[i] = make_uint4(r[0], r[1], r[2], r[3]);
}

// ---------------------------------------------------------------------------
// Fused sparse-conv block, fp16 asymmetric-split MMA (k16 = 16 ci),
// double-buffered cp.async staging of pair-planes.
// ---------------------------------------------------------------------------
template<int CIN, int CO_BLK, int NSPLIT, int DIL, int PXT, int WARPS>
__global__ void __launch_bounds__(WARPS*32, 3) conv_mma_kernel(
    const uint32_t* __restrict__ xpk, const float* __restrict__ min_,
    const uint2* __restrict__ wsplit, const float* __restrict__ bg,
    float* __restrict__ yout, float* __restrict__ mout,
    float* __restrict__ sums)
{
    constexpr int NT    = WARPS*32;
    constexpr int PXG   = WARPS*16/CO_BLK;
    constexpr int XW    = PXT + 2*DIL;
    constexpr int WPX   = PXT + 12;
    constexpr int XTSZ  = 24*WPX;
    constexpr int COUTT = CO_BLK*NSPLIT;
    constexpr int TX    = 256/PXT;
    constexpr int CHUNKS = CIN/16;
    constexpr int PLANES = CIN/2;

    extern __shared__ char dsm[];
    uint32_t* xt  = (uint32_t*)dsm;             // [2][24][WPX]
    float*  msk = (float*)(xt + 2*XTSZ);        // [3][WPX]
    float*  invc= msk + 3*WPX;                  // [PXT]
    float*  red = invc + PXT;                   // [2*CO_BLK]

    const int tid  = threadIdx.x;
    const int lane = tid & 31, warp = tid >> 5;
    const int g    = lane >> 2, tig = lane & 3;
    const int cog  = warp / PXG, pxg = warp % PXG;
    const int pxb  = pxg * 64;
    const int cb   = cog * 16;
    const uint32_t sx = (uint32_t)__cvta_generic_to_shared(xt);

    const int tile = blockIdx.x;
    const int x0 = (tile % TX) * PXT;
    const int y0 = tile / TX;
    const int z  = blockIdx.z;
    const int b  = z / NSPLIT;
    const int split = z % NSPLIT;
    const int co_base = split * CO_BLK;

    // --- stage mask rows ---
    for (int i = tid; i < 3*XW; i += NT) {
        int col = i % XW, r = i / XW;
        int gy = y0 + (r-1)*DIL, gx = x0 - DIL + col;
        float v = 0.f;
        if (gy >= 0 && gy < Hh && gx >= 0 && gx < Ww) v = min_[b*HW + gy*Ww + gx];
        msk[r*WPX + col] = v;
    }
    for (int i = tid; i < 2*CO_BLK; i += NT) red[i] = 0.f;

    auto stage = [&](int q, int buf) {
        for (int pr = warp; pr < 8; pr += WARPS) {
            const uint32_t* srcp = xpk + (size_t)(b*PLANES + q*8 + pr)*HW;
            #pragma unroll
            for (int r = 0; r < 3; r++) {
                int gy = y0 + (r-1)*DIL;
                bool rowok = ((unsigned)gy < (unsigned)Hh);
                const uint32_t* srow = srcp + (rowok ? gy*Ww : 0);
                uint32_t dstb = sx + ((buf*XTSZ + (pr*3 + r)*WPX) << 2);
                for (int col = lane; col < XW; col += 32) {
                    int gx = x0 - DIL + col;
                    bool ok = rowok && ((unsigned)gx < (unsigned)Ww);
                    cp_async4(dstb + (col << 2), srow + (ok ? gx : 0), ok ? 4 : 0);
                }
            }
        }
        asm volatile("cp.async.commit_group;\n");
    };

    stage(0, 0);
    __syncthreads();

    // --- per-pixel 1/count + mask maxpool (overlaps chunk-0 arrival) ---
    for (int px = tid; px < PXT; px += NT) {
        float cnt = 0.f, mn = 0.f;
        #pragma unroll
        for (int ky = 0; ky < 3; ky++)
            #pragma unroll
            for (int kx = 0; kx < 3; kx++) {
                float v = msk[ky*WPX + px + kx*DIL];
                cnt += v; mn = fmaxf(mn, v);
            }
        invc[px] = 1.f / fmaxf(cnt * (float)CIN, 1e-5f);
        if (split == 0) mout[b*HW + y0*Ww + x0 + px] = mn;
    }

    float c[8][4];
    #pragma unroll
    for (int f = 0; f < 8; f++) { c[f][0]=0.f; c[f][1]=0.f; c[f][2]=0.f; c[f][3]=0.f; }

    for (int q = 0; q < CHUNKS; q++) {
        const int buf = q & 1;
        if (q + 1 < CHUNKS) {
            stage(q + 1, buf ^ 1);
            asm volatile("cp.async.wait_group 1;\n");
        } else {
            asm volatile("cp.async.wait_group 0;\n");
        }
        __syncthreads();

        const uint32_t* xb = xt + buf*XTSZ;
        const uint2* Ab = wsplit + (size_t)(split*CHUNKS + q)*72*CO_BLK + cb + g;
        #pragma unroll 3
        for (int t = 0; t < 9; t++) {
            const int ky = t/3, kx = t - 3*ky;
            const uint2* Ap = Ab + t*8*CO_BLK;
            uint2 A0 = __ldg(Ap + tig*CO_BLK);
            uint2 A1 = __ldg(Ap + tig*CO_BLK + 8);
            uint2 A2 = __ldg(Ap + (tig+4)*CO_BLK);
            uint2 A3 = __ldg(Ap + (tig+4)*CO_BLK + 8);
            const uint32_t* brow0 = &xb[(tig    *3 + ky)*WPX + pxb + kx*DIL + g];
            const uint32_t* brow1 = &xb[((tig+4)*3 + ky)*WPX + pxb + kx*DIL + g];
            #pragma unroll
            for (int f = 0; f < 8; f++) {
                uint32_t b0 = brow0[f*8];
                uint32_t b1 = brow1[f*8];
                mma16f(c[f], A0.x, A1.x, A2.x, A3.x, b0, b1);  // w_hi * x
                mma16f(c[f], A0.y, A1.y, A2.y, A3.y, b0, b1);  // w_lo * x
            }
        }
        __syncthreads();
    }

    // --- epilogue ---
    const int gco0 = co_base + cb + g;
    const int gco1 = gco0 + 8;
    const float b0v = bg[gco0], b1v = bg[gco1];
    float* rowp0 = yout + (size_t)(b*COUTT + gco0)*HW + y0*Ww + x0;
    float* rowp1 = yout + (size_t)(b*COUTT + gco1)*HW + y0*Ww + x0;
    float s0 = 0.f, q0 = 0.f, s1 = 0.f, q1 = 0.f;
    #pragma unroll
    for (int f = 0; f < 8; f++) {
        int pxl = pxb + f*8 + 2*tig;
        float i0 = invc[pxl], i1 = invc[pxl + 1];
        float y00 = fmaf(c[f][0], i0, b0v);
        float y01 = fmaf(c[f][1], i1, b0v);
        float y10 = fmaf(c[f][2], i0, b1v);
        float y11 = fmaf(c[f][3], i1, b1v);
        *(float2*)(rowp0 + pxl) = make_float2(y00, y01);
        *(float2*)(rowp1 + pxl) = make_float2(y10, y11);
        s0 += y00 + y01; q0 += y00*y00 + y01*y01;
        s1 += y10 + y11; q1 += y10*y10 + y11*y11;
    }
    #pragma unroll
    for (int o = 1; o <= 2; o <<= 1) {
        s0 += __shfl_xor_sync(0xffffffffu, s0, o);
        q0 += __shfl_xor_sync(0xffffffffu, q0, o);
        s1 += __shfl_xor_sync(0xffffffffu, s1, o);
        q1 += __shfl_xor_sync(0xffffffffu, q1, o);
    }
    if (tig == 0) {
        atomicAdd(&red[cb + g],              s0);
        atomicAdd(&red[CO_BLK + cb + g],     q0);
        atomicAdd(&red[cb + g + 8],          s1);
        atomicAdd(&red[CO_BLK + cb + g + 8], q1);
    }
    __syncthreads();
    if (tid < CO_BLK) {
        atomicAdd(&sums[co_base + tid],          red[tid]);
        atomicAdd(&sums[COUTT + co_base + tid],  red[CO_BLK + tid]);
    }
}

// ---------------------------------------------------------------------------
// final 1x1 conv 128 -> 64, fp16 asymmetric split, double-buffered
// ---------------------------------------------------------------------------
__global__ void __launch_bounds__(256, 3) conv1x1_mma_kernel(
    const uint32_t* __restrict__ xpk, const uint2* __restrict__ wsp1,
    const float* __restrict__ bg, float* __restrict__ out)
{
    constexpr int CO = 64, PXT = 128, WPX1 = 140, PLANES = 64;
    __shared__ uint32_t xt[2*8*WPX1];

    const int tid = threadIdx.x, lane = tid & 31, warp = tid >> 5;
    const int g = lane >> 2, tig = lane & 3;
    const int cog = warp >> 1, pxg = warp & 1;
    const int pxb = pxg * 64;
    const int tile = blockIdx.x;
    const int x0 = (tile & 1)*PXT, y0 = tile >> 1;
    const int b  = blockIdx.z;
    const uint32_t sx = (uint32_t)__cvta_generic_to_shared(xt);

    auto stage = [&](int q, int buf) {
        const int pr = warp;
        const uint32_t* s = xpk + (size_t)(b*PLANES + q*8 + pr)*HW + y0*Ww + x0;
        uint32_t dstb = sx + ((buf*8*WPX1 + pr*WPX1) << 2);
        #pragma unroll
        for (int k = 0; k < 4; k++) {
            int col = lane + k*32;
            cp_async4(dstb + (col << 2), s + col, 4);
        }
        asm volatile("cp.async.commit_group;\n");
    };

    float c[8][4];
    #pragma unroll
    for (int f = 0; f < 8; f++) { c[f][0]=0.f; c[f][1]=0.f; c[f][2]=0.f; c[f][3]=0.f; }

    stage(0, 0);
    for (int q = 0; q < 8; q++) {
        const int buf = q & 1;
        if (q + 1 < 8) {
            stage(q + 1, buf ^ 1);
            asm volatile("cp.async.wait_group 1;\n");
        } else {
            asm volatile("cp.async.wait_group 0;\n");
        }
        __syncthreads();

        const uint32_t* xb = xt + buf*8*WPX1;
        const uint2* Ap = wsp1 + q*512;
        uint2 a0 = __ldg(Ap + tig*64 + cog*16 + g);
        uint2 a1 = __ldg(Ap + tig*64 + cog*16 + g + 8);
        uint2 a2 = __ldg(Ap + (tig+4)*64 + cog*16 + g);
        uint2 a3 = __ldg(Ap + (tig+4)*64 + cog*16 + g + 8);
        #pragma unroll
        for (int f = 0; f < 8; f++) {
            uint32_t b0 = xb[tig    *WPX1 + pxb + f*8 + g];
            uint32_t b1 = xb[(tig+4)*WPX1 + pxb + f*8 + g];
            mma16f(c[f], a0.x, a1.x, a2.x, a3.x, b0, b1);
            mma16f(c[f], a0.y, a1.y, a2.y, a3.y, b0, b1);
        }
        __syncthreads();
    }
    const int co0 = cog*16 + g, co1 = co0 + 8;
    const float b0v = bg[co0], b1v = bg[co1];
    float* r0 = out + (size_t)(b*CO + co0)*HW + y0*Ww + x0;
    float* r1 = out + (size_t)(b*CO + co1)*HW + y0*Ww + x0;
    #pragma unroll
    for (int f = 0; f < 8; f++) {
        int pxl = pxb + f*8 + 2*tig;
        *(float2*)(r0 + pxl) = make_float2(c[f][0] + b0v, c[f][1] + b0v);
        *(float2*)(r1 + pxl) = make_float2(c[f][2] + b1v, c[f][3] + b1v);
    }
}

// ---------------------------------------------------------------------------
extern "C" void kernel_launch(void* const* d_in, const int* in_sizes, int n_in,
                              void* d_out, int out_size)
{
    const float* feat = (const float*)d_in[0];
    const float* mask = (const float*)d_in[1];
    const float* Wl[5]; const float* bl[5]; const float* gl[5]; const float* bel[5];
    for (int l = 0; l < 5; l++) {
        Wl[l]  = (const float*)d_in[2 + 4*l];
        bl[l]  = (const float*)d_in[3 + 4*l];
        gl[l]  = (const float*)d_in[4 + 4*l];
        bel[l] = (const float*)d_in[5 + 4*l];
    }
    const float* Wf = (const float*)d_in[22];
    const float* bf = (const float*)d_in[23];

    float *bufA, *bufB, *mA, *mB, *sumsG;
    uint32_t* P;
    uint2* wsp;
    cudaGetSymbolAddress((void**)&bufA, g_bufA);
    cudaGetSymbolAddress((void**)&bufB, g_bufB);
    cudaGetSymbolAddress((void**)&P,    g_bufP);
    cudaGetSymbolAddress((void**)&mA,   g_maskA);
    cudaGetSymbolAddress((void**)&mB,   g_maskB);
    cudaGetSymbolAddress((void**)&sumsG, g_sums);
    cudaGetSymbolAddress((void**)&wsp,  g_wsplit);
    float* su0 = sumsG;         // ping
    float* su1 = sumsG + 256;   // pong

    // weight tables (uint2 offsets)
    const int off0 = 0, off1 = 2304, off2 = 4608, off3 = 13824, off4 = 32256;
    const int off1x1 = 69120;
    presplit3x3_all<<<270, 256>>>(Wl[0], Wl[1], Wl[2], Wl[3], Wl[4], wsp);
    presplit1x1_kernel<<<16, 256>>>(Wf, wsp+off1x1);

    // smem sizes
    const int smem_L0 = 2*24*268*4 + 3*268*4 + 256*4 + 2*16*4 + 16;
    const int smem_L1 = 2*24*268*4 + 3*268*4 + 256*4 + 2*32*4 + 16;
    const int smem_Lx = 2*24*140*4 + 3*140*4 + 128*4 + 2*64*4 + 16;
    const int smem_L4 = 2*24*76*4  + 3*76*4  + 64*4  + 2*128*4 + 16;

    auto k0 = conv_mma_kernel<32,16,1,1,256,4>;
    auto k1 = conv_mma_kernel<16,32,1,2,256,8>;
    auto k2 = conv_mma_kernel<32,64,1,1,128,8>;
    auto k3 = conv_mma_kernel<64,64,1,2,128,8>;
    auto k4 = conv_mma_kernel<64,128,1,1,64,8>;     // single-pass, CO=128, PXT=64
    cudaFuncSetAttribute(k0, cudaFuncAttributeMaxDynamicSharedMemorySize, smem_L0);
    cudaFuncSetAttribute(k1, cudaFuncAttributeMaxDynamicSharedMemorySize, smem_L1);
    cudaFuncSetAttribute(k2, cudaFuncAttributeMaxDynamicSharedMemorySize, smem_Lx);
    cudaFuncSetAttribute(k3, cudaFuncAttributeMaxDynamicSharedMemorySize, smem_Lx);
    cudaFuncSetAttribute(k4, cudaFuncAttributeMaxDynamicSharedMemorySize, smem_L4);

    auto TFM  = transform_kernel<true,  true >;
    auto TF0  = transform_kernel<false, true >;
    auto TFNM = transform_kernel<true,  false>;
    #define TGRID(C) ((C)*256)   // exact: C*65536 uint4 / 256 threads

    // input transform: feat*mask -> packed; zeroes su0 for L0
    TF0<<<TGRID(32), 256>>>(feat, mask, nullptr, nullptr, nullptr, su0, P, 32, 32*65536);

    // L0: 32 -> 16, d=1  (sums -> su0)
    k0<<<dim3(256,1,8), 128, smem_L0>>>(P, mask, wsp+off0, bl[0], bufA, mA, su0);
    TFM<<<TGRID(16), 256>>>(bufA, mA, su0, gl[0], bel[0], su1, P, 16, 16*65536);

    // L1: 16 -> 32, d=2  (sums -> su1)
    k1<<<dim3(256,1,8), 256, smem_L1>>>(P, mA, wsp+off1, bl[1], bufB, mB, su1);
    TFM<<<TGRID(32), 256>>>(bufB, mB, su1, gl[1], bel[1], su0, P, 32, 32*65536);

    // L2: 32 -> 64, d=1  (sums -> su0)
    k2<<<dim3(512,1,8), 256, smem_Lx>>>(P, mB, wsp+off2, bl[2], bufA, mA, su0);
    TFM<<<TGRID(64), 256>>>(bufA, mA, su0, gl[2], bel[2], su1, P, 64, 64*65536);

    // L3: 64 -> 64, d=2  (sums -> su1)
    k3<<<dim3(512,1,8), 256, smem_Lx>>>(P, mA, wsp+off3, bl[3], bufB, mB, su1);
    TFM<<<TGRID(64), 256>>>(bufB, mB, su1, gl[3], bel[3], su0, P, 64, 64*65536);

    // L4: 64 -> 128, d=1, single pass (sums -> su0)
    k4<<<dim3(1024,1,8), 256, smem_L4>>>(P, mB, wsp+off4, bl[4], bufA, mA, su0);
    TFNM<<<TGRID(128), 256>>>(bufA, nullptr, su0, gl[4], bel[4], nullptr, P, 128, 128*65536);

    // final 1x1 conv
    conv1x1_mma_kernel<<<dim3(512,1,8), 256>>>(P, wsp+off1x1, bf, (float*)d_out);

    // final mask
    const int xelems = Bb*64*HW;
    const int melems = Bb*HW;
    if (out_size >= xelems + melems) {
        cudaMemcpyAsync((float*)d_out + xelems, mA, (size_t)melems*sizeof(float),
                        cudaMemcpyDeviceToDevice);
    }
}

// round 11
// speedup vs baseline: 4.9526x; 1.0613x over previous
#include <cuda_runtime.h>
#include <cuda_fp16.h>
#include <cstdint>

#define Hh 256
#define Ww 256
#define Bb 8
#define HW 65536
#define NPIX (Bb*HW)   // 524288

// Scratch (device globals — no allocation allowed)
__device__ float    g_bufA[(size_t)Bb*128*HW];
__device__ float    g_bufB[(size_t)Bb*128*HW];
__device__ uint32_t g_bufP[(size_t)Bb*64*HW];    // packed fp16 x (2 ci per word)
__device__ float    g_maskA[(size_t)Bb*HW];
__device__ float    g_maskB[(size_t)Bb*HW];
__device__ float    g_sums[512];                 // two ping-pong buffers of 256
__device__ uint2    g_wsplit[100000];            // fp16 (hi,lo) weight pair words

// ---------------------------------------------------------------------------
// helpers
// ---------------------------------------------------------------------------
__device__ __forceinline__ uint32_t pack2_f16(float a, float b) {
    __half2 h = __floats2half2_rn(a, b);
    return *reinterpret_cast<uint32_t*>(&h);
}
__device__ __forceinline__ void mma16f(float* c,
                                       uint32_t a0, uint32_t a1, uint32_t a2, uint32_t a3,
                                       uint32_t b0, uint32_t b1) {
    asm volatile(
        "mma.sync.aligned.m16n8k16.row.col.f32.f16.f16.f32 "
        "{%0,%1,%2,%3},{%4,%5,%6,%7},{%8,%9},{%0,%1,%2,%3};"
        : "+f"(c[0]), "+f"(c[1]), "+f"(c[2]), "+f"(c[3])
        : "r"(a0), "r"(a1), "r"(a2), "r"(a3), "r"(b0), "r"(b1));
}
__device__ __forceinline__ void cp_async16(uint32_t dst_smem, const void* src, int src_size) {
    asm volatile("cp.async.cg.shared.global [%0],[%1],16,%2;\n"
                 :: "r"(dst_smem), "l"(src), "r"(src_size));
}
__device__ __forceinline__ uint2 wpair(float v0, float v1) {
    __half h0 = __float2half_rn(v0), h1 = __float2half_rn(v1);
    __half l0 = __float2half_rn(v0 - __half2float(h0));
    __half l1 = __float2half_rn(v1 - __half2float(h1));
    __half2 HH = __halves2half2(h0, h1), LL = __halves2half2(l0, l1);
    return make_uint2(*reinterpret_cast<uint32_t*>(&HH), *reinterpret_cast<uint32_t*>(&LL));
}

// ---------------------------------------------------------------------------
// Weight pre-split, ALL 3x3 layers in one launch.
// ---------------------------------------------------------------------------
__device__ __forceinline__ void presplit_one(const float* W, uint2* dst,
                                             int CIN, int CO_BLK, int i)
{
    int co   = i % CO_BLK;
    int pr   = (i / CO_BLK) & 7;
    int t    = (i / (CO_BLK*8)) % 9;
    int rest = i / (CO_BLK*72);
    int chunks = CIN >> 4;
    int q = rest % chunks;
    int s = rest / chunks;
    int ci = q*16 + 2*pr;
    const float* wb = W + ((size_t)(s*CO_BLK + co)*CIN + ci)*9 + t;
    dst[i] = wpair(wb[0], wb[9]);
}
__global__ void presplit3x3_all(const float* __restrict__ W0, const float* __restrict__ W1,
                                const float* __restrict__ W2, const float* __restrict__ W3,
                                const float* __restrict__ W4, uint2* __restrict__ dst)
{
    int j = blockIdx.x*256 + threadIdx.x;
    if (j >= 69120) return;
    if      (j < 2304)  presplit_one(W0, dst,          32, 16,  j);
    else if (j < 4608)  presplit_one(W1, dst + 2304,   16, 32,  j - 2304);
    else if (j < 13824) presplit_one(W2, dst + 4608,   32, 64,  j - 4608);
    else if (j < 32256) presplit_one(W3, dst + 13824,  64, 64,  j - 13824);
    else                presplit_one(W4, dst + 32256,  64, 128, j - 32256);
}
__global__ void presplit1x1_kernel(const float* __restrict__ W, uint2* __restrict__ dst)
{
    int i = blockIdx.x*256 + threadIdx.x;
    if (i >= 4096) return;
    int co = i & 63, pr = (i >> 6) & 7, q = i >> 9;
    int ci = q*16 + 2*pr;
    dst[i] = wpair(W[co*128 + ci], W[co*128 + ci + 1]);
}

// ---------------------------------------------------------------------------
// Activation transform + fused BN-stats finalization + next-sums zeroing.
// ---------------------------------------------------------------------------
template<bool BN, bool MASKED>
__global__ void transform_kernel(const float* __restrict__ y,
                                 const float* __restrict__ m,
                                 const float* __restrict__ sums,
                                 const float* __restrict__ gam,
                                 const float* __restrict__ bet,
                                 float* __restrict__ sums_next,
                                 uint32_t* __restrict__ out, int C, int n4)
{
    __shared__ float ssm[256];
    const int tid = threadIdx.x;
    if (BN) {
        if (tid < C) {
            const float invN = 1.f / (float)NPIX;
            float mean = sums[tid] * invN;
            float var  = sums[C + tid] * invN - mean*mean;
            float sc = gam[tid] * rsqrtf(var + 1e-5f);
            ssm[tid]     = sc;
            ssm[C + tid] = fmaf(-mean, sc, bet[tid]);
        }
        __syncthreads();
    }
    if (blockIdx.x == 0 && sums_next != nullptr && tid < 256) sums_next[tid] = 0.f;

    int i = blockIdx.x*256 + tid;
    if (i >= n4) return;
    int plane = i >> 14;
    int half = C >> 1;
    int pp = plane % half;
    int b  = plane / half;
    int c0 = pp*2;
    float sc0 = 1.f, sh0 = 0.f, sc1 = 1.f, sh1 = 0.f;
    if (BN) { sc0 = ssm[c0]; sh0 = ssm[C + c0]; sc1 = ssm[c0+1]; sh1 = ssm[C + c0 + 1]; }
    int px4 = i & 16383;
    float4 v0 = ((const float4*)y)[(((size_t)b*C + c0    ) << 14) + px4];
    float4 v1 = ((const float4*)y)[(((size_t)b*C + c0 + 1) << 14) + px4];
    float4 mk = make_float4(1.f,1.f,1.f,1.f);
    if (MASKED) mk = ((const float4*)m)[(((size_t)b) << 14) + px4];
    const float* p0 = &v0.x; const float* p1 = &v1.x; const float* pm = &mk.x;
    uint32_t r[4];
    #pragma unroll
    for (int k = 0; k < 4; k++) {
        float a = p0[k], c = p1[k];
        if (BN) {
            a = fmaf(a, sc0, sh0); a = a >= 0.f ? a : 0.01f*a;
            c = fmaf(c, sc1, sh1); c = c >= 0.f ? c : 0.01f*c;
        }
        if (MASKED) { a *= pm[k]; c *= pm[k]; }
        r[k] = pack2_f16(a, c);
    }
    ((uint4*)out)[i] = make_uint4(r[0], r[1], r[2], r[3]);
}

// ---------------------------------------------------------------------------
// Fused sparse-conv block, fp16 asymmetric-split MMA, double-buffered 16B
// cp.async staging (window widened to [x0-4, x0+PXT+4) so every 16B chunk is
// all-in or all-out of bounds -> single cp.async.cg 16 with zero-fill).
// ---------------------------------------------------------------------------
template<int CIN, int CO_BLK, int NSPLIT, int DIL, int PXT, int WARPS>
__global__ void __launch_bounds__(WARPS*32, 3) conv_mma_kernel(
    const uint32_t* __restrict__ xpk, const float* __restrict__ min_,
    const uint2* __restrict__ wsplit, const float* __restrict__ bg,
    float* __restrict__ yout, float* __restrict__ mout,
    float* __restrict__ sums)
{
    constexpr int NT    = WARPS*32;
    constexpr int PXG   = WARPS*16/CO_BLK;
    constexpr int XW    = PXT + 2*DIL;          // mask window (start x0-DIL)
    constexpr int WPX   = PXT + 12;             // padded row stride (mult of 4)
    constexpr int NCH   = (PXT + 8) / 4;        // 16B chunks per x row
    constexpr int XTSZ  = 24*WPX;
    constexpr int COUTT = CO_BLK*NSPLIT;
    constexpr int TX    = 256/PXT;
    constexpr int CHUNKS = CIN/16;
    constexpr int PLANES = CIN/2;

    extern __shared__ char dsm[];
    uint32_t* xt  = (uint32_t*)dsm;             // [2][24][WPX], window start x0-4
    float*  msk = (float*)(xt + 2*XTSZ);        // [3][WPX]
    float*  invc= msk + 3*WPX;                  // [PXT]
    float*  red = invc + PXT;                   // [2*CO_BLK]

    const int tid  = threadIdx.x;
    const int lane = tid & 31, warp = tid >> 5;
    const int g    = lane >> 2, tig = lane & 3;
    const int cog  = warp / PXG, pxg = warp % PXG;
    const int pxb  = pxg * 64;
    const int cb   = cog * 16;
    const uint32_t sx = (uint32_t)__cvta_generic_to_shared(xt);

    const int tile = blockIdx.x;
    const int x0 = (tile % TX) * PXT;
    const int y0 = tile / TX;
    const int z  = blockIdx.z;
    const int b  = z / NSPLIT;
    const int split = z % NSPLIT;
    const int co_base = split * CO_BLK;

    // --- stage mask rows (window start x0-DIL as before) ---
    for (int i = tid; i < 3*XW; i += NT) {
        int col = i % XW, r = i / XW;
        int gy = y0 + (r-1)*DIL, gx = x0 - DIL + col;
        float v = 0.f;
        if (gy >= 0 && gy < Hh && gx >= 0 && gx < Ww) v = min_[b*HW + gy*Ww + gx];
        msk[r*WPX + col] = v;
    }
    for (int i = tid; i < 2*CO_BLK; i += NT) red[i] = 0.f;

    // 16B vector staging: chunk ch covers gx = x0-4+4ch .. +3 (all-or-nothing OOB)
    auto stage = [&](int q, int buf) {
        for (int pr = warp; pr < 8; pr += WARPS) {
            const uint32_t* srcp = xpk + (size_t)(b*PLANES + q*8 + pr)*HW;
            #pragma unroll
            for (int r = 0; r < 3; r++) {
                int gy = y0 + (r-1)*DIL;
                bool rowok = ((unsigned)gy < (unsigned)Hh);
                const uint32_t* srow = srcp + (rowok ? gy*Ww : 0);
                uint32_t dstb = sx + ((buf*XTSZ + (pr*3 + r)*WPX) << 2);
                #pragma unroll
                for (int ch = lane; ch < NCH; ch += 32) {
                    int gx = x0 - 4 + ch*4;
                    bool ok = rowok && (gx >= 0) && (gx < Ww);
                    cp_async16(dstb + (ch << 4), srow + (ok ? gx : 0), ok ? 16 : 0);
                }
            }
        }
        asm volatile("cp.async.commit_group;\n");
    };

    stage(0, 0);
    __syncthreads();

    // --- per-pixel 1/count + mask maxpool (overlaps chunk-0 arrival) ---
    for (int px = tid; px < PXT; px += NT) {
        float cnt = 0.f, mn = 0.f;
        #pragma unroll
        for (int ky = 0; ky < 3; ky++)
            #pragma unroll
            for (int kx = 0; kx < 3; kx++) {
                float v = msk[ky*WPX + px + kx*DIL];
                cnt += v; mn = fmaxf(mn, v);
            }
        invc[px] = 1.f / fmaxf(cnt * (float)CIN, 1e-5f);
        if (split == 0) mout[b*HW + y0*Ww + x0 + px] = mn;
    }

    float c[8][4];
    #pragma unroll
    for (int f = 0; f < 8; f++) { c[f][0]=0.f; c[f][1]=0.f; c[f][2]=0.f; c[f][3]=0.f; }

    for (int q = 0; q < CHUNKS; q++) {
        const int buf = q & 1;
        if (q + 1 < CHUNKS) {
            stage(q + 1, buf ^ 1);
            asm volatile("cp.async.wait_group 1;\n");
        } else {
            asm volatile("cp.async.wait_group 0;\n");
        }
        __syncthreads();

        const uint32_t* xb = xt + buf*XTSZ;
        const uint2* Ab = wsplit + (size_t)(split*CHUNKS + q)*72*CO_BLK + cb + g;
        #pragma unroll 3
        for (int t = 0; t < 9; t++) {
            const int ky = t/3, kx = t - 3*ky;
            const int xoff = (kx-1)*DIL + 4;        // window-start shift
            const uint2* Ap = Ab + t*8*CO_BLK;
            uint2 A0 = __ldg(Ap + tig*CO_BLK);
            uint2 A1 = __ldg(Ap + tig*CO_BLK + 8);
            uint2 A2 = __ldg(Ap + (tig+4)*CO_BLK);
            uint2 A3 = __ldg(Ap + (tig+4)*CO_BLK + 8);
            const uint32_t* brow0 = &xb[(tig    *3 + ky)*WPX + pxb + xoff + g];
            const uint32_t* brow1 = &xb[((tig+4)*3 + ky)*WPX + pxb + xoff + g];
            #pragma unroll
            for (int f = 0; f < 8; f++) {
                uint32_t b0 = brow0[f*8];
                uint32_t b1 = brow1[f*8];
                mma16f(c[f], A0.x, A1.x, A2.x, A3.x, b0, b1);  // w_hi * x
                mma16f(c[f], A0.y, A1.y, A2.y, A3.y, b0, b1);  // w_lo * x
            }
        }
        __syncthreads();
    }

    // --- epilogue ---
    const int gco0 = co_base + cb + g;
    const int gco1 = gco0 + 8;
    const float b0v = bg[gco0], b1v = bg[gco1];
    float* rowp0 = yout + (size_t)(b*COUTT + gco0)*HW + y0*Ww + x0;
    float* rowp1 = yout + (size_t)(b*COUTT + gco1)*HW + y0*Ww + x0;
    float s0 = 0.f, q0 = 0.f, s1 = 0.f, q1 = 0.f;
    #pragma unroll
    for (int f = 0; f < 8; f++) {
        int pxl = pxb + f*8 + 2*tig;
        float i0 = invc[pxl], i1 = invc[pxl + 1];
        float y00 = fmaf(c[f][0], i0, b0v);
        float y01 = fmaf(c[f][1], i1, b0v);
        float y10 = fmaf(c[f][2], i0, b1v);
        float y11 = fmaf(c[f][3], i1, b1v);
        *(float2*)(rowp0 + pxl) = make_float2(y00, y01);
        *(float2*)(rowp1 + pxl) = make_float2(y10, y11);
        s0 += y00 + y01; q0 += y00*y00 + y01*y01;
        s1 += y10 + y11; q1 += y10*y10 + y11*y11;
    }
    #pragma unroll
    for (int o = 1; o <= 2; o <<= 1) {
        s0 += __shfl_xor_sync(0xffffffffu, s0, o);
        q0 += __shfl_xor_sync(0xffffffffu, q0, o);
        s1 += __shfl_xor_sync(0xffffffffu, s1, o);
        q1 += __shfl_xor_sync(0xffffffffu, q1, o);
    }
    if (tig == 0) {
        atomicAdd(&red[cb + g],              s0);
        atomicAdd(&red[CO_BLK + cb + g],     q0);
        atomicAdd(&red[cb + g + 8],          s1);
        atomicAdd(&red[CO_BLK + cb + g + 8], q1);
    }
    __syncthreads();
    if (tid < CO_BLK) {
        atomicAdd(&sums[co_base + tid],          red[tid]);
        atomicAdd(&sums[COUTT + co_base + tid],  red[CO_BLK + tid]);
    }
}

// ---------------------------------------------------------------------------
// final 1x1 conv 128 -> 64, fp16 asymmetric split, 16B double-buffered staging
// ---------------------------------------------------------------------------
__global__ void __launch_bounds__(256, 3) conv1x1_mma_kernel(
    const uint32_t* __restrict__ xpk, const uint2* __restrict__ wsp1,
    const float* __restrict__ bg, float* __restrict__ out)
{
    constexpr int CO = 64, PXT = 128, WPX1 = 140, PLANES = 64;
    __shared__ uint32_t xt[2*8*WPX1];

    const int tid = threadIdx.x, lane = tid & 31, warp = tid >> 5;
    const int g = lane >> 2, tig = lane & 3;
    const int cog = warp >> 1, pxg = warp & 1;
    const int pxb = pxg * 64;
    const int tile = blockIdx.x;
    const int x0 = (tile & 1)*PXT, y0 = tile >> 1;
    const int b  = blockIdx.z;
    const uint32_t sx = (uint32_t)__cvta_generic_to_shared(xt);

    auto stage = [&](int q, int buf) {
        const int pr = warp;
        const uint32_t* s = xpk + (size_t)(b*PLANES + q*8 + pr)*HW + y0*Ww + x0;
        uint32_t dstb = sx + ((buf*8*WPX1 + pr*WPX1) << 2);
        cp_async16(dstb + (lane << 4), s + lane*4, 16);
        asm volatile("cp.async.commit_group;\n");
    };

    float c[8][4];
    #pragma unroll
    for (int f = 0; f < 8; f++) { c[f][0]=0.f; c[f][1]=0.f; c[f][2]=0.f; c[f][3]=0.f; }

    stage(0, 0);
    for (int q = 0; q < 8; q++) {
        const int buf = q & 1;
        if (q + 1 < 8) {
            stage(q + 1, buf ^ 1);
            asm volatile("cp.async.wait_group 1;\n");
        } else {
            asm volatile("cp.async.wait_group 0;\n");
        }
        __syncthreads();

        const uint32_t* xb = xt + buf*8*WPX1;
        const uint2* Ap = wsp1 + q*512;
        uint2 a0 = __ldg(Ap + tig*64 + cog*16 + g);
        uint2 a1 = __ldg(Ap + tig*64 + cog*16 + g + 8);
        uint2 a2 = __ldg(Ap + (tig+4)*64 + cog*16 + g);
        uint2 a3 = __ldg(Ap + (tig+4)*64 + cog*16 + g + 8);
        #pragma unroll
        for (int f = 0; f < 8; f++) {
            uint32_t b0 = xb[tig    *WPX1 + pxb + f*8 + g];
            uint32_t b1 = xb[(tig+4)*WPX1 + pxb + f*8 + g];
            mma16f(c[f], a0.x, a1.x, a2.x, a3.x, b0, b1);
            mma16f(c[f], a0.y, a1.y, a2.y, a3.y, b0, b1);
        }
        __syncthreads();
    }
    const int co0 = cog*16 + g, co1 = co0 + 8;
    const float b0v = bg[co0], b1v = bg[co1];
    float* r0 = out + (size_t)(b*CO + co0)*HW + y0*Ww + x0;
    float* r1 = out + (size_t)(b*CO + co1)*HW + y0*Ww + x0;
    #pragma unroll
    for (int f = 0; f < 8; f++) {
        int pxl = pxb + f*8 + 2*tig;
        *(float2*)(r0 + pxl) = make_float2(c[f][0] + b0v, c[f][1] + b0v);
        *(float2*)(r1 + pxl) = make_float2(c[f][2] + b1v, c[f][3] + b1v);
    }
}

// ---------------------------------------------------------------------------
extern "C" void kernel_launch(void* const* d_in, const int* in_sizes, int n_in,
                              void* d_out, int out_size)
{
    const float* feat = (const float*)d_in[0];
    const float* mask = (const float*)d_in[1];
    const float* Wl[5]; const float* bl[5]; const float* gl[5]; const float* bel[5];
    for (int l = 0; l < 5; l++) {
        Wl[l]  = (const float*)d_in[2 + 4*l];
        bl[l]  = (const float*)d_in[3 + 4*l];
        gl[l]  = (const float*)d_in[4 + 4*l];
        bel[l] = (const float*)d_in[5 + 4*l];
    }
    const float* Wf = (const float*)d_in[22];
    const float* bf = (const float*)d_in[23];

    float *bufA, *bufB, *mA, *mB, *sumsG;
    uint32_t* P;
    uint2* wsp;
    cudaGetSymbolAddress((void**)&bufA, g_bufA);
    cudaGetSymbolAddress((void**)&bufB, g_bufB);
    cudaGetSymbolAddress((void**)&P,    g_bufP);
    cudaGetSymbolAddress((void**)&mA,   g_maskA);
    cudaGetSymbolAddress((void**)&mB,   g_maskB);
    cudaGetSymbolAddress((void**)&sumsG, g_sums);
    cudaGetSymbolAddress((void**)&wsp,  g_wsplit);
    float* su0 = sumsG;
    float* su1 = sumsG + 256;

    const int off0 = 0, off1 = 2304, off2 = 4608, off3 = 13824, off4 = 32256;
    const int off1x1 = 69120;
    presplit3x3_all<<<270, 256>>>(Wl[0], Wl[1], Wl[2], Wl[3], Wl[4], wsp);
    presplit1x1_kernel<<<16, 256>>>(Wf, wsp+off1x1);

    const int smem_L0 = 2*24*268*4 + 3*268*4 + 256*4 + 2*16*4 + 16;
    const int smem_L1 = 2*24*268*4 + 3*268*4 + 256*4 + 2*32*4 + 16;
    const int smem_Lx = 2*24*140*4 + 3*140*4 + 128*4 + 2*64*4 + 16;
    const int smem_L4 = 2*24*76*4  + 3*76*4  + 64*4  + 2*128*4 + 16;

    auto k0 = conv_mma_kernel<32,16,1,1,256,4>;
    auto k1 = conv_mma_kernel<16,32,1,2,256,8>;
    auto k2 = conv_mma_kernel<32,64,1,1,128,8>;
    auto k3 = conv_mma_kernel<64,64,1,2,128,8>;
    auto k4 = conv_mma_kernel<64,128,1,1,64,8>;
    cudaFuncSetAttribute(k0, cudaFuncAttributeMaxDynamicSharedMemorySize, smem_L0);
    cudaFuncSetAttribute(k1, cudaFuncAttributeMaxDynamicSharedMemorySize, smem_L1);
    cudaFuncSetAttribute(k2, cudaFuncAttributeMaxDynamicSharedMemorySize, smem_Lx);
    cudaFuncSetAttribute(k3, cudaFuncAttributeMaxDynamicSharedMemorySize, smem_Lx);
    cudaFuncSetAttribute(k4, cudaFuncAttributeMaxDynamicSharedMemorySize, smem_L4);

    auto TFM  = transform_kernel<true,  true >;
    auto TF0  = transform_kernel<false, true >;
    auto TFNM = transform_kernel<true,  false>;
    #define TGRID(C) ((C)*256)

    // input transform: feat*mask -> packed; zeroes su0 for L0
    TF0<<<TGRID(32), 256>>>(feat, mask, nullptr, nullptr, nullptr, su0, P, 32, 32*65536);

    // L0: 32 -> 16, d=1
    k0<<<dim3(256,1,8), 128, smem_L0>>>(P, mask, wsp+off0, bl[0], bufA, mA, su0);
    TFM<<<TGRID(16), 256>>>(bufA, mA, su0, gl[0], bel[0], su1, P, 16, 16*65536);

    // L1: 16 -> 32, d=2
    k1<<<dim3(256,1,8), 256, smem_L1>>>(P, mA, wsp+off1, bl[1], bufB, mB, su1);
    TFM<<<TGRID(32), 256>>>(bufB, mB, su1, gl[1], bel[1], su0, P, 32, 32*65536);

    // L2: 32 -> 64, d=1
    k2<<<dim3(512,1,8), 256, smem_Lx>>>(P, mB, wsp+off2, bl[2], bufA, mA, su0);
    TFM<<<TGRID(64), 256>>>(bufA, mA, su0, gl[2], bel[2], su1, P, 64, 64*65536);

    // L3: 64 -> 64, d=2
    k3<<<dim3(512,1,8), 256, smem_Lx>>>(P, mA, wsp+off3, bl[3], bufB, mB, su1);
    TFM<<<TGRID(64), 256>>>(bufB, mB, su1, gl[3], bel[3], su0, P, 64, 64*65536);

    // L4: 64 -> 128, d=1, single pass
    k4<<<dim3(1024,1,8), 256, smem_L4>>>(P, mB, wsp+off4, bl[4], bufA, mA, su0);
    TFNM<<<TGRID(128), 256>>>(bufA, nullptr, su0, gl[4], bel[4], nullptr, P, 128, 128*65536);

    // final 1x1 conv
    conv1x1_mma_kernel<<<dim3(512,1,8), 256>>>(P, wsp+off1x1, bf, (float*)d_out);

    // final mask
    const int xelems = Bb*64*HW;
    const int melems = Bb*HW;
    if (out_size >= xelems + melems) {
        cudaMemcpyAsync((float*)d_out + xelems, mA, (size_t)melems*sizeof(float),
                        cudaMemcpyDeviceToDevice);
    }
}

// round 12
// speedup vs baseline: 5.4051x; 1.0914x over previous
#include <cuda_runtime.h>
#include <cuda_fp16.h>
#include <cstdint>

#define Hh 256
#define Ww 256
#define Bb 8
#define HW 65536
#define NPIX (Bb*HW)   // 524288

// Scratch (device globals — no allocation allowed)
__device__ float    g_bufA[(size_t)Bb*128*HW];
__device__ float    g_bufB[(size_t)Bb*128*HW];
__device__ uint32_t g_bufP[(size_t)Bb*64*HW];    // packed fp16 x (2 ci per word)
__device__ float    g_maskA[(size_t)Bb*HW];
__device__ float    g_maskB[(size_t)Bb*HW];
__device__ float    g_sums[512];                 // two ping-pong buffers of 256
__device__ uint2    g_wsplit[100000];            // fp16 (hi,lo) weight pair words

// ---------------------------------------------------------------------------
// helpers
// ---------------------------------------------------------------------------
__device__ __forceinline__ uint32_t pack2_f16(float a, float b) {
    __half2 h = __floats2half2_rn(a, b);
    return *reinterpret_cast<uint32_t*>(&h);
}
__device__ __forceinline__ void mma16f(float* c,
                                       uint32_t a0, uint32_t a1, uint32_t a2, uint32_t a3,
                                       uint32_t b0, uint32_t b1) {
    asm volatile(
        "mma.sync.aligned.m16n8k16.row.col.f32.f16.f16.f32 "
        "{%0,%1,%2,%3},{%4,%5,%6,%7},{%8,%9},{%0,%1,%2,%3};"
        : "+f"(c[0]), "+f"(c[1]), "+f"(c[2]), "+f"(c[3])
        : "r"(a0), "r"(a1), "r"(a2), "r"(a3), "r"(b0), "r"(b1));
}
__device__ __forceinline__ void cp_async16(uint32_t dst_smem, const void* src, int src_size) {
    asm volatile("cp.async.cg.shared.global [%0],[%1],16,%2;\n"
                 :: "r"(dst_smem), "l"(src), "r"(src_size));
}
__device__ __forceinline__ uint2 wpair(float v0, float v1) {
    __half h0 = __float2half_rn(v0), h1 = __float2half_rn(v1);
    __half l0 = __float2half_rn(v0 - __half2float(h0));
    __half l1 = __float2half_rn(v1 - __half2float(h1));
    __half2 HH = __halves2half2(h0, h1), LL = __halves2half2(l0, l1);
    return make_uint2(*reinterpret_cast<uint32_t*>(&HH), *reinterpret_cast<uint32_t*>(&LL));
}

// ---------------------------------------------------------------------------
// Weight pre-split, ALL 3x3 layers in one launch.
// ---------------------------------------------------------------------------
__device__ __forceinline__ void presplit_one(const float* W, uint2* dst,
                                             int CIN, int CO_BLK, int i)
{
    int co   = i % CO_BLK;
    int pr   = (i / CO_BLK) & 7;
    int t    = (i / (CO_BLK*8)) % 9;
    int rest = i / (CO_BLK*72);
    int chunks = CIN >> 4;
    int q = rest % chunks;
    int s = rest / chunks;
    int ci = q*16 + 2*pr;
    const float* wb = W + ((size_t)(s*CO_BLK + co)*CIN + ci)*9 + t;
    dst[i] = wpair(wb[0], wb[9]);
}
__global__ void presplit3x3_all(const float* __restrict__ W0, const float* __restrict__ W1,
                                const float* __restrict__ W2, const float* __restrict__ W3,
                                const float* __restrict__ W4, uint2* __restrict__ dst)
{
    int j = blockIdx.x*256 + threadIdx.x;
    if (j >= 69120) return;
    if      (j < 2304)  presplit_one(W0, dst,          32, 16,  j);
    else if (j < 4608)  presplit_one(W1, dst + 2304,   16, 32,  j - 2304);
    else if (j < 13824) presplit_one(W2, dst + 4608,   32, 64,  j - 4608);
    else if (j < 32256) presplit_one(W3, dst + 13824,  64, 64,  j - 13824);
    else                presplit_one(W4, dst + 32256,  64, 128, j - 32256);
}
__global__ void presplit1x1_kernel(const float* __restrict__ W, uint2* __restrict__ dst)
{
    int i = blockIdx.x*256 + threadIdx.x;
    if (i >= 4096) return;
    int co = i & 63, pr = (i >> 6) & 7, q = i >> 9;
    int ci = q*16 + 2*pr;
    dst[i] = wpair(W[co*128 + ci], W[co*128 + ci + 1]);
}

// ---------------------------------------------------------------------------
// Activation transform + fused BN-stats finalization + next-sums zeroing.
// ---------------------------------------------------------------------------
template<bool BN, bool MASKED>
__global__ void transform_kernel(const float* __restrict__ y,
                                 const float* __restrict__ m,
                                 const float* __restrict__ sums,
                                 const float* __restrict__ gam,
                                 const float* __restrict__ bet,
                                 float* __restrict__ sums_next,
                                 uint32_t* __restrict__ out, int C, int n4)
{
    __shared__ float ssm[256];
    const int tid = threadIdx.x;
    if (BN) {
        if (tid < C) {
            const float invN = 1.f / (float)NPIX;
            float mean = sums[tid] * invN;
            float var  = sums[C + tid] * invN - mean*mean;
            float sc = gam[tid] * rsqrtf(var + 1e-5f);
            ssm[tid]     = sc;
            ssm[C + tid] = fmaf(-mean, sc, bet[tid]);
        }
        __syncthreads();
    }
    if (blockIdx.x == 0 && sums_next != nullptr && tid < 256) sums_next[tid] = 0.f;

    int i = blockIdx.x*256 + tid;
    if (i >= n4) return;
    int plane = i >> 14;
    int half = C >> 1;
    int pp = plane % half;
    int b  = plane / half;
    int c0 = pp*2;
    float sc0 = 1.f, sh0 = 0.f, sc1 = 1.f, sh1 = 0.f;
    if (BN) { sc0 = ssm[c0]; sh0 = ssm[C + c0]; sc1 = ssm[c0+1]; sh1 = ssm[C + c0 + 1]; }
    int px4 = i & 16383;
    float4 v0 = ((const float4*)y)[(((size_t)b*C + c0    ) << 14) + px4];
    float4 v1 = ((const float4*)y)[(((size_t)b*C + c0 + 1) << 14) + px4];
    float4 mk = make_float4(1.f,1.f,1.f,1.f);
    if (MASKED) mk = ((const float4*)m)[(((size_t)b) << 14) + px4];
    const float* p0 = &v0.x; const float* p1 = &v1.x; const float* pm = &mk.x;
    uint32_t r[4];
    #pragma unroll
    for (int k = 0; k < 4; k++) {
        float a = p0[k], c = p1[k];
        if (BN) {
            a = fmaf(a, sc0, sh0); a = a >= 0.f ? a : 0.01f*a;
            c = fmaf(c, sc1, sh1); c = c >= 0.f ? c : 0.01f*c;
        }
        if (MASKED) { a *= pm[k]; c *= pm[k]; }
        r[k] = pack2_f16(a, c);
    }
    ((uint4*)out)[i] = make_uint4(r[0], r[1], r[2], r[3]);
}

// ---------------------------------------------------------------------------
// Fused sparse-conv block, fp16 asymmetric-split MMA, double-buffered 16B
// cp.async staging. Row stride WPX chosen with 3*WPX ≡ 8 (mod 32) so the
// B-fragment LDS pattern (tig*3*WPX + g) is bank-conflict-free.
// ---------------------------------------------------------------------------
template<int CIN, int CO_BLK, int NSPLIT, int DIL, int PXT, int WARPS>
__global__ void __launch_bounds__(WARPS*32, 3) conv_mma_kernel(
    const uint32_t* __restrict__ xpk, const float* __restrict__ min_,
    const uint2* __restrict__ wsplit, const float* __restrict__ bg,
    float* __restrict__ yout, float* __restrict__ mout,
    float* __restrict__ sums)
{
    constexpr int NT    = WARPS*32;
    constexpr int PXG   = WARPS*16/CO_BLK;
    constexpr int XW    = PXT + 2*DIL;          // mask window (start x0-DIL)
    // WPX ≥ PXT+8 (staged words) and WPX ≡ 24 (mod 32) → conflict-free frags
    constexpr int WPX   = ((PXT + 8 - 24 + 31)/32)*32 + 24;
    constexpr int NCH   = (PXT + 8) / 4;        // 16B chunks per x row
    constexpr int XTSZ  = 24*WPX;
    constexpr int COUTT = CO_BLK*NSPLIT;
    constexpr int TX    = 256/PXT;
    constexpr int CHUNKS = CIN/16;
    constexpr int PLANES = CIN/2;

    extern __shared__ char dsm[];
    uint32_t* xt  = (uint32_t*)dsm;             // [2][24][WPX], window start x0-4
    float*  msk = (float*)(xt + 2*XTSZ);        // [3][WPX]
    float*  invc= msk + 3*WPX;                  // [PXT]
    float*  red = invc + PXT;                   // [2*CO_BLK]

    const int tid  = threadIdx.x;
    const int lane = tid & 31, warp = tid >> 5;
    const int g    = lane >> 2, tig = lane & 3;
    const int cog  = warp / PXG, pxg = warp % PXG;
    const int pxb  = pxg * 64;
    const int cb   = cog * 16;
    const uint32_t sx = (uint32_t)__cvta_generic_to_shared(xt);

    const int tile = blockIdx.x;
    const int x0 = (tile % TX) * PXT;
    const int y0 = tile / TX;
    const int z  = blockIdx.z;
    const int b  = z / NSPLIT;
    const int split = z % NSPLIT;
    const int co_base = split * CO_BLK;

    // --- stage mask rows ---
    for (int i = tid; i < 3*XW; i += NT) {
        int col = i % XW, r = i / XW;
        int gy = y0 + (r-1)*DIL, gx = x0 - DIL + col;
        float v = 0.f;
        if (gy >= 0 && gy < Hh && gx >= 0 && gx < Ww) v = min_[b*HW + gy*Ww + gx];
        msk[r*WPX + col] = v;
    }
    for (int i = tid; i < 2*CO_BLK; i += NT) red[i] = 0.f;

    // 16B vector staging: chunk ch covers gx = x0-4+4ch .. +3 (all-or-nothing OOB)
    auto stage = [&](int q, int buf) {
        for (int pr = warp; pr < 8; pr += WARPS) {
            const uint32_t* srcp = xpk + (size_t)(b*PLANES + q*8 + pr)*HW;
            #pragma unroll
            for (int r = 0; r < 3; r++) {
                int gy = y0 + (r-1)*DIL;
                bool rowok = ((unsigned)gy < (unsigned)Hh);
                const uint32_t* srow = srcp + (rowok ? gy*Ww : 0);
                uint32_t dstb = sx + ((buf*XTSZ + (pr*3 + r)*WPX) << 2);
                #pragma unroll
                for (int ch = lane; ch < NCH; ch += 32) {
                    int gx = x0 - 4 + ch*4;
                    bool ok = rowok && (gx >= 0) && (gx < Ww);
                    cp_async16(dstb + (ch << 4), srow + (ok ? gx : 0), ok ? 16 : 0);
                }
            }
        }
        asm volatile("cp.async.commit_group;\n");
    };

    stage(0, 0);
    __syncthreads();

    // --- per-pixel 1/count + mask maxpool (overlaps chunk-0 arrival) ---
    for (int px = tid; px < PXT; px += NT) {
        float cnt = 0.f, mn = 0.f;
        #pragma unroll
        for (int ky = 0; ky < 3; ky++)
            #pragma unroll
            for (int kx = 0; kx < 3; kx++) {
                float v = msk[ky*WPX + px + kx*DIL];
                cnt += v; mn = fmaxf(mn, v);
            }
        invc[px] = 1.f / fmaxf(cnt * (float)CIN, 1e-5f);
        if (split == 0) mout[b*HW + y0*Ww + x0 + px] = mn;
    }

    float c[8][4];
    #pragma unroll
    for (int f = 0; f < 8; f++) { c[f][0]=0.f; c[f][1]=0.f; c[f][2]=0.f; c[f][3]=0.f; }

    for (int q = 0; q < CHUNKS; q++) {
        const int buf = q & 1;
        if (q + 1 < CHUNKS) {
            stage(q + 1, buf ^ 1);
            asm volatile("cp.async.wait_group 1;\n");
        } else {
            asm volatile("cp.async.wait_group 0;\n");
        }
        __syncthreads();

        const uint32_t* xb = xt + buf*XTSZ;
        const uint2* Ab = wsplit + (size_t)(split*CHUNKS + q)*72*CO_BLK + cb + g;
        #pragma unroll 3
        for (int t = 0; t < 9; t++) {
            const int ky = t/3, kx = t - 3*ky;
            const int xoff = (kx-1)*DIL + 4;        // window-start shift
            const uint2* Ap = Ab + t*8*CO_BLK;
            uint2 A0 = __ldg(Ap + tig*CO_BLK);
            uint2 A1 = __ldg(Ap + tig*CO_BLK + 8);
            uint2 A2 = __ldg(Ap + (tig+4)*CO_BLK);
            uint2 A3 = __ldg(Ap + (tig+4)*CO_BLK + 8);
            const uint32_t* brow0 = &xb[(tig    *3 + ky)*WPX + pxb + xoff + g];
            const uint32_t* brow1 = &xb[((tig+4)*3 + ky)*WPX + pxb + xoff + g];
            #pragma unroll
            for (int f = 0; f < 8; f++) {
                uint32_t b0 = brow0[f*8];
                uint32_t b1 = brow1[f*8];
                mma16f(c[f], A0.x, A1.x, A2.x, A3.x, b0, b1);  // w_hi * x
                mma16f(c[f], A0.y, A1.y, A2.y, A3.y, b0, b1);  // w_lo * x
            }
        }
        __syncthreads();
    }

    // --- epilogue ---
    const int gco0 = co_base + cb + g;
    const int gco1 = gco0 + 8;
    const float b0v = bg[gco0], b1v = bg[gco1];
    float* rowp0 = yout + (size_t)(b*COUTT + gco0)*HW + y0*Ww + x0;
    float* rowp1 = yout + (size_t)(b*COUTT + gco1)*HW + y0*Ww + x0;
    float s0 = 0.f, q0 = 0.f, s1 = 0.f, q1 = 0.f;
    #pragma unroll
    for (int f = 0; f < 8; f++) {
        int pxl = pxb + f*8 + 2*tig;
        float i0 = invc[pxl], i1 = invc[pxl + 1];
        float y00 = fmaf(c[f][0], i0, b0v);
        float y01 = fmaf(c[f][1], i1, b0v);
        float y10 = fmaf(c[f][2], i0, b1v);
        float y11 = fmaf(c[f][3], i1, b1v);
        *(float2*)(rowp0 + pxl) = make_float2(y00, y01);
        *(float2*)(rowp1 + pxl) = make_float2(y10, y11);
        s0 += y00 + y01; q0 += y00*y00 + y01*y01;
        s1 += y10 + y11; q1 += y10*y10 + y11*y11;
    }
    #pragma unroll
    for (int o = 1; o <= 2; o <<= 1) {
        s0 += __shfl_xor_sync(0xffffffffu, s0, o);
        q0 += __shfl_xor_sync(0xffffffffu, q0, o);
        s1 += __shfl_xor_sync(0xffffffffu, s1, o);
        q1 += __shfl_xor_sync(0xffffffffu, q1, o);
    }
    if (tig == 0) {
        atomicAdd(&red[cb + g],              s0);
        atomicAdd(&red[CO_BLK + cb + g],     q0);
        atomicAdd(&red[cb + g + 8],          s1);
        atomicAdd(&red[CO_BLK + cb + g + 8], q1);
    }
    __syncthreads();
    if (tid < CO_BLK) {
        atomicAdd(&sums[co_base + tid],          red[tid]);
        atomicAdd(&sums[COUTT + co_base + tid],  red[CO_BLK + tid]);
    }
}

// ---------------------------------------------------------------------------
// final 1x1 conv 128 -> 64, fp16 asymmetric split, 16B double-buffered staging
// ---------------------------------------------------------------------------
__global__ void __launch_bounds__(256, 3) conv1x1_mma_kernel(
    const uint32_t* __restrict__ xpk, const uint2* __restrict__ wsp1,
    const float* __restrict__ bg, float* __restrict__ out)
{
    constexpr int CO = 64, PXT = 128, WPX1 = 140, PLANES = 64;
    __shared__ uint32_t xt[2*8*WPX1];

    const int tid = threadIdx.x, lane = tid & 31, warp = tid >> 5;
    const int g = lane >> 2, tig = lane & 3;
    const int cog = warp >> 1, pxg = warp & 1;
    const int pxb = pxg * 64;
    const int tile = blockIdx.x;
    const int x0 = (tile & 1)*PXT, y0 = tile >> 1;
    const int b  = blockIdx.z;
    const uint32_t sx = (uint32_t)__cvta_generic_to_shared(xt);

    auto stage = [&](int q, int buf) {
        const int pr = warp;
        const uint32_t* s = xpk + (size_t)(b*PLANES + q*8 + pr)*HW + y0*Ww + x0;
        uint32_t dstb = sx + ((buf*8*WPX1 + pr*WPX1) << 2);
        cp_async16(dstb + (lane << 4), s + lane*4, 16);
        asm volatile("cp.async.commit_group;\n");
    };

    float c[8][4];
    #pragma unroll
    for (int f = 0; f < 8; f++) { c[f][0]=0.f; c[f][1]=0.f; c[f][2]=0.f; c[f][3]=0.f; }

    stage(0, 0);
    for (int q = 0; q < 8; q++) {
        const int buf = q & 1;
        if (q + 1 < 8) {
            stage(q + 1, buf ^ 1);
            asm volatile("cp.async.wait_group 1;\n");
        } else {
            asm volatile("cp.async.wait_group 0;\n");
        }
        __syncthreads();

        const uint32_t* xb = xt + buf*8*WPX1;
        const uint2* Ap = wsp1 + q*512;
        uint2 a0 = __ldg(Ap + tig*64 + cog*16 + g);
        uint2 a1 = __ldg(Ap + tig*64 + cog*16 + g + 8);
        uint2 a2 = __ldg(Ap + (tig+4)*64 + cog*16 + g);
        uint2 a3 = __ldg(Ap + (tig+4)*64 + cog*16 + g + 8);
        #pragma unroll
        for (int f = 0; f < 8; f++) {
            uint32_t b0 = xb[tig    *WPX1 + pxb + f*8 + g];
            uint32_t b1 = xb[(tig+4)*WPX1 + pxb + f*8 + g];
            mma16f(c[f], a0.x, a1.x, a2.x, a3.x, b0, b1);
            mma16f(c[f], a0.y, a1.y, a2.y, a3.y, b0, b1);
        }
        __syncthreads();
    }
    const int co0 = cog*16 + g, co1 = co0 + 8;
    const float b0v = bg[co0], b1v = bg[co1];
    float* r0 = out + (size_t)(b*CO + co0)*HW + y0*Ww + x0;
    float* r1 = out + (size_t)(b*CO + co1)*HW + y0*Ww + x0;
    #pragma unroll
    for (int f = 0; f < 8; f++) {
        int pxl = pxb + f*8 + 2*tig;
        *(float2*)(r0 + pxl) = make_float2(c[f][0] + b0v, c[f][1] + b0v);
        *(float2*)(r1 + pxl) = make_float2(c[f][2] + b1v, c[f][3] + b1v);
    }
}

// ---------------------------------------------------------------------------
extern "C" void kernel_launch(void* const* d_in, const int* in_sizes, int n_in,
                              void* d_out, int out_size)
{
    const float* feat = (const float*)d_in[0];
    const float* mask = (const float*)d_in[1];
    const float* Wl[5]; const float* bl[5]; const float* gl[5]; const float* bel[5];
    for (int l = 0; l < 5; l++) {
        Wl[l]  = (const float*)d_in[2 + 4*l];
        bl[l]  = (const float*)d_in[3 + 4*l];
        gl[l]  = (const float*)d_in[4 + 4*l];
        bel[l] = (const float*)d_in[5 + 4*l];
    }
    const float* Wf = (const float*)d_in[22];
    const float* bf = (const float*)d_in[23];

    float *bufA, *bufB, *mA, *mB, *sumsG;
    uint32_t* P;
    uint2* wsp;
    cudaGetSymbolAddress((void**)&bufA, g_bufA);
    cudaGetSymbolAddress((void**)&bufB, g_bufB);
    cudaGetSymbolAddress((void**)&P,    g_bufP);
    cudaGetSymbolAddress((void**)&mA,   g_maskA);
    cudaGetSymbolAddress((void**)&mB,   g_maskB);
    cudaGetSymbolAddress((void**)&sumsG, g_sums);
    cudaGetSymbolAddress((void**)&wsp,  g_wsplit);
    float* su0 = sumsG;
    float* su1 = sumsG + 256;

    const int off0 = 0, off1 = 2304, off2 = 4608, off3 = 13824, off4 = 32256;
    const int off1x1 = 69120;
    presplit3x3_all<<<270, 256>>>(Wl[0], Wl[1], Wl[2], Wl[3], Wl[4], wsp);
    presplit1x1_kernel<<<16, 256>>>(Wf, wsp+off1x1);

    // WPX: 256->280, 128->152, 64->88
    const int smem_L0 = 2*24*280*4 + 3*280*4 + 256*4 + 2*16*4 + 16;   // 58288
    const int smem_L1 = 2*24*280*4 + 3*280*4 + 256*4 + 2*32*4 + 16;   // 58416
    const int smem_Lx = 2*24*152*4 + 3*152*4 + 128*4 + 2*64*4 + 16;   // 32048
    const int smem_L4 = 2*24*88*4  + 3*88*4  + 64*4  + 2*128*4 + 16;  // 19248

    auto k0 = conv_mma_kernel<32,16,1,1,256,4>;
    auto k1 = conv_mma_kernel<16,32,1,2,256,8>;
    auto k2 = conv_mma_kernel<32,64,1,1,128,8>;
    auto k3 = conv_mma_kernel<64,64,1,2,128,8>;
    auto k4 = conv_mma_kernel<64,128,1,1,64,8>;
    cudaFuncSetAttribute(k0, cudaFuncAttributeMaxDynamicSharedMemorySize, smem_L0);
    cudaFuncSetAttribute(k1, cudaFuncAttributeMaxDynamicSharedMemorySize, smem_L1);
    cudaFuncSetAttribute(k2, cudaFuncAttributeMaxDynamicSharedMemorySize, smem_Lx);
    cudaFuncSetAttribute(k3, cudaFuncAttributeMaxDynamicSharedMemorySize, smem_Lx);
    cudaFuncSetAttribute(k4, cudaFuncAttributeMaxDynamicSharedMemorySize, smem_L4);

    auto TFM  = transform_kernel<true,  true >;
    auto TF0  = transform_kernel<false, true >;
    auto TFNM = transform_kernel<true,  false>;
    #define TGRID(C) ((C)*256)

    // input transform: feat*mask -> packed; zeroes su0 for L0
    TF0<<<TGRID(32), 256>>>(feat, mask, nullptr, nullptr, nullptr, su0, P, 32, 32*65536);

    // L0: 32 -> 16, d=1
    k0<<<dim3(256,1,8), 128, smem_L0>>>(P, mask, wsp+off0, bl[0], bufA, mA, su0);
    TFM<<<TGRID(16), 256>>>(bufA, mA, su0, gl[0], bel[0], su1, P, 16, 16*65536);

    // L1: 16 -> 32, d=2
    k1<<<dim3(256,1,8), 256, smem_L1>>>(P, mA, wsp+off1, bl[1], bufB, mB, su1);
    TFM<<<TGRID(32), 256>>>(bufB, mB, su1, gl[1], bel[1], su0, P, 32, 32*65536);

    // L2: 32 -> 64, d=1
    k2<<<dim3(512,1,8), 256, smem_Lx>>>(P, mB, wsp+off2, bl[2], bufA, mA, su0);
    TFM<<<TGRID(64), 256>>>(bufA, mA, su0, gl[2], bel[2], su1, P, 64, 64*65536);

    // L3: 64 -> 64, d=2
    k3<<<dim3(512,1,8), 256, smem_Lx>>>(P, mA, wsp+off3, bl[3], bufB, mB, su1);
    TFM<<<TGRID(64), 256>>>(bufB, mB, su1, gl[3], bel[3], su0, P, 64, 64*65536);

    // L4: 64 -> 128, d=1, single pass
    k4<<<dim3(1024,1,8), 256, smem_L4>>>(P, mB, wsp+off4, bl[4], bufA, mA, su0);
    TFNM<<<TGRID(128), 256>>>(bufA, nullptr, su0, gl[4], bel[4], nullptr, P, 128, 128*65536);

    // final 1x1 conv
    conv1x1_mma_kernel<<<dim3(512,1,8), 256>>>(P, wsp+off1x1, bf, (float*)d_out);

    // final mask
    const int xelems = Bb*64*HW;
    const int melems = Bb*HW;
    if (out_size >= xelems + melems) {
        cudaMemcpyAsync((float*)d_out + xelems, mA, (size_t)melems*sizeof(float),
                        cudaMemcpyDeviceToDevice);
    }
}